// round 5
// baseline (speedup 1.0000x reference)
#include <cuda_runtime.h>
#include <cuda_bf16.h>
#include <math.h>
#include <stdint.h>

#define DD 256
#define SS 22
#define NAC 20
#define NTOK 768
#define NWIN 7
#define BATCH 32
#define BWIN 224
#define MBIG 172032
#define MGRU 4928
#define MSO  4480
#define SLOTS_OUT_ELEMS 1146880  // 32*7*20*256

__device__ float g_pe[NTOK * DD];
__device__ float g_buf0[MBIG * DD];
__device__ float g_buf1[MBIG * DD];
__device__ float g_buf2[MBIG * DD];
__device__ float g_qs[SS * DD];
__device__ float g_hg[SS * 768];
__device__ float g_upd[MGRU * DD];
__device__ float g_xg[MGRU * 768];
__device__ float g_so[MSO * DD];
__device__ float g_soln[MSO * DD];
__device__ float g_t2[MSO * DD];
__device__ float g_t3[MSO * DD];
// pre-split weights (hi/lo bf16): FC1, FC2, k, v
__device__ __nv_bfloat16 g_w1h[65536], g_w1l[65536];
__device__ __nv_bfloat16 g_w2h[65536], g_w2l[65536];
__device__ __nv_bfloat16 g_wkh[65536], g_wkl[65536];
__device__ __nv_bfloat16 g_wvh[65536], g_wvl[65536];

// ---------------- helpers ----------------
__device__ __forceinline__ uint32_t smem_u32(const void* p) {
    uint32_t a;
    asm("{ .reg .u64 t; cvta.to.shared.u64 t, %1; cvt.u32.u64 %0, t; }" : "=r"(a) : "l"(p));
    return a;
}
__device__ __forceinline__ unsigned long long pk(float x, float y) {
    unsigned long long r;
    asm("mov.b64 %0, {%1,%2};" : "=l"(r) : "f"(x), "f"(y));
    return r;
}
__device__ __forceinline__ void upk(unsigned long long v, float& x, float& y) {
    asm("mov.b64 {%0,%1}, %2;" : "=f"(x), "=f"(y) : "l"(v));
}
__device__ __forceinline__ unsigned long long fma2(unsigned long long a,
                                                   unsigned long long b,
                                                   unsigned long long c) {
    unsigned long long d;
    asm("fma.rn.f32x2 %0, %1, %2, %3;" : "=l"(d) : "l"(a), "l"(b), "l"(c));
    return d;
}
__device__ __forceinline__ uint32_t bfpack(float a, float b) {
    __nv_bfloat162 t = __floats2bfloat162_rn(a, b);
    return *reinterpret_cast<uint32_t*>(&t);
}
__device__ __forceinline__ void ldsm4(uint32_t* r, uint32_t addr) {
    asm volatile("ldmatrix.sync.aligned.m8n8.x4.shared.b16 {%0,%1,%2,%3}, [%4];"
        : "=r"(r[0]), "=r"(r[1]), "=r"(r[2]), "=r"(r[3]) : "r"(addr));
}
__device__ __forceinline__ void mma16816(float* d, const uint32_t* a,
                                         uint32_t b0, uint32_t b1) {
    asm volatile(
        "mma.sync.aligned.m16n8k16.row.col.f32.bf16.bf16.f32 "
        "{%0,%1,%2,%3}, {%4,%5,%6,%7}, {%8,%9}, {%0,%1,%2,%3};"
        : "+f"(d[0]), "+f"(d[1]), "+f"(d[2]), "+f"(d[3])
        : "r"(a[0]), "r"(a[1]), "r"(a[2]), "r"(a[3]), "r"(b0), "r"(b1));
}
__device__ __forceinline__ void cp16(uint32_t sm, const void* g) {
    asm volatile("cp.async.cg.shared.global [%0], [%1], 16;" :: "r"(sm), "l"(g));
}
__device__ __forceinline__ void cp_commit() {
    asm volatile("cp.async.commit_group;" ::: "memory");
}
template <int N>
__device__ __forceinline__ void cp_wait() {
    asm volatile("cp.async.wait_group %0;" :: "n"(N) : "memory");
}

__device__ __forceinline__ float blockSum(float v, float* s) {
    int tid = threadIdx.x;
#pragma unroll
    for (int o = 16; o > 0; o >>= 1) v += __shfl_down_sync(0xffffffffu, v, o);
    if ((tid & 31) == 0) s[tid >> 5] = v;
    __syncthreads();
    float r = (tid < (blockDim.x >> 5)) ? s[tid] : 0.f;
    if (tid < 32) {
#pragma unroll
        for (int o = 4; o > 0; o >>= 1) r += __shfl_down_sync(0xffffffffu, r, o);
    }
    if (tid == 0) s[0] = r;
    __syncthreads();
    r = s[0];
    __syncthreads();
    return r;
}

// ---------------- small kernels ----------------
__global__ void k_pe(const float* __restrict__ pe_w, const float* __restrict__ pe_b) {
    int p = blockIdx.x, c = threadIdx.x;
    int t = p / 192, rem = p % 192, y = rem / 24, x = rem % 24;
    float g0 = t * (1.f / 3.f), g1 = y * (1.f / 7.f), g2 = x * (1.f / 23.f);
    const float* wr = pe_w + c * 6;
    g_pe[p * DD + c] = pe_b[c] + wr[0] * g0 + wr[1] * g1 + wr[2] * g2
        + wr[3] * (1.f - g0) + wr[4] * (1.f - g1) + wr[5] * (1.f - g2);
}

__global__ void k_winln(const float* __restrict__ inp,
                        const float* __restrict__ gam,
                        const float* __restrict__ bet) {
    __shared__ float red[32];
    int m = blockIdx.x, c = threadIdx.x;
    int wiB = m / NTOK, p = m % NTOK;
    int wi = wiB / BATCH, bb = wiB % BATCH;
    int t = p / 192, rem = p % 192;
    int f = 2 * wi + t;
    float x = inp[((size_t)(bb * 16 + f) * 192 + rem) * DD + c] + g_pe[p * DD + c];
    float mean = blockSum(x, red) * (1.f / 256.f);
    float d0 = x - mean;
    float var = blockSum(d0 * d0, red) * (1.f / 256.f);
    g_buf0[(size_t)m * DD + c] = d0 * rsqrtf(var + 1e-5f) * gam[c] + bet[c];
}

__global__ void k_ln(const float* __restrict__ src, float* __restrict__ dst,
                     const float* __restrict__ gam, const float* __restrict__ bet) {
    __shared__ float red[32];
    int m = blockIdx.x, c = threadIdx.x;
    float x = src[(size_t)m * DD + c];
    float mean = blockSum(x, red) * (1.f / 256.f);
    float d0 = x - mean;
    float var = blockSum(d0 * d0, red) * (1.f / 256.f);
    dst[(size_t)m * DD + c] = d0 * rsqrtf(var + 1e-5f) * gam[c] + bet[c];
}

// split all four 256x256 weights in one launch: fp32 -> hi/lo bf16
__global__ void k_split4(const float* __restrict__ w1, const float* __restrict__ w2,
                         const float* __restrict__ w3, const float* __restrict__ w4) {
    int idx = blockIdx.x * 256 + threadIdx.x;   // 0 .. 262143
    int which = idx >> 16, j = idx & 65535;
    const float* src = (which == 0) ? w1 : (which == 1) ? w2 : (which == 2) ? w3 : w4;
    __nv_bfloat16* h = (which == 0) ? g_w1h : (which == 1) ? g_w2h : (which == 2) ? g_wkh : g_wvh;
    __nv_bfloat16* l = (which == 0) ? g_w1l : (which == 1) ? g_w2l : (which == 2) ? g_wkl : g_wvl;
    float x = src[j];
    __nv_bfloat16 hh = __float2bfloat16(x);
    h[j] = hh;
    l[j] = __float2bfloat16(x - __bfloat162float(hh));
}

// ---------------- pipelined mma.sync split-bf16 GEMM ----------------
// C[M,256] = A[M,256] @ W[256,256]^T + bias (optional ReLU), M % 128 == 0
// CTA 128x128, BK=64, 4 chunks. A: single smem stage + register prefetch.
// B: cp.async double-buffered (bf16 pre-split, no conversion needed).
// smem: A hi/lo (36864) + B 2 stages x hi/lo (73728) = 110592 B
#define MM_SMEM 110592
#define ROWB 144  // (64+8) bf16 row stride in bytes
#define A_HI 0
#define A_LO 18432
#define B_BUF 36864
#define B_STG 36864  // per-stage size (hi 18432 + lo 18432)

template <bool RELU>
__global__ void __launch_bounds__(256) k_mma(const float* __restrict__ A,
                                             const __nv_bfloat16* __restrict__ Wh,
                                             const __nv_bfloat16* __restrict__ Wl,
                                             const float* __restrict__ bias,
                                             float* __restrict__ C, int M) {
    extern __shared__ char sm[];
    int tid = threadIdx.x, lane = tid & 31, wid = tid >> 5;
    int m0 = blockIdx.x * 128, n0 = blockIdx.y * 128;
    int mw = wid & 3, nw = wid >> 2;
    uint32_t sb = smem_u32(sm);

    // A prefetch addressing: each thread owns 8 float4 groups
    const int arow = tid >> 1;                    // used pattern: idx = tid + i*256
    (void)arow;

    float4 av[8];

    float acc[2][8][4];
#pragma unroll
    for (int i = 0; i < 2; i++)
#pragma unroll
        for (int j = 0; j < 8; j++)
#pragma unroll
            for (int k = 0; k < 4; k++) acc[i][j][k] = 0.f;

    // ---- helpers as lambdas ----
    auto ldgA = [&](int ch) {
        int k0 = ch * 64;
#pragma unroll
        for (int i = 0; i < 8; i++) {
            int idx = tid + i * 256;
            int row = idx >> 4, cg = idx & 15;
            av[i] = *reinterpret_cast<const float4*>(
                A + (size_t)(m0 + row) * 256 + k0 + cg * 4);
        }
    };
    auto stsA = [&]() {
#pragma unroll
        for (int i = 0; i < 8; i++) {
            int idx = tid + i * 256;
            int row = idx >> 4, cg = idx & 15;
            float4 v = av[i];
            __nv_bfloat16 hx = __float2bfloat16(v.x);
            __nv_bfloat16 hy = __float2bfloat16(v.y);
            __nv_bfloat16 hz = __float2bfloat16(v.z);
            __nv_bfloat16 hw = __float2bfloat16(v.w);
            uint2 H, L;
            {
                __nv_bfloat162 p0; p0.x = hx; p0.y = hy;
                __nv_bfloat162 p1; p1.x = hz; p1.y = hw;
                H.x = *reinterpret_cast<uint32_t*>(&p0);
                H.y = *reinterpret_cast<uint32_t*>(&p1);
            }
            L.x = bfpack(v.x - __bfloat162float(hx), v.y - __bfloat162float(hy));
            L.y = bfpack(v.z - __bfloat162float(hz), v.w - __bfloat162float(hw));
            uint32_t off = (uint32_t)row * ROWB + cg * 8;
            *reinterpret_cast<uint2*>(sm + A_HI + off) = H;
            *reinterpret_cast<uint2*>(sm + A_LO + off) = L;
        }
    };
    auto cpB = [&](int ch, int buf) {
        int k0 = ch * 64;
        uint32_t bb = sb + B_BUF + (uint32_t)buf * B_STG;
#pragma unroll
        for (int i = 0; i < 4; i++) {
            int idx = tid + i * 256;
            int row = idx >> 3, g = idx & 7;
            size_t gb = (size_t)(n0 + row) * 256 + k0 + g * 8;
            uint32_t off = (uint32_t)row * ROWB + g * 16;
            cp16(bb + off, Wh + gb);
            cp16(bb + 18432 + off, Wl + gb);
        }
    };
    auto domma = [&](int buf) {
        uint32_t bbase = sb + B_BUF + (uint32_t)buf * B_STG;
#pragma unroll
        for (int ks = 0; ks < 4; ks++) {
            int k = ks * 16;
            uint32_t ah[2][4], al[2][4];
#pragma unroll
            for (int mt = 0; mt < 2; mt++) {
                uint32_t addr = sb + A_HI
                    + (uint32_t)(mw * 32 + mt * 16 + (lane & 15)) * ROWB
                    + (uint32_t)(k + (lane >> 4) * 8) * 2;
                ldsm4(ah[mt], addr);
                ldsm4(al[mt], addr + (A_LO - A_HI));
            }
#pragma unroll
            for (int p = 0; p < 4; p++) {
                uint32_t baddr = bbase
                    + (uint32_t)(nw * 64 + p * 16 + (lane & 15)) * ROWB
                    + (uint32_t)(k + (lane >> 4) * 8) * 2;
                uint32_t bh[4], bl[4];
                ldsm4(bh, baddr);
                ldsm4(bl, baddr + 18432);
#pragma unroll
                for (int mt = 0; mt < 2; mt++) {
                    mma16816(acc[mt][2 * p], ah[mt], bh[0], bh[2]);
                    mma16816(acc[mt][2 * p], ah[mt], bl[0], bl[2]);
                    mma16816(acc[mt][2 * p], al[mt], bh[0], bh[2]);
                    mma16816(acc[mt][2 * p + 1], ah[mt], bh[1], bh[3]);
                    mma16816(acc[mt][2 * p + 1], ah[mt], bl[1], bl[3]);
                    mma16816(acc[mt][2 * p + 1], al[mt], bh[1], bh[3]);
                }
            }
        }
    };

    // ---- prologue ----
    ldgA(0);
    cpB(0, 0);
    cp_commit();
    stsA();

    // ---- main loop (unrolled for compile-time wait counts) ----
#pragma unroll
    for (int ch = 0; ch < 4; ch++) {
        if (ch < 3) {
            ldgA(ch + 1);              // DRAM latency overlaps mma below
            cpB(ch + 1, (ch + 1) & 1); // async copy into other B buffer
            cp_commit();
        }
        if (ch < 3) cp_wait<1>(); else cp_wait<0>();
        __syncthreads();
        domma(ch & 1);
        __syncthreads();
        if (ch < 3) stsA();
    }

    // ---- epilogue ----
#pragma unroll
    for (int nt = 0; nt < 8; nt++) {
        int col = n0 + nw * 64 + nt * 8 + (lane & 3) * 2;
        float bx = bias[col], by = bias[col + 1];
#pragma unroll
        for (int mt = 0; mt < 2; mt++) {
            int row = m0 + mw * 32 + mt * 16 + (lane >> 2);
            float* a = acc[mt][nt];
            float2 o0 = make_float2(a[0] + bx, a[1] + by);
            float2 o1 = make_float2(a[2] + bx, a[3] + by);
            if (RELU) {
                o0.x = fmaxf(o0.x, 0.f); o0.y = fmaxf(o0.y, 0.f);
                o1.x = fmaxf(o1.x, 0.f); o1.y = fmaxf(o1.y, 0.f);
            }
            *reinterpret_cast<float2*>(C + (size_t)row * 256 + col) = o0;
            *reinterpret_cast<float2*>(C + (size_t)(row + 8) * 256 + col) = o1;
        }
    }
}

// ---------------- FFMA2 GEMM (gru / ff) ----------------
template <bool RELU>
__global__ void __launch_bounds__(256) k_gemm(const float* __restrict__ A,
                                              const float* __restrict__ W,
                                              const float* __restrict__ bias,
                                              float* __restrict__ C,
                                              int M, int N) {
    __shared__ float As[16][132];
    __shared__ float Bs[16][68];
    int tid = threadIdx.x;
    int m0 = blockIdx.x * 128, n0 = blockIdx.y * 64;
    int tx = tid & 15, ty = tid >> 4;
    int arow = m0 + (tid >> 1), acol = (tid & 1) * 8;
    int brow = n0 + (tid >> 2), bcol = (tid & 3) * 4;
    const bool aval = arow < M;

    unsigned long long cp[4][4];
#pragma unroll
    for (int i = 0; i < 4; i++)
#pragma unroll
        for (int j = 0; j < 4; j++) cp[i][j] = 0ULL;

    for (int k0 = 0; k0 < 256; k0 += 16) {
        float4 av0 = make_float4(0.f, 0.f, 0.f, 0.f), av1 = av0;
        if (aval) {
            av0 = *(const float4*)(A + (size_t)arow * 256 + k0 + acol);
            av1 = *(const float4*)(A + (size_t)arow * 256 + k0 + acol + 4);
        }
        float4 bv = *(const float4*)(W + (size_t)brow * 256 + k0 + bcol);
        int ar = tid >> 1;
        As[acol + 0][ar] = av0.x; As[acol + 1][ar] = av0.y;
        As[acol + 2][ar] = av0.z; As[acol + 3][ar] = av0.w;
        As[acol + 4][ar] = av1.x; As[acol + 5][ar] = av1.y;
        As[acol + 6][ar] = av1.z; As[acol + 7][ar] = av1.w;
        int br = tid >> 2;
        Bs[bcol + 0][br] = bv.x; Bs[bcol + 1][br] = bv.y;
        Bs[bcol + 2][br] = bv.z; Bs[bcol + 3][br] = bv.w;
        __syncthreads();
#pragma unroll
        for (int kk = 0; kk < 16; kk++) {
            ulonglong2 la = *(const ulonglong2*)&As[kk][ty * 8];
            ulonglong2 lb = *(const ulonglong2*)&As[kk][ty * 8 + 4];
            float4 bq = *(const float4*)&Bs[kk][tx * 4];
            unsigned long long am[4] = {la.x, la.y, lb.x, lb.y};
            unsigned long long bs[4] = {pk(bq.x, bq.x), pk(bq.y, bq.y),
                                        pk(bq.z, bq.z), pk(bq.w, bq.w)};
#pragma unroll
            for (int mp = 0; mp < 4; mp++)
#pragma unroll
                for (int n = 0; n < 4; n++)
                    cp[mp][n] = fma2(am[mp], bs[n], cp[mp][n]);
        }
        __syncthreads();
    }

    float4 b4 = *(const float4*)(bias + n0 + tx * 4);
#pragma unroll
    for (int mp = 0; mp < 4; mp++) {
        float lo[4], hi[4];
#pragma unroll
        for (int n = 0; n < 4; n++) upk(cp[mp][n], lo[n], hi[n]);
        float4 o0 = make_float4(lo[0] + b4.x, lo[1] + b4.y, lo[2] + b4.z, lo[3] + b4.w);
        float4 o1 = make_float4(hi[0] + b4.x, hi[1] + b4.y, hi[2] + b4.z, hi[3] + b4.w);
        if (RELU) {
            o0.x = fmaxf(o0.x, 0.f); o0.y = fmaxf(o0.y, 0.f);
            o0.z = fmaxf(o0.z, 0.f); o0.w = fmaxf(o0.w, 0.f);
            o1.x = fmaxf(o1.x, 0.f); o1.y = fmaxf(o1.y, 0.f);
            o1.z = fmaxf(o1.z, 0.f); o1.w = fmaxf(o1.w, 0.f);
        }
        int r0 = m0 + ty * 8 + mp * 2;
        if (r0 < M)     *(float4*)(C + (size_t)r0 * N + n0 + tx * 4) = o0;
        if (r0 + 1 < M) *(float4*)(C + (size_t)(r0 + 1) * N + n0 + tx * 4) = o1;
    }
}

// q = LN_ns(slots)@q_w^T + q_b ; hg = slots@gru_wh^T + gru_bh (22 rows)
__global__ void k_small(const float* __restrict__ slots,
                        const float* __restrict__ nsg, const float* __restrict__ nsb,
                        const float* __restrict__ qw, const float* __restrict__ qb,
                        const float* __restrict__ wh, const float* __restrict__ bh) {
    __shared__ float red[32];
    __shared__ float sraw[DD];
    __shared__ float sln[DD];
    int i = blockIdx.x, c = threadIdx.x;
    float x = slots[i * DD + c];
    sraw[c] = x;
    float mean = blockSum(x, red) * (1.f / 256.f);
    float d0 = x - mean;
    float var = blockSum(d0 * d0, red) * (1.f / 256.f);
    sln[c] = d0 * rsqrtf(var + 1e-5f) * nsg[c] + nsb[c];
    __syncthreads();
    float acc = qb[c];
    const float* wr = qw + (size_t)c * 256;
#pragma unroll 8
    for (int k = 0; k < 256; k++) acc += sln[k] * wr[k];
    g_qs[i * DD + c] = acc;
#pragma unroll
    for (int j = 0; j < 3; j++) {
        int u = j * 256 + c;
        float a = bh[u];
        const float* hr = wh + (size_t)u * 256;
#pragma unroll 8
        for (int k = 0; k < 256; k++) a += sraw[k] * hr[k];
        g_hg[i * 768 + u] = a;
    }
}

__device__ __forceinline__ void softmax_store(const unsigned long long* d,
                                              float* __restrict__ dst, int j) {
    float v[SS];
#pragma unroll
    for (int ip = 0; ip < 11; ip++) {
        float a, b;
        upk(d[ip], a, b);
        v[2 * ip] = a * 0.0625f;
        v[2 * ip + 1] = b * 0.0625f;
    }
    float mx = v[0];
#pragma unroll
    for (int i = 1; i < SS; i++) mx = fmaxf(mx, v[i]);
    float s = 0.f;
#pragma unroll
    for (int i = 0; i < SS; i++) { v[i] = __expf(v[i] - mx); s += v[i]; }
    float inv = 1.f / s;
#pragma unroll
    for (int i = 0; i < SS; i++) dst[i * NTOK + j] = v[i] * inv + 1e-8f;
}

__global__ void __launch_bounds__(384) k_attn(float* __restrict__ out_attn,
                                              const float* __restrict__ kk) {
    __shared__ unsigned long long q2[11 * 256];
    __shared__ float ks[8][768];
    int bB = blockIdx.x, tid = threadIdx.x;
    for (int idx = tid; idx < 11 * 256; idx += 384) {
        int ip = idx >> 8, k = idx & 255;
        q2[idx] = pk(g_qs[(2 * ip) * DD + k], g_qs[(2 * ip + 1) * DD + k]);
    }
    unsigned long long da[11], db[11];
#pragma unroll
    for (int ip = 0; ip < 11; ip++) { da[ip] = 0ULL; db[ip] = 0ULL; }
    size_t rowbase = (size_t)bB * NTOK;
    for (int kc = 0; kc < 256; kc += 8) {
#pragma unroll
        for (int rr = 0; rr < 2; rr++) {
            int r = tid + rr * 384;
            const float4* src = (const float4*)(kk + (rowbase + r) * 256 + kc);
            float4 v0 = src[0], v1 = src[1];
            ks[0][r] = v0.x; ks[1][r] = v0.y; ks[2][r] = v0.z; ks[3][r] = v0.w;
            ks[4][r] = v1.x; ks[5][r] = v1.y; ks[6][r] = v1.z; ks[7][r] = v1.w;
        }
        __syncthreads();
#pragma unroll
        for (int kl = 0; kl < 8; kl++) {
            int k = kc + kl;
            float kv0 = ks[kl][tid], kv1 = ks[kl][tid + 384];
            unsigned long long s0 = pk(kv0, kv0), s1 = pk(kv1, kv1);
#pragma unroll
            for (int ip = 0; ip < 11; ip++) {
                unsigned long long qv = q2[ip * 256 + k];
                da[ip] = fma2(qv, s0, da[ip]);
                db[ip] = fma2(qv, s1, db[ip]);
            }
        }
        __syncthreads();
    }
    int wi = bB / BATCH, bb = bB % BATCH;
    float* dst = out_attn + ((size_t)(bb * NWIN + wi)) * SS * NTOK;
    softmax_store(da, dst, tid);
    softmax_store(db, dst, tid + 384);
}

__global__ void __launch_bounds__(256) k_upd(const float* __restrict__ attn,
                                             const float* __restrict__ vv) {
    __shared__ float red[32];
    __shared__ float sinv[SS];
    __shared__ unsigned long long at2[11 * 64];
    int bB = blockIdx.x, tid = threadIdx.x;
    int wi = bB / BATCH, bb = bB % BATCH;
    const float* ab = attn + ((size_t)(bb * NWIN + wi)) * SS * NTOK;
    for (int i = 0; i < SS; i++) {
        float p = 0.f;
        for (int j = tid; j < NTOK; j += 256) p += ab[i * NTOK + j];
        float s = blockSum(p, red);
        if (tid == 0) sinv[i] = 1.f / s;
    }
    __syncthreads();
    unsigned long long acc[11];
#pragma unroll
    for (int ip = 0; ip < 11; ip++) acc[ip] = 0ULL;
    for (int j0 = 0; j0 < NTOK; j0 += 64) {
        for (int idx = tid; idx < 11 * 64; idx += 256) {
            int ip = idx >> 6, jj = idx & 63;
            at2[idx] = pk(ab[(2 * ip) * NTOK + j0 + jj],
                          ab[(2 * ip + 1) * NTOK + j0 + jj]);
        }
        __syncthreads();
        const float* vp = vv + ((size_t)bB * NTOK + j0) * 256 + tid;
#pragma unroll 4
        for (int jj = 0; jj < 64; jj++) {
            float v = vp[(size_t)jj * 256];
            unsigned long long sv = pk(v, v);
#pragma unroll
            for (int ip = 0; ip < 11; ip++)
                acc[ip] = fma2(at2[ip * 64 + jj], sv, acc[ip]);
        }
        __syncthreads();
    }
#pragma unroll
    for (int ip = 0; ip < 11; ip++) {
        float u0, u1;
        upk(acc[ip], u0, u1);
        g_upd[((size_t)bB * SS + 2 * ip) * DD + tid] = u0 * sinv[2 * ip];
        g_upd[((size_t)bB * SS + 2 * ip + 1) * DD + tid] = u1 * sinv[2 * ip + 1];
    }
}

__global__ void k_gate(const float* __restrict__ slots) {
    int m = blockIdx.x, c = threadIdx.x;
    int Bi = m / NAC, i = m % NAC;
    size_t row = (size_t)Bi * SS + i;
    float ir = g_xg[row * 768 + c];
    float iz = g_xg[row * 768 + 256 + c];
    float in_ = g_xg[row * 768 + 512 + c];
    float hr = g_hg[i * 768 + c];
    float hz = g_hg[i * 768 + 256 + c];
    float hn = g_hg[i * 768 + 512 + c];
    float h = slots[i * DD + c];
    float r = 1.f / (1.f + __expf(-(ir + hr)));
    float z = 1.f / (1.f + __expf(-(iz + hz)));
    float n = tanhf(in_ + r * hn);
    g_so[(size_t)m * DD + c] = (1.f - z) * n + z * h;
}

__global__ void k_final(float* __restrict__ out) {
    int m = blockIdx.x, c = threadIdx.x;
    int Bi = m / NAC, sl = m % NAC;
    int wi = Bi / BATCH, bb = Bi % BATCH;
    out[(((size_t)bb * NWIN + wi) * NAC + sl) * DD + c] =
        g_so[(size_t)m * DD + c] + g_t3[(size_t)m * DD + c];
}

extern "C" void kernel_launch(void* const* d_in, const int* in_sizes, int n_in,
                              void* d_out, int out_size) {
    const float* inputs = (const float*)d_in[0];
    const float* slots  = (const float*)d_in[1];
    const float* pe_w   = (const float*)d_in[2];
    const float* pe_b   = (const float*)d_in[3];
    const float* LN_g   = (const float*)d_in[4];
    const float* LN_b   = (const float*)d_in[5];
    const float* ni_g   = (const float*)d_in[6];
    const float* ni_b   = (const float*)d_in[7];
    const float* ns_g   = (const float*)d_in[8];
    const float* ns_b   = (const float*)d_in[9];
    const float* npf_g  = (const float*)d_in[10];
    const float* npf_b  = (const float*)d_in[11];
    const float* FC1_w  = (const float*)d_in[12];
    const float* FC1_b  = (const float*)d_in[13];
    const float* FC2_w  = (const float*)d_in[14];
    const float* FC2_b  = (const float*)d_in[15];
    const float* q_w    = (const float*)d_in[16];
    const float* q_b    = (const float*)d_in[17];
    const float* k_w    = (const float*)d_in[18];
    const float* k_b    = (const float*)d_in[19];
    const float* v_w    = (const float*)d_in[20];
    const float* v_b    = (const float*)d_in[21];
    const float* ff1_w  = (const float*)d_in[22];
    const float* ff1_b  = (const float*)d_in[23];
    const float* ff2_w  = (const float*)d_in[24];
    const float* ff2_b  = (const float*)d_in[25];
    const float* gru_wi = (const float*)d_in[26];
    const float* gru_wh = (const float*)d_in[27];
    const float* gru_bi = (const float*)d_in[28];
    const float* gru_bh = (const float*)d_in[29];

    float* out = (float*)d_out;
    float* out_attn = out + SLOTS_OUT_ELEMS;

    float *b0, *b1, *b2, *upd_, *xg_, *so_, *soln_, *t2_, *t3_;
    cudaGetSymbolAddress((void**)&b0, g_buf0);
    cudaGetSymbolAddress((void**)&b1, g_buf1);
    cudaGetSymbolAddress((void**)&b2, g_buf2);
    cudaGetSymbolAddress((void**)&upd_, g_upd);
    cudaGetSymbolAddress((void**)&xg_, g_xg);
    cudaGetSymbolAddress((void**)&so_, g_so);
    cudaGetSymbolAddress((void**)&soln_, g_soln);
    cudaGetSymbolAddress((void**)&t2_, g_t2);
    cudaGetSymbolAddress((void**)&t3_, g_t3);

    __nv_bfloat16 *w1h, *w1l, *w2h, *w2l, *wkh, *wkl, *wvh, *wvl;
    cudaGetSymbolAddress((void**)&w1h, g_w1h); cudaGetSymbolAddress((void**)&w1l, g_w1l);
    cudaGetSymbolAddress((void**)&w2h, g_w2h); cudaGetSymbolAddress((void**)&w2l, g_w2l);
    cudaGetSymbolAddress((void**)&wkh, g_wkh); cudaGetSymbolAddress((void**)&wkl, g_wkl);
    cudaGetSymbolAddress((void**)&wvh, g_wvh); cudaGetSymbolAddress((void**)&wvl, g_wvl);

    cudaFuncSetAttribute(k_mma<true>, cudaFuncAttributeMaxDynamicSharedMemorySize, MM_SMEM);
    cudaFuncSetAttribute(k_mma<false>, cudaFuncAttributeMaxDynamicSharedMemorySize, MM_SMEM);

    // split weights (single launch)
    k_split4<<<1024, 256>>>(FC1_w, FC2_w, k_w, v_w);

    // positional embedding + gather + LN
    k_pe<<<NTOK, 256>>>(pe_w, pe_b);
    k_winln<<<MBIG, 256>>>(inputs, LN_g, LN_b);

    dim3 gBig(MBIG / 128, 2);
    // MLP: FC1 (relu) -> FC2 (tensor cores, pipelined)
    k_mma<true><<<gBig, 256, MM_SMEM>>>(b0, w1h, w1l, FC1_b, b1, MBIG);
    k_mma<false><<<gBig, 256, MM_SMEM>>>(b1, w2h, w2l, FC2_b, b2, MBIG);

    // norm_input, K and V projections
    k_ln<<<MBIG, 256>>>(b2, b0, ni_g, ni_b);
    k_mma<false><<<gBig, 256, MM_SMEM>>>(b0, wkh, wkl, k_b, b1, MBIG);  // kk
    k_mma<false><<<gBig, 256, MM_SMEM>>>(b0, wvh, wvl, v_b, b2, MBIG);  // vv

    // batch-invariant q and hidden gates
    k_small<<<SS, 256>>>(slots, ns_g, ns_b, q_w, q_b, gru_wh, gru_bh);

    // dots + softmax-over-slots + EPS (writes attns output directly)
    k_attn<<<BWIN, 384>>>(out_attn, b1);

    // renorm + weighted update
    k_upd<<<BWIN, 256>>>(out_attn, b2);

    // GRU input gates GEMM: (4928x256)@(768x256)^T
    dim3 gGru((MGRU + 127) / 128, 12);
    k_gemm<false><<<gGru, 256>>>(upd_, gru_wi, gru_bi, xg_, MGRU, 768);

    // gates -> slots (first 20)
    k_gate<<<MSO, 256>>>(slots);

    // residual MLP
    k_ln<<<MSO, 256>>>(so_, soln_, npf_g, npf_b);
    dim3 gSo(MSO / 128, 4);
    k_gemm<true><<<gSo, 256>>>(soln_, ff1_w, ff1_b, t2_, MSO, 256);
    k_gemm<false><<<gSo, 256>>>(t2_, ff2_w, ff2_b, t3_, MSO, 256);

    // residual + permute into slots output
    k_final<<<MSO, 256>>>(out);
}

// round 6
// speedup vs baseline: 1.3040x; 1.3040x over previous
#include <cuda_runtime.h>
#include <cuda_bf16.h>
#include <math.h>
#include <stdint.h>

#define DD 256
#define SS 22
#define NAC 20
#define NTOK 768
#define NWIN 7
#define BATCH 32
#define BWIN 224
#define MBIG 172032
#define MGRU 4928
#define MSO  4480
#define SLOTS_OUT_ELEMS 1146880  // 32*7*20*256

__device__ float g_pe[NTOK * DD];
__device__ float g_buf0[MBIG * DD];   // FC2 out (fp32, feeds LN)
__device__ float g_buf1[MBIG * DD];   // kk
__device__ float g_buf2[MBIG * DD];   // vv
__device__ __nv_bfloat16 g_x0h[MBIG * DD], g_x0l[MBIG * DD];  // winln out
__device__ __nv_bfloat16 g_x1h[MBIG * DD], g_x1l[MBIG * DD];  // FC1 out
__device__ __nv_bfloat16 g_x2h[MBIG * DD], g_x2l[MBIG * DD];  // ni-LN out
__device__ float g_qs[SS * DD];
__device__ float g_hg[SS * 768];
__device__ float g_upd[MGRU * DD];
__device__ float g_xg[MGRU * 768];
__device__ float g_so[MSO * DD];
__device__ float g_soln[MSO * DD];
__device__ float g_t2[MSO * DD];
__device__ float g_t3[MSO * DD];
// pre-split weights (hi/lo bf16): FC1, FC2, k, v
__device__ __nv_bfloat16 g_w1h[65536], g_w1l[65536];
__device__ __nv_bfloat16 g_w2h[65536], g_w2l[65536];
__device__ __nv_bfloat16 g_wkh[65536], g_wkl[65536];
__device__ __nv_bfloat16 g_wvh[65536], g_wvl[65536];

// ---------------- helpers ----------------
__device__ __forceinline__ uint32_t smem_u32(const void* p) {
    uint32_t a;
    asm("{ .reg .u64 t; cvta.to.shared.u64 t, %1; cvt.u32.u64 %0, t; }" : "=r"(a) : "l"(p));
    return a;
}
__device__ __forceinline__ unsigned long long pk(float x, float y) {
    unsigned long long r;
    asm("mov.b64 %0, {%1,%2};" : "=l"(r) : "f"(x), "f"(y));
    return r;
}
__device__ __forceinline__ void upk(unsigned long long v, float& x, float& y) {
    asm("mov.b64 {%0,%1}, %2;" : "=f"(x), "=f"(y) : "l"(v));
}
__device__ __forceinline__ unsigned long long fma2(unsigned long long a,
                                                   unsigned long long b,
                                                   unsigned long long c) {
    unsigned long long d;
    asm("fma.rn.f32x2 %0, %1, %2, %3;" : "=l"(d) : "l"(a), "l"(b), "l"(c));
    return d;
}
__device__ __forceinline__ uint32_t bfpack(float a, float b) {
    __nv_bfloat162 t = __floats2bfloat162_rn(a, b);
    return *reinterpret_cast<uint32_t*>(&t);
}
__device__ __forceinline__ void ldsm4(uint32_t* r, uint32_t addr) {
    asm volatile("ldmatrix.sync.aligned.m8n8.x4.shared.b16 {%0,%1,%2,%3}, [%4];"
        : "=r"(r[0]), "=r"(r[1]), "=r"(r[2]), "=r"(r[3]) : "r"(addr));
}
__device__ __forceinline__ void mma16816(float* d, const uint32_t* a,
                                         uint32_t b0, uint32_t b1) {
    asm volatile(
        "mma.sync.aligned.m16n8k16.row.col.f32.bf16.bf16.f32 "
        "{%0,%1,%2,%3}, {%4,%5,%6,%7}, {%8,%9}, {%0,%1,%2,%3};"
        : "+f"(d[0]), "+f"(d[1]), "+f"(d[2]), "+f"(d[3])
        : "r"(a[0]), "r"(a[1]), "r"(a[2]), "r"(a[3]), "r"(b0), "r"(b1));
}
__device__ __forceinline__ void cp16(uint32_t sm, const void* g) {
    asm volatile("cp.async.cg.shared.global [%0], [%1], 16;" :: "r"(sm), "l"(g));
}
__device__ __forceinline__ void cp_commit() {
    asm volatile("cp.async.commit_group;" ::: "memory");
}
template <int N>
__device__ __forceinline__ void cp_wait() {
    asm volatile("cp.async.wait_group %0;" :: "n"(N) : "memory");
}

__device__ __forceinline__ float blockSum(float v, float* s) {
    int tid = threadIdx.x;
#pragma unroll
    for (int o = 16; o > 0; o >>= 1) v += __shfl_down_sync(0xffffffffu, v, o);
    if ((tid & 31) == 0) s[tid >> 5] = v;
    __syncthreads();
    float r = (tid < (int)(blockDim.x >> 5)) ? s[tid] : 0.f;
    if (tid < 32) {
#pragma unroll
        for (int o = 4; o > 0; o >>= 1) r += __shfl_down_sync(0xffffffffu, r, o);
    }
    if (tid == 0) s[0] = r;
    __syncthreads();
    r = s[0];
    __syncthreads();
    return r;
}

// ---------------- small kernels ----------------
__global__ void k_pe(const float* __restrict__ pe_w, const float* __restrict__ pe_b) {
    int p = blockIdx.x, c = threadIdx.x;
    int t = p / 192, rem = p % 192, y = rem / 24, x = rem % 24;
    float g0 = t * (1.f / 3.f), g1 = y * (1.f / 7.f), g2 = x * (1.f / 23.f);
    const float* wr = pe_w + c * 6;
    g_pe[p * DD + c] = pe_b[c] + wr[0] * g0 + wr[1] * g1 + wr[2] * g2
        + wr[3] * (1.f - g0) + wr[4] * (1.f - g1) + wr[5] * (1.f - g2);
}

// warp-per-row: gather window + pe + LN -> split bf16
__global__ void __launch_bounds__(256) k_winln(const float* __restrict__ inp,
                                               const float* __restrict__ gam,
                                               const float* __restrict__ bet) {
    int m = (blockIdx.x * 256 + threadIdx.x) >> 5;
    int lane = threadIdx.x & 31;
    int wiB = m / NTOK, p = m % NTOK;
    int wi = wiB / BATCH, bb = wiB % BATCH;
    int t = p / 192, rem = p % 192;
    int f = 2 * wi + t;
    const float* src = inp + ((size_t)(bb * 16 + f) * 192 + rem) * DD;
    const float* pe = g_pe + p * DD;
    float x[8], s = 0.f, sq = 0.f;
#pragma unroll
    for (int i = 0; i < 8; i++) {
        int c = lane + i * 32;
        x[i] = src[c] + pe[c];
        s += x[i];
        sq += x[i] * x[i];
    }
#pragma unroll
    for (int o = 16; o > 0; o >>= 1) {
        s += __shfl_xor_sync(0xffffffffu, s, o);
        sq += __shfl_xor_sync(0xffffffffu, sq, o);
    }
    float mean = s * (1.f / 256.f);
    float var = sq * (1.f / 256.f) - mean * mean;
    float rs = rsqrtf(var + 1e-5f);
#pragma unroll
    for (int i = 0; i < 8; i++) {
        int c = lane + i * 32;
        float y = (x[i] - mean) * rs * gam[c] + bet[c];
        __nv_bfloat16 h = __float2bfloat16(y);
        g_x0h[(size_t)m * DD + c] = h;
        g_x0l[(size_t)m * DD + c] = __float2bfloat16(y - __bfloat162float(h));
    }
}

// warp-per-row LN; SPLIT -> bf16 hi/lo, else fp32
template <bool SPLIT>
__global__ void __launch_bounds__(256) k_ln2(const float* __restrict__ src,
                                             float* __restrict__ dst,
                                             __nv_bfloat16* __restrict__ dsth,
                                             __nv_bfloat16* __restrict__ dstl,
                                             const float* __restrict__ gam,
                                             const float* __restrict__ bet) {
    int m = (blockIdx.x * 256 + threadIdx.x) >> 5;
    int lane = threadIdx.x & 31;
    const float* sp = src + (size_t)m * DD;
    float x[8], s = 0.f, sq = 0.f;
#pragma unroll
    for (int i = 0; i < 8; i++) {
        x[i] = sp[lane + i * 32];
        s += x[i];
        sq += x[i] * x[i];
    }
#pragma unroll
    for (int o = 16; o > 0; o >>= 1) {
        s += __shfl_xor_sync(0xffffffffu, s, o);
        sq += __shfl_xor_sync(0xffffffffu, sq, o);
    }
    float mean = s * (1.f / 256.f);
    float var = sq * (1.f / 256.f) - mean * mean;
    float rs = rsqrtf(var + 1e-5f);
#pragma unroll
    for (int i = 0; i < 8; i++) {
        int c = lane + i * 32;
        float y = (x[i] - mean) * rs * gam[c] + bet[c];
        if (SPLIT) {
            __nv_bfloat16 h = __float2bfloat16(y);
            dsth[(size_t)m * DD + c] = h;
            dstl[(size_t)m * DD + c] = __float2bfloat16(y - __bfloat162float(h));
        } else {
            dst[(size_t)m * DD + c] = y;
        }
    }
}

// split all four 256x256 weights in one launch: fp32 -> hi/lo bf16
__global__ void k_split4(const float* __restrict__ w1, const float* __restrict__ w2,
                         const float* __restrict__ w3, const float* __restrict__ w4) {
    int idx = blockIdx.x * 256 + threadIdx.x;
    int which = idx >> 16, j = idx & 65535;
    const float* src = (which == 0) ? w1 : (which == 1) ? w2 : (which == 2) ? w3 : w4;
    __nv_bfloat16* h = (which == 0) ? g_w1h : (which == 1) ? g_w2h : (which == 2) ? g_wkh : g_wvh;
    __nv_bfloat16* l = (which == 0) ? g_w1l : (which == 1) ? g_w2l : (which == 2) ? g_wkl : g_wvl;
    float x = src[j];
    __nv_bfloat16 hh = __float2bfloat16(x);
    h[j] = hh;
    l[j] = __float2bfloat16(x - __bfloat162float(hh));
}

// ---------------- all-async split-bf16 mma GEMM ----------------
// C[M,256] = A[M,256] @ W[256,256]^T + bias; A,W pre-split bf16 hi/lo.
// CTA 128x128, BK=32, 8 chunks, 2-stage cp.async double buffer, 2 CTAs/SM.
#define ROW2 80      // 32 bf16 (64B) + 16B pad
#define MAT2 10240   // 128 * 80
#define STG2 40960   // Ah,Al,Bh,Bl
#define MM_SMEM 81920

template <bool RELU, bool SPLIT>
__global__ void __launch_bounds__(256, 2) k_mma(
    const __nv_bfloat16* __restrict__ Ah, const __nv_bfloat16* __restrict__ Al,
    const __nv_bfloat16* __restrict__ Wh, const __nv_bfloat16* __restrict__ Wl,
    const float* __restrict__ bias, float* __restrict__ C,
    __nv_bfloat16* __restrict__ Ch, __nv_bfloat16* __restrict__ Cl) {
    extern __shared__ char sm[];
    int tid = threadIdx.x, lane = tid & 31, wid = tid >> 5;
    int m0 = blockIdx.x * 128, n0 = blockIdx.y * 128;
    int mw = wid & 3, nw = wid >> 2;
    uint32_t sb = smem_u32(sm);

    float acc[2][8][4];
#pragma unroll
    for (int i = 0; i < 2; i++)
#pragma unroll
        for (int j = 0; j < 8; j++)
#pragma unroll
            for (int k = 0; k < 4; k++) acc[i][j][k] = 0.f;

    auto cpStage = [&](int ch, int buf) {
        int k0 = ch * 32;
        uint32_t st = sb + (uint32_t)buf * STG2;
#pragma unroll
        for (int i = 0; i < 2; i++) {
            int idx = tid + i * 256;
            int row = idx >> 2, g = idx & 3;
            uint32_t off = (uint32_t)row * ROW2 + g * 16;
            size_t ga = (size_t)(m0 + row) * 256 + k0 + g * 8;
            size_t gb = (size_t)(n0 + row) * 256 + k0 + g * 8;
            cp16(st + off, Ah + ga);
            cp16(st + MAT2 + off, Al + ga);
            cp16(st + 2 * MAT2 + off, Wh + gb);
            cp16(st + 3 * MAT2 + off, Wl + gb);
        }
    };

    cpStage(0, 0); cp_commit();
    cpStage(1, 1); cp_commit();

#pragma unroll
    for (int ch = 0; ch < 8; ch++) {
        if (ch < 7) cp_wait<1>(); else cp_wait<0>();
        __syncthreads();
        uint32_t st = sb + (uint32_t)(ch & 1) * STG2;
#pragma unroll
        for (int ks = 0; ks < 2; ks++) {
            int k = ks * 16;
            uint32_t ah[2][4], al[2][4];
#pragma unroll
            for (int mt = 0; mt < 2; mt++) {
                uint32_t addr = st
                    + (uint32_t)(mw * 32 + mt * 16 + (lane & 15)) * ROW2
                    + (uint32_t)(k + (lane >> 4) * 8) * 2;
                ldsm4(ah[mt], addr);
                ldsm4(al[mt], addr + MAT2);
            }
#pragma unroll
            for (int p = 0; p < 4; p++) {
                uint32_t ba = st + 2 * MAT2
                    + (uint32_t)(nw * 64 + p * 16 + (lane & 15)) * ROW2
                    + (uint32_t)(k + (lane >> 4) * 8) * 2;
                uint32_t bh[4], bl[4];
                ldsm4(bh, ba);
                ldsm4(bl, ba + MAT2);
#pragma unroll
                for (int mt = 0; mt < 2; mt++) {
                    mma16816(acc[mt][2 * p], ah[mt], bh[0], bh[2]);
                    mma16816(acc[mt][2 * p], ah[mt], bl[0], bl[2]);
                    mma16816(acc[mt][2 * p], al[mt], bh[0], bh[2]);
                    mma16816(acc[mt][2 * p + 1], ah[mt], bh[1], bh[3]);
                    mma16816(acc[mt][2 * p + 1], ah[mt], bl[1], bl[3]);
                    mma16816(acc[mt][2 * p + 1], al[mt], bh[1], bh[3]);
                }
            }
        }
        __syncthreads();
        if (ch < 6) { cpStage(ch + 2, ch & 1); cp_commit(); }
    }

    // epilogue
#pragma unroll
    for (int nt = 0; nt < 8; nt++) {
        int col = n0 + nw * 64 + nt * 8 + (lane & 3) * 2;
        float bx = bias[col], by = bias[col + 1];
#pragma unroll
        for (int mt = 0; mt < 2; mt++) {
            int row = m0 + mw * 32 + mt * 16 + (lane >> 2);
            float* a = acc[mt][nt];
            float2 o0 = make_float2(a[0] + bx, a[1] + by);
            float2 o1 = make_float2(a[2] + bx, a[3] + by);
            if (RELU) {
                o0.x = fmaxf(o0.x, 0.f); o0.y = fmaxf(o0.y, 0.f);
                o1.x = fmaxf(o1.x, 0.f); o1.y = fmaxf(o1.y, 0.f);
            }
            if (SPLIT) {
                __nv_bfloat162 h0 = __floats2bfloat162_rn(o0.x, o0.y);
                __nv_bfloat162 h1 = __floats2bfloat162_rn(o1.x, o1.y);
                uint32_t L0 = bfpack(o0.x - __bfloat162float(h0.x),
                                     o0.y - __bfloat162float(h0.y));
                uint32_t L1 = bfpack(o1.x - __bfloat162float(h1.x),
                                     o1.y - __bfloat162float(h1.y));
                *reinterpret_cast<uint32_t*>(Ch + (size_t)row * 256 + col) =
                    *reinterpret_cast<uint32_t*>(&h0);
                *reinterpret_cast<uint32_t*>(Cl + (size_t)row * 256 + col) = L0;
                *reinterpret_cast<uint32_t*>(Ch + (size_t)(row + 8) * 256 + col) =
                    *reinterpret_cast<uint32_t*>(&h1);
                *reinterpret_cast<uint32_t*>(Cl + (size_t)(row + 8) * 256 + col) = L1;
            } else {
                *reinterpret_cast<float2*>(C + (size_t)row * 256 + col) = o0;
                *reinterpret_cast<float2*>(C + (size_t)(row + 8) * 256 + col) = o1;
            }
        }
    }
}

// ---------------- FFMA2 GEMM (gru / ff) ----------------
template <bool RELU>
__global__ void __launch_bounds__(256) k_gemm(const float* __restrict__ A,
                                              const float* __restrict__ W,
                                              const float* __restrict__ bias,
                                              float* __restrict__ C,
                                              int M, int N) {
    __shared__ float As[16][132];
    __shared__ float Bs[16][68];
    int tid = threadIdx.x;
    int m0 = blockIdx.x * 128, n0 = blockIdx.y * 64;
    int tx = tid & 15, ty = tid >> 4;
    int arow = m0 + (tid >> 1), acol = (tid & 1) * 8;
    int brow = n0 + (tid >> 2), bcol = (tid & 3) * 4;
    const bool aval = arow < M;

    unsigned long long cp[4][4];
#pragma unroll
    for (int i = 0; i < 4; i++)
#pragma unroll
        for (int j = 0; j < 4; j++) cp[i][j] = 0ULL;

    for (int k0 = 0; k0 < 256; k0 += 16) {
        float4 av0 = make_float4(0.f, 0.f, 0.f, 0.f), av1 = av0;
        if (aval) {
            av0 = *(const float4*)(A + (size_t)arow * 256 + k0 + acol);
            av1 = *(const float4*)(A + (size_t)arow * 256 + k0 + acol + 4);
        }
        float4 bv = *(const float4*)(W + (size_t)brow * 256 + k0 + bcol);
        int ar = tid >> 1;
        As[acol + 0][ar] = av0.x; As[acol + 1][ar] = av0.y;
        As[acol + 2][ar] = av0.z; As[acol + 3][ar] = av0.w;
        As[acol + 4][ar] = av1.x; As[acol + 5][ar] = av1.y;
        As[acol + 6][ar] = av1.z; As[acol + 7][ar] = av1.w;
        int br = tid >> 2;
        Bs[bcol + 0][br] = bv.x; Bs[bcol + 1][br] = bv.y;
        Bs[bcol + 2][br] = bv.z; Bs[bcol + 3][br] = bv.w;
        __syncthreads();
#pragma unroll
        for (int kk = 0; kk < 16; kk++) {
            ulonglong2 la = *(const ulonglong2*)&As[kk][ty * 8];
            ulonglong2 lb = *(const ulonglong2*)&As[kk][ty * 8 + 4];
            float4 bq = *(const float4*)&Bs[kk][tx * 4];
            unsigned long long am[4] = {la.x, la.y, lb.x, lb.y};
            unsigned long long bs[4] = {pk(bq.x, bq.x), pk(bq.y, bq.y),
                                        pk(bq.z, bq.z), pk(bq.w, bq.w)};
#pragma unroll
            for (int mp = 0; mp < 4; mp++)
#pragma unroll
                for (int n = 0; n < 4; n++)
                    cp[mp][n] = fma2(am[mp], bs[n], cp[mp][n]);
        }
        __syncthreads();
    }

    float4 b4 = *(const float4*)(bias + n0 + tx * 4);
#pragma unroll
    for (int mp = 0; mp < 4; mp++) {
        float lo[4], hi[4];
#pragma unroll
        for (int n = 0; n < 4; n++) upk(cp[mp][n], lo[n], hi[n]);
        float4 o0 = make_float4(lo[0] + b4.x, lo[1] + b4.y, lo[2] + b4.z, lo[3] + b4.w);
        float4 o1 = make_float4(hi[0] + b4.x, hi[1] + b4.y, hi[2] + b4.z, hi[3] + b4.w);
        if (RELU) {
            o0.x = fmaxf(o0.x, 0.f); o0.y = fmaxf(o0.y, 0.f);
            o0.z = fmaxf(o0.z, 0.f); o0.w = fmaxf(o0.w, 0.f);
            o1.x = fmaxf(o1.x, 0.f); o1.y = fmaxf(o1.y, 0.f);
            o1.w = fmaxf(o1.w, 0.f); o1.z = fmaxf(o1.z, 0.f);
        }
        int r0 = m0 + ty * 8 + mp * 2;
        if (r0 < M)     *(float4*)(C + (size_t)r0 * N + n0 + tx * 4) = o0;
        if (r0 + 1 < M) *(float4*)(C + (size_t)(r0 + 1) * N + n0 + tx * 4) = o1;
    }
}

// q = LN_ns(slots)@q_w^T + q_b ; hg = slots@gru_wh^T + gru_bh (22 rows)
__global__ void k_small(const float* __restrict__ slots,
                        const float* __restrict__ nsg, const float* __restrict__ nsb,
                        const float* __restrict__ qw, const float* __restrict__ qb,
                        const float* __restrict__ wh, const float* __restrict__ bh) {
    __shared__ float red[32];
    __shared__ float sraw[DD];
    __shared__ float sln[DD];
    int i = blockIdx.x, c = threadIdx.x;
    float x = slots[i * DD + c];
    sraw[c] = x;
    float mean = blockSum(x, red) * (1.f / 256.f);
    float d0 = x - mean;
    float var = blockSum(d0 * d0, red) * (1.f / 256.f);
    sln[c] = d0 * rsqrtf(var + 1e-5f) * nsg[c] + nsb[c];
    __syncthreads();
    float acc = qb[c];
    const float* wr = qw + (size_t)c * 256;
#pragma unroll 8
    for (int k = 0; k < 256; k++) acc += sln[k] * wr[k];
    g_qs[i * DD + c] = acc;
#pragma unroll
    for (int j = 0; j < 3; j++) {
        int u = j * 256 + c;
        float a = bh[u];
        const float* hr = wh + (size_t)u * 256;
#pragma unroll 8
        for (int k = 0; k < 256; k++) a += sraw[k] * hr[k];
        g_hg[i * 768 + u] = a;
    }
}

__device__ __forceinline__ void softmax_store(const unsigned long long* d,
                                              float* __restrict__ dst, int j) {
    float v[SS];
#pragma unroll
    for (int ip = 0; ip < 11; ip++) {
        float a, b;
        upk(d[ip], a, b);
        v[2 * ip] = a * 0.0625f;
        v[2 * ip + 1] = b * 0.0625f;
    }
    float mx = v[0];
#pragma unroll
    for (int i = 1; i < SS; i++) mx = fmaxf(mx, v[i]);
    float s = 0.f;
#pragma unroll
    for (int i = 0; i < SS; i++) { v[i] = __expf(v[i] - mx); s += v[i]; }
    float inv = 1.f / s;
#pragma unroll
    for (int i = 0; i < SS; i++) dst[i * NTOK + j] = v[i] * inv + 1e-8f;
}

// dots + softmax-over-slots + EPS; grid (BWIN, 4), 192 tokens per block
__global__ void __launch_bounds__(192) k_attn(float* __restrict__ out_attn,
                                              const float* __restrict__ kk) {
    __shared__ unsigned long long q2[11 * 256];
    __shared__ float ks[8][192];
    int bB = blockIdx.x, qa = blockIdx.y, tid = threadIdx.x;
    for (int idx = tid; idx < 11 * 256; idx += 192) {
        int ip = idx >> 8, k = idx & 255;
        q2[idx] = pk(g_qs[(2 * ip) * DD + k], g_qs[(2 * ip + 1) * DD + k]);
    }
    unsigned long long d[11];
#pragma unroll
    for (int ip = 0; ip < 11; ip++) d[ip] = 0ULL;
    size_t rowbase = (size_t)bB * NTOK + qa * 192;
    for (int kc = 0; kc < 256; kc += 8) {
        __syncthreads();
        const float4* src = (const float4*)(kk + (rowbase + tid) * 256 + kc);
        float4 v0 = src[0], v1 = src[1];
        ks[0][tid] = v0.x; ks[1][tid] = v0.y; ks[2][tid] = v0.z; ks[3][tid] = v0.w;
        ks[4][tid] = v1.x; ks[5][tid] = v1.y; ks[6][tid] = v1.z; ks[7][tid] = v1.w;
        __syncthreads();
#pragma unroll
        for (int kl = 0; kl < 8; kl++) {
            float kv = ks[kl][tid];
            unsigned long long sv = pk(kv, kv);
#pragma unroll
            for (int ip = 0; ip < 11; ip++)
                d[ip] = fma2(q2[ip * 256 + kc + kl], sv, d[ip]);
        }
    }
    int wi = bB / BATCH, bb = bB % BATCH;
    float* dst = out_attn + ((size_t)(bb * NWIN + wi)) * SS * NTOK;
    softmax_store(d, dst, qa * 192 + tid);
}

// renorm + weighted update; grid (BWIN, 2), 128 channels per block
__global__ void __launch_bounds__(128) k_upd(const float* __restrict__ attn,
                                             const float* __restrict__ vv) {
    __shared__ float red[32];
    __shared__ float sinv[SS];
    __shared__ unsigned long long at2[11 * 64];
    int bB = blockIdx.x, half = blockIdx.y, tid = threadIdx.x;
    int wi = bB / BATCH, bb = bB % BATCH;
    const float* ab = attn + ((size_t)(bb * NWIN + wi)) * SS * NTOK;
    for (int i = 0; i < SS; i++) {
        float p = 0.f;
        for (int j = tid; j < NTOK; j += 128) p += ab[i * NTOK + j];
        float s = blockSum(p, red);
        if (tid == 0) sinv[i] = 1.f / s;
    }
    __syncthreads();
    unsigned long long acc[11];
#pragma unroll
    for (int ip = 0; ip < 11; ip++) acc[ip] = 0ULL;
    int ch = half * 128 + tid;
    for (int j0 = 0; j0 < NTOK; j0 += 64) {
        for (int idx = tid; idx < 11 * 64; idx += 128) {
            int ip = idx >> 6, jj = idx & 63;
            at2[idx] = pk(ab[(2 * ip) * NTOK + j0 + jj],
                          ab[(2 * ip + 1) * NTOK + j0 + jj]);
        }
        __syncthreads();
        const float* vp = vv + ((size_t)bB * NTOK + j0) * 256 + ch;
#pragma unroll 4
        for (int jj = 0; jj < 64; jj++) {
            float v = vp[(size_t)jj * 256];
            unsigned long long sv = pk(v, v);
#pragma unroll
            for (int ip = 0; ip < 11; ip++)
                acc[ip] = fma2(at2[ip * 64 + jj], sv, acc[ip]);
        }
        __syncthreads();
    }
#pragma unroll
    for (int ip = 0; ip < 11; ip++) {
        float u0, u1;
        upk(acc[ip], u0, u1);
        g_upd[((size_t)bB * SS + 2 * ip) * DD + ch] = u0 * sinv[2 * ip];
        g_upd[((size_t)bB * SS + 2 * ip + 1) * DD + ch] = u1 * sinv[2 * ip + 1];
    }
}

__global__ void k_gate(const float* __restrict__ slots) {
    int m = blockIdx.x, c = threadIdx.x;
    int Bi = m / NAC, i = m % NAC;
    size_t row = (size_t)Bi * SS + i;
    float ir = g_xg[row * 768 + c];
    float iz = g_xg[row * 768 + 256 + c];
    float in_ = g_xg[row * 768 + 512 + c];
    float hr = g_hg[i * 768 + c];
    float hz = g_hg[i * 768 + 256 + c];
    float hn = g_hg[i * 768 + 512 + c];
    float h = slots[i * DD + c];
    float r = 1.f / (1.f + __expf(-(ir + hr)));
    float z = 1.f / (1.f + __expf(-(iz + hz)));
    float n = tanhf(in_ + r * hn);
    g_so[(size_t)m * DD + c] = (1.f - z) * n + z * h;
}

__global__ void k_final(float* __restrict__ out) {
    int m = blockIdx.x, c = threadIdx.x;
    int Bi = m / NAC, sl = m % NAC;
    int wi = Bi / BATCH, bb = Bi % BATCH;
    out[(((size_t)bb * NWIN + wi) * NAC + sl) * DD + c] =
        g_so[(size_t)m * DD + c] + g_t3[(size_t)m * DD + c];
}

extern "C" void kernel_launch(void* const* d_in, const int* in_sizes, int n_in,
                              void* d_out, int out_size) {
    const float* inputs = (const float*)d_in[0];
    const float* slots  = (const float*)d_in[1];
    const float* pe_w   = (const float*)d_in[2];
    const float* pe_b   = (const float*)d_in[3];
    const float* LN_g   = (const float*)d_in[4];
    const float* LN_b   = (const float*)d_in[5];
    const float* ni_g   = (const float*)d_in[6];
    const float* ni_b   = (const float*)d_in[7];
    const float* ns_g   = (const float*)d_in[8];
    const float* ns_b   = (const float*)d_in[9];
    const float* npf_g  = (const float*)d_in[10];
    const float* npf_b  = (const float*)d_in[11];
    const float* FC1_w  = (const float*)d_in[12];
    const float* FC1_b  = (const float*)d_in[13];
    const float* FC2_w  = (const float*)d_in[14];
    const float* FC2_b  = (const float*)d_in[15];
    const float* q_w    = (const float*)d_in[16];
    const float* q_b    = (const float*)d_in[17];
    const float* k_w    = (const float*)d_in[18];
    const float* k_b    = (const float*)d_in[19];
    const float* v_w    = (const float*)d_in[20];
    const float* v_b    = (const float*)d_in[21];
    const float* ff1_w  = (const float*)d_in[22];
    const float* ff1_b  = (const float*)d_in[23];
    const float* ff2_w  = (const float*)d_in[24];
    const float* ff2_b  = (const float*)d_in[25];
    const float* gru_wi = (const float*)d_in[26];
    const float* gru_wh = (const float*)d_in[27];
    const float* gru_bi = (const float*)d_in[28];
    const float* gru_bh = (const float*)d_in[29];

    float* out = (float*)d_out;
    float* out_attn = out + SLOTS_OUT_ELEMS;

    float *b0, *b1, *b2, *upd_, *xg_, *so_, *soln_, *t2_, *t3_;
    cudaGetSymbolAddress((void**)&b0, g_buf0);
    cudaGetSymbolAddress((void**)&b1, g_buf1);
    cudaGetSymbolAddress((void**)&b2, g_buf2);
    cudaGetSymbolAddress((void**)&upd_, g_upd);
    cudaGetSymbolAddress((void**)&xg_, g_xg);
    cudaGetSymbolAddress((void**)&so_, g_so);
    cudaGetSymbolAddress((void**)&soln_, g_soln);
    cudaGetSymbolAddress((void**)&t2_, g_t2);
    cudaGetSymbolAddress((void**)&t3_, g_t3);

    __nv_bfloat16 *w1h, *w1l, *w2h, *w2l, *wkh, *wkl, *wvh, *wvl;
    __nv_bfloat16 *x0h, *x0l, *x1h, *x1l, *x2h, *x2l;
    cudaGetSymbolAddress((void**)&w1h, g_w1h); cudaGetSymbolAddress((void**)&w1l, g_w1l);
    cudaGetSymbolAddress((void**)&w2h, g_w2h); cudaGetSymbolAddress((void**)&w2l, g_w2l);
    cudaGetSymbolAddress((void**)&wkh, g_wkh); cudaGetSymbolAddress((void**)&wkl, g_wkl);
    cudaGetSymbolAddress((void**)&wvh, g_wvh); cudaGetSymbolAddress((void**)&wvl, g_wvl);
    cudaGetSymbolAddress((void**)&x0h, g_x0h); cudaGetSymbolAddress((void**)&x0l, g_x0l);
    cudaGetSymbolAddress((void**)&x1h, g_x1h); cudaGetSymbolAddress((void**)&x1l, g_x1l);
    cudaGetSymbolAddress((void**)&x2h, g_x2h); cudaGetSymbolAddress((void**)&x2l, g_x2l);

    cudaFuncSetAttribute(k_mma<true, true>, cudaFuncAttributeMaxDynamicSharedMemorySize, MM_SMEM);
    cudaFuncSetAttribute(k_mma<false, false>, cudaFuncAttributeMaxDynamicSharedMemorySize, MM_SMEM);

    // split weights
    k_split4<<<1024, 256>>>(FC1_w, FC2_w, k_w, v_w);

    // positional embedding + gather + LN (split bf16 out)
    k_pe<<<NTOK, 256>>>(pe_w, pe_b);
    k_winln<<<MBIG / 8, 256>>>(inputs, LN_g, LN_b);

    dim3 gBig(MBIG / 128, 2);
    // FC1 (relu, split out) -> FC2 (fp32 out)
    k_mma<true, true><<<gBig, 256, MM_SMEM>>>(x0h, x0l, w1h, w1l, FC1_b,
                                              nullptr, x1h, x1l);
    k_mma<false, false><<<gBig, 256, MM_SMEM>>>(x1h, x1l, w2h, w2l, FC2_b,
                                                b0, nullptr, nullptr);

    // norm_input (split out), K and V projections (fp32 out)
    k_ln2<true><<<MBIG / 8, 256>>>(b0, nullptr, x2h, x2l, ni_g, ni_b);
    k_mma<false, false><<<gBig, 256, MM_SMEM>>>(x2h, x2l, wkh, wkl, k_b,
                                                b1, nullptr, nullptr);  // kk
    k_mma<false, false><<<gBig, 256, MM_SMEM>>>(x2h, x2l, wvh, wvl, v_b,
                                                b2, nullptr, nullptr);  // vv

    // batch-invariant q and hidden gates
    k_small<<<SS, 256>>>(slots, ns_g, ns_b, q_w, q_b, gru_wh, gru_bh);

    // dots + softmax-over-slots + EPS (writes attns output directly)
    dim3 gAttn(BWIN, 4);
    k_attn<<<gAttn, 192>>>(out_attn, b1);

    // renorm + weighted update
    dim3 gUpd(BWIN, 2);
    k_upd<<<gUpd, 128>>>(out_attn, b2);

    // GRU input gates GEMM: (4928x256)@(768x256)^T
    dim3 gGru((MGRU + 127) / 128, 12);
    k_gemm<false><<<gGru, 256>>>(upd_, gru_wi, gru_bi, xg_, MGRU, 768);

    // gates -> slots (first 20)
    k_gate<<<MSO, 256>>>(slots);

    // residual MLP
    k_ln2<false><<<MSO / 8, 256>>>(so_, soln_, nullptr, nullptr, npf_g, npf_b);
    dim3 gSo(MSO / 128, 4);
    k_gemm<true><<<gSo, 256>>>(soln_, ff1_w, ff1_b, t2_, MSO, 256);
    k_gemm<false><<<gSo, 256>>>(t2_, ff2_w, ff2_b, t3_, MSO, 256);

    // residual + permute into slots output
    k_final<<<MSO, 256>>>(out);
}

// round 7
// speedup vs baseline: 1.3303x; 1.0202x over previous
#include <cuda_runtime.h>
#include <cuda_bf16.h>
#include <math.h>
#include <stdint.h>

#define DD 256
#define SS 22
#define NAC 20
#define NTOK 768
#define NWIN 7
#define BATCH 32
#define BWIN 224
#define MBIG 172032
#define MGRU 4928
#define MGRUPAD 4992   // 39*128
#define MSO  4480
#define SLOTS_OUT_ELEMS 1146880  // 32*7*20*256

__device__ float g_pe[NTOK * DD];
__device__ float g_buf0[MBIG * DD];   // FC2 out (fp32, feeds LN)
__device__ float g_buf1[MBIG * DD];   // kk
__device__ float g_buf2[MBIG * DD];   // vv
__device__ __nv_bfloat16 g_x0h[MBIG * DD], g_x0l[MBIG * DD];  // winln out
__device__ __nv_bfloat16 g_x1h[MBIG * DD], g_x1l[MBIG * DD];  // FC1 out
__device__ __nv_bfloat16 g_x2h[MBIG * DD], g_x2l[MBIG * DD];  // ni-LN out
__device__ float g_qs[SS * DD];
__device__ float g_hg[SS * 768];
__device__ __nv_bfloat16 g_updh[MGRUPAD * DD], g_updl[MGRUPAD * DD];
__device__ float g_xg[MGRU * 768];
__device__ float g_so[MSO * DD];
__device__ __nv_bfloat16 g_solnh[MSO * DD], g_solnl[MSO * DD];
__device__ __nv_bfloat16 g_t2h[MSO * DD], g_t2l[MSO * DD];
__device__ float g_t3[MSO * DD];
// pre-split weights (hi/lo bf16)
__device__ __nv_bfloat16 g_w1h[65536], g_w1l[65536];
__device__ __nv_bfloat16 g_w2h[65536], g_w2l[65536];
__device__ __nv_bfloat16 g_wkh[65536], g_wkl[65536];
__device__ __nv_bfloat16 g_wvh[65536], g_wvl[65536];
__device__ __nv_bfloat16 g_wgh[196608], g_wgl[196608];
__device__ __nv_bfloat16 g_wf1h[65536], g_wf1l[65536];
__device__ __nv_bfloat16 g_wf2h[65536], g_wf2l[65536];

// ---------------- helpers ----------------
__device__ __forceinline__ uint32_t smem_u32(const void* p) {
    uint32_t a;
    asm("{ .reg .u64 t; cvta.to.shared.u64 t, %1; cvt.u32.u64 %0, t; }" : "=r"(a) : "l"(p));
    return a;
}
__device__ __forceinline__ unsigned long long pk(float x, float y) {
    unsigned long long r;
    asm("mov.b64 %0, {%1,%2};" : "=l"(r) : "f"(x), "f"(y));
    return r;
}
__device__ __forceinline__ void upk(unsigned long long v, float& x, float& y) {
    asm("mov.b64 {%0,%1}, %2;" : "=f"(x), "=f"(y) : "l"(v));
}
__device__ __forceinline__ unsigned long long fma2(unsigned long long a,
                                                   unsigned long long b,
                                                   unsigned long long c) {
    unsigned long long d;
    asm("fma.rn.f32x2 %0, %1, %2, %3;" : "=l"(d) : "l"(a), "l"(b), "l"(c));
    return d;
}
__device__ __forceinline__ uint32_t bfpack(float a, float b) {
    __nv_bfloat162 t = __floats2bfloat162_rn(a, b);
    return *reinterpret_cast<uint32_t*>(&t);
}
__device__ __forceinline__ void ldsm4(uint32_t* r, uint32_t addr) {
    asm volatile("ldmatrix.sync.aligned.m8n8.x4.shared.b16 {%0,%1,%2,%3}, [%4];"
        : "=r"(r[0]), "=r"(r[1]), "=r"(r[2]), "=r"(r[3]) : "r"(addr));
}
__device__ __forceinline__ void mma16816(float* d, const uint32_t* a,
                                         uint32_t b0, uint32_t b1) {
    asm volatile(
        "mma.sync.aligned.m16n8k16.row.col.f32.bf16.bf16.f32 "
        "{%0,%1,%2,%3}, {%4,%5,%6,%7}, {%8,%9}, {%0,%1,%2,%3};"
        : "+f"(d[0]), "+f"(d[1]), "+f"(d[2]), "+f"(d[3])
        : "r"(a[0]), "r"(a[1]), "r"(a[2]), "r"(a[3]), "r"(b0), "r"(b1));
}
__device__ __forceinline__ void cp16(uint32_t sm, const void* g) {
    asm volatile("cp.async.cg.shared.global [%0], [%1], 16;" :: "r"(sm), "l"(g));
}
__device__ __forceinline__ void cp_commit() {
    asm volatile("cp.async.commit_group;" ::: "memory");
}
template <int N>
__device__ __forceinline__ void cp_wait() {
    asm volatile("cp.async.wait_group %0;" :: "n"(N) : "memory");
}

__device__ __forceinline__ float blockSum(float v, float* s) {
    int tid = threadIdx.x;
#pragma unroll
    for (int o = 16; o > 0; o >>= 1) v += __shfl_down_sync(0xffffffffu, v, o);
    if ((tid & 31) == 0) s[tid >> 5] = v;
    __syncthreads();
    float r = (tid < (int)(blockDim.x >> 5)) ? s[tid] : 0.f;
    if (tid < 32) {
#pragma unroll
        for (int o = 4; o > 0; o >>= 1) r += __shfl_down_sync(0xffffffffu, r, o);
    }
    if (tid == 0) s[0] = r;
    __syncthreads();
    r = s[0];
    __syncthreads();
    return r;
}

// ---------------- small kernels ----------------
__global__ void k_pe(const float* __restrict__ pe_w, const float* __restrict__ pe_b) {
    int p = blockIdx.x, c = threadIdx.x;
    int t = p / 192, rem = p % 192, y = rem / 24, x = rem % 24;
    float g0 = t * (1.f / 3.f), g1 = y * (1.f / 7.f), g2 = x * (1.f / 23.f);
    const float* wr = pe_w + c * 6;
    g_pe[p * DD + c] = pe_b[c] + wr[0] * g0 + wr[1] * g1 + wr[2] * g2
        + wr[3] * (1.f - g0) + wr[4] * (1.f - g1) + wr[5] * (1.f - g2);
}

// warp-per-row: gather window + pe + LN -> split bf16
__global__ void __launch_bounds__(256) k_winln(const float* __restrict__ inp,
                                               const float* __restrict__ gam,
                                               const float* __restrict__ bet) {
    int m = (blockIdx.x * 256 + threadIdx.x) >> 5;
    int lane = threadIdx.x & 31;
    int wiB = m / NTOK, p = m % NTOK;
    int wi = wiB / BATCH, bb = wiB % BATCH;
    int t = p / 192, rem = p % 192;
    int f = 2 * wi + t;
    const float* src = inp + ((size_t)(bb * 16 + f) * 192 + rem) * DD;
    const float* pe = g_pe + p * DD;
    float x[8], s = 0.f, sq = 0.f;
#pragma unroll
    for (int i = 0; i < 8; i++) {
        int c = lane + i * 32;
        x[i] = src[c] + pe[c];
        s += x[i];
        sq += x[i] * x[i];
    }
#pragma unroll
    for (int o = 16; o > 0; o >>= 1) {
        s += __shfl_xor_sync(0xffffffffu, s, o);
        sq += __shfl_xor_sync(0xffffffffu, sq, o);
    }
    float mean = s * (1.f / 256.f);
    float var = sq * (1.f / 256.f) - mean * mean;
    float rs = rsqrtf(var + 1e-5f);
#pragma unroll
    for (int i = 0; i < 8; i++) {
        int c = lane + i * 32;
        float y = (x[i] - mean) * rs * gam[c] + bet[c];
        __nv_bfloat16 h = __float2bfloat16(y);
        g_x0h[(size_t)m * DD + c] = h;
        g_x0l[(size_t)m * DD + c] = __float2bfloat16(y - __bfloat162float(h));
    }
}

// warp-per-row LN -> split bf16
__global__ void __launch_bounds__(256) k_ln2(const float* __restrict__ src,
                                             __nv_bfloat16* __restrict__ dsth,
                                             __nv_bfloat16* __restrict__ dstl,
                                             const float* __restrict__ gam,
                                             const float* __restrict__ bet) {
    int m = (blockIdx.x * 256 + threadIdx.x) >> 5;
    int lane = threadIdx.x & 31;
    const float* sp = src + (size_t)m * DD;
    float x[8], s = 0.f, sq = 0.f;
#pragma unroll
    for (int i = 0; i < 8; i++) {
        x[i] = sp[lane + i * 32];
        s += x[i];
        sq += x[i] * x[i];
    }
#pragma unroll
    for (int o = 16; o > 0; o >>= 1) {
        s += __shfl_xor_sync(0xffffffffu, s, o);
        sq += __shfl_xor_sync(0xffffffffu, sq, o);
    }
    float mean = s * (1.f / 256.f);
    float var = sq * (1.f / 256.f) - mean * mean;
    float rs = rsqrtf(var + 1e-5f);
#pragma unroll
    for (int i = 0; i < 8; i++) {
        int c = lane + i * 32;
        float y = (x[i] - mean) * rs * gam[c] + bet[c];
        __nv_bfloat16 h = __float2bfloat16(y);
        dsth[(size_t)m * DD + c] = h;
        dstl[(size_t)m * DD + c] = __float2bfloat16(y - __bfloat162float(h));
    }
}

// split ALL weights in one launch: fp32 -> hi/lo bf16
// layout: [w1 w2 wk wv | wg(196608) | wf1 wf2] = 589824 elements
__global__ void k_splitall(const float* __restrict__ w1, const float* __restrict__ w2,
                           const float* __restrict__ wk, const float* __restrict__ wv,
                           const float* __restrict__ wg, const float* __restrict__ wf1,
                           const float* __restrict__ wf2) {
    int idx = blockIdx.x * 256 + threadIdx.x;
    const float* src;
    __nv_bfloat16 *h, *l;
    int j;
    if (idx < 262144) {
        int which = idx >> 16; j = idx & 65535;
        src = (which == 0) ? w1 : (which == 1) ? w2 : (which == 2) ? wk : wv;
        h = (which == 0) ? g_w1h : (which == 1) ? g_w2h : (which == 2) ? g_wkh : g_wvh;
        l = (which == 0) ? g_w1l : (which == 1) ? g_w2l : (which == 2) ? g_wkl : g_wvl;
    } else if (idx < 458752) {
        j = idx - 262144; src = wg; h = g_wgh; l = g_wgl;
    } else if (idx < 524288) {
        j = idx - 458752; src = wf1; h = g_wf1h; l = g_wf1l;
    } else {
        j = idx - 524288; src = wf2; h = g_wf2h; l = g_wf2l;
    }
    float x = src[j];
    __nv_bfloat16 hh = __float2bfloat16(x);
    h[j] = hh;
    l[j] = __float2bfloat16(x - __bfloat162float(hh));
}

// ---------------- all-async split-bf16 mma GEMM ----------------
// C[M,N] = A[M,256] @ W[N,256]^T + bias; A,W pre-split bf16 hi/lo.
// CTA 128x128, BK=32, 8 chunks, 2-stage cp.async, 2 CTAs/SM.
// mma inner loop is pass-major within each p: same-accumulator distance 4.
#define ROW2 80      // 32 bf16 (64B) + 16B pad
#define MAT2 10240   // 128 * 80
#define STG2 40960
#define MM_SMEM 81920

template <bool RELU, bool SPLIT, bool MBOUND>
__global__ void __launch_bounds__(256, 2) k_mma(
    const __nv_bfloat16* __restrict__ Ah, const __nv_bfloat16* __restrict__ Al,
    const __nv_bfloat16* __restrict__ Wh, const __nv_bfloat16* __restrict__ Wl,
    const float* __restrict__ bias, float* __restrict__ C,
    __nv_bfloat16* __restrict__ Ch, __nv_bfloat16* __restrict__ Cl,
    int M, int N) {
    extern __shared__ char sm[];
    int tid = threadIdx.x, lane = tid & 31, wid = tid >> 5;
    int m0 = blockIdx.x * 128, n0 = blockIdx.y * 128;
    int mw = wid & 3, nw = wid >> 2;
    uint32_t sb = smem_u32(sm);

    float acc[2][8][4];
#pragma unroll
    for (int i = 0; i < 2; i++)
#pragma unroll
        for (int j = 0; j < 8; j++)
#pragma unroll
            for (int k = 0; k < 4; k++) acc[i][j][k] = 0.f;

    auto cpStage = [&](int ch, int buf) {
        int k0 = ch * 32;
        uint32_t st = sb + (uint32_t)buf * STG2;
#pragma unroll
        for (int i = 0; i < 2; i++) {
            int idx = tid + i * 256;
            int row = idx >> 2, g = idx & 3;
            uint32_t off = (uint32_t)row * ROW2 + g * 16;
            size_t ga = (size_t)(m0 + row) * 256 + k0 + g * 8;
            size_t gb = (size_t)(n0 + row) * 256 + k0 + g * 8;
            cp16(st + off, Ah + ga);
            cp16(st + MAT2 + off, Al + ga);
            cp16(st + 2 * MAT2 + off, Wh + gb);
            cp16(st + 3 * MAT2 + off, Wl + gb);
        }
    };

    cpStage(0, 0); cp_commit();
    cpStage(1, 1); cp_commit();

#pragma unroll
    for (int ch = 0; ch < 8; ch++) {
        if (ch < 7) cp_wait<1>(); else cp_wait<0>();
        __syncthreads();
        uint32_t st = sb + (uint32_t)(ch & 1) * STG2;
#pragma unroll
        for (int ks = 0; ks < 2; ks++) {
            int k = ks * 16;
            uint32_t ah[2][4], al[2][4];
#pragma unroll
            for (int mt = 0; mt < 2; mt++) {
                uint32_t addr = st
                    + (uint32_t)(mw * 32 + mt * 16 + (lane & 15)) * ROW2
                    + (uint32_t)(k + (lane >> 4) * 8) * 2;
                ldsm4(ah[mt], addr);
                ldsm4(al[mt], addr + MAT2);
            }
#pragma unroll
            for (int p = 0; p < 4; p++) {
                uint32_t ba = st + 2 * MAT2
                    + (uint32_t)(nw * 64 + p * 16 + (lane & 15)) * ROW2
                    + (uint32_t)(k + (lane >> 4) * 8) * 2;
                uint32_t bh[4], bl[4];
                ldsm4(bh, ba);
                ldsm4(bl, ba + MAT2);
                // pass-major: 4 distinct accumulators between reuses
                mma16816(acc[0][2 * p],     ah[0], bh[0], bh[2]);
                mma16816(acc[0][2 * p + 1], ah[0], bh[1], bh[3]);
                mma16816(acc[1][2 * p],     ah[1], bh[0], bh[2]);
                mma16816(acc[1][2 * p + 1], ah[1], bh[1], bh[3]);
                mma16816(acc[0][2 * p],     ah[0], bl[0], bl[2]);
                mma16816(acc[0][2 * p + 1], ah[0], bl[1], bl[3]);
                mma16816(acc[1][2 * p],     ah[1], bl[0], bl[2]);
                mma16816(acc[1][2 * p + 1], ah[1], bl[1], bl[3]);
                mma16816(acc[0][2 * p],     al[0], bh[0], bh[2]);
                mma16816(acc[0][2 * p + 1], al[0], bh[1], bh[3]);
                mma16816(acc[1][2 * p],     al[1], bh[0], bh[2]);
                mma16816(acc[1][2 * p + 1], al[1], bh[1], bh[3]);
            }
        }
        __syncthreads();
        if (ch < 6) { cpStage(ch + 2, ch & 1); cp_commit(); }
    }

    // epilogue
#pragma unroll
    for (int nt = 0; nt < 8; nt++) {
        int col = n0 + nw * 64 + nt * 8 + (lane & 3) * 2;
        float bx = bias[col], by = bias[col + 1];
#pragma unroll
        for (int mt = 0; mt < 2; mt++) {
            int row = m0 + mw * 32 + mt * 16 + (lane >> 2);
            float* a = acc[mt][nt];
            float2 o0 = make_float2(a[0] + bx, a[1] + by);
            float2 o1 = make_float2(a[2] + bx, a[3] + by);
            if (RELU) {
                o0.x = fmaxf(o0.x, 0.f); o0.y = fmaxf(o0.y, 0.f);
                o1.x = fmaxf(o1.x, 0.f); o1.y = fmaxf(o1.y, 0.f);
            }
            bool w0 = !MBOUND || row < M;
            bool w1 = !MBOUND || row + 8 < M;
            if (SPLIT) {
                __nv_bfloat162 h0 = __floats2bfloat162_rn(o0.x, o0.y);
                __nv_bfloat162 h1 = __floats2bfloat162_rn(o1.x, o1.y);
                uint32_t L0 = bfpack(o0.x - __bfloat162float(h0.x),
                                     o0.y - __bfloat162float(h0.y));
                uint32_t L1 = bfpack(o1.x - __bfloat162float(h1.x),
                                     o1.y - __bfloat162float(h1.y));
                if (w0) {
                    *reinterpret_cast<uint32_t*>(Ch + (size_t)row * N + col) =
                        *reinterpret_cast<uint32_t*>(&h0);
                    *reinterpret_cast<uint32_t*>(Cl + (size_t)row * N + col) = L0;
                }
                if (w1) {
                    *reinterpret_cast<uint32_t*>(Ch + (size_t)(row + 8) * N + col) =
                        *reinterpret_cast<uint32_t*>(&h1);
                    *reinterpret_cast<uint32_t*>(Cl + (size_t)(row + 8) * N + col) = L1;
                }
            } else {
                if (w0) *reinterpret_cast<float2*>(C + (size_t)row * N + col) = o0;
                if (w1) *reinterpret_cast<float2*>(C + (size_t)(row + 8) * N + col) = o1;
            }
        }
    }
}

// q = LN_ns(slots)@q_w^T + q_b ; hg = slots@gru_wh^T + gru_bh (22 rows)
__global__ void k_small(const float* __restrict__ slots,
                        const float* __restrict__ nsg, const float* __restrict__ nsb,
                        const float* __restrict__ qw, const float* __restrict__ qb,
                        const float* __restrict__ wh, const float* __restrict__ bh) {
    __shared__ float red[32];
    __shared__ float sraw[DD];
    __shared__ float sln[DD];
    int i = blockIdx.x, c = threadIdx.x;
    float x = slots[i * DD + c];
    sraw[c] = x;
    float mean = blockSum(x, red) * (1.f / 256.f);
    float d0 = x - mean;
    float var = blockSum(d0 * d0, red) * (1.f / 256.f);
    sln[c] = d0 * rsqrtf(var + 1e-5f) * nsg[c] + nsb[c];
    __syncthreads();
    float acc = qb[c];
    const float* wr = qw + (size_t)c * 256;
#pragma unroll 8
    for (int k = 0; k < 256; k++) acc += sln[k] * wr[k];
    g_qs[i * DD + c] = acc;
#pragma unroll
    for (int j = 0; j < 3; j++) {
        int u = j * 256 + c;
        float a = bh[u];
        const float* hr = wh + (size_t)u * 256;
#pragma unroll 8
        for (int k = 0; k < 256; k++) a += sraw[k] * hr[k];
        g_hg[i * 768 + u] = a;
    }
}

__device__ __forceinline__ void softmax_store(const unsigned long long* d,
                                              float* __restrict__ dst, int j) {
    float v[SS];
#pragma unroll
    for (int ip = 0; ip < 11; ip++) {
        float a, b;
        upk(d[ip], a, b);
        v[2 * ip] = a * 0.0625f;
        v[2 * ip + 1] = b * 0.0625f;
    }
    float mx = v[0];
#pragma unroll
    for (int i = 1; i < SS; i++) mx = fmaxf(mx, v[i]);
    float s = 0.f;
#pragma unroll
    for (int i = 0; i < SS; i++) { v[i] = __expf(v[i] - mx); s += v[i]; }
    float inv = 1.f / s;
#pragma unroll
    for (int i = 0; i < SS; i++) dst[i * NTOK + j] = v[i] * inv + 1e-8f;
}

// dots + softmax-over-slots + EPS; grid (BWIN, 4), 192 tokens per block
__global__ void __launch_bounds__(192) k_attn(float* __restrict__ out_attn,
                                              const float* __restrict__ kk) {
    __shared__ unsigned long long q2[11 * 256];
    __shared__ float ks[8][192];
    int bB = blockIdx.x, qa = blockIdx.y, tid = threadIdx.x;
    for (int idx = tid; idx < 11 * 256; idx += 192) {
        int ip = idx >> 8, k = idx & 255;
        q2[idx] = pk(g_qs[(2 * ip) * DD + k], g_qs[(2 * ip + 1) * DD + k]);
    }
    unsigned long long d[11];
#pragma unroll
    for (int ip = 0; ip < 11; ip++) d[ip] = 0ULL;
    size_t rowbase = (size_t)bB * NTOK + qa * 192;
    for (int kc = 0; kc < 256; kc += 8) {
        __syncthreads();
        const float4* src = (const float4*)(kk + (rowbase + tid) * 256 + kc);
        float4 v0 = src[0], v1 = src[1];
        ks[0][tid] = v0.x; ks[1][tid] = v0.y; ks[2][tid] = v0.z; ks[3][tid] = v0.w;
        ks[4][tid] = v1.x; ks[5][tid] = v1.y; ks[6][tid] = v1.z; ks[7][tid] = v1.w;
        __syncthreads();
#pragma unroll
        for (int kl = 0; kl < 8; kl++) {
            float kv = ks[kl][tid];
            unsigned long long sv = pk(kv, kv);
#pragma unroll
            for (int ip = 0; ip < 11; ip++)
                d[ip] = fma2(q2[ip * 256 + kc + kl], sv, d[ip]);
        }
    }
    int wi = bB / BATCH, bb = bB % BATCH;
    float* dst = out_attn + ((size_t)(bb * NWIN + wi)) * SS * NTOK;
    softmax_store(d, dst, qa * 192 + tid);
}

// renorm + weighted update -> split bf16; grid (BWIN, 2), 128 channels per block
__global__ void __launch_bounds__(128) k_upd(const float* __restrict__ attn,
                                             const float* __restrict__ vv) {
    __shared__ float red[32];
    __shared__ float sinv[SS];
    __shared__ unsigned long long at2[11 * 64];
    int bB = blockIdx.x, half = blockIdx.y, tid = threadIdx.x;
    int wi = bB / BATCH, bb = bB % BATCH;
    const float* ab = attn + ((size_t)(bb * NWIN + wi)) * SS * NTOK;
    for (int i = 0; i < SS; i++) {
        float p = 0.f;
        for (int j = tid; j < NTOK; j += 128) p += ab[i * NTOK + j];
        float s = blockSum(p, red);
        if (tid == 0) sinv[i] = 1.f / s;
    }
    __syncthreads();
    unsigned long long acc[11];
#pragma unroll
    for (int ip = 0; ip < 11; ip++) acc[ip] = 0ULL;
    int ch = half * 128 + tid;
    for (int j0 = 0; j0 < NTOK; j0 += 64) {
        for (int idx = tid; idx < 11 * 64; idx += 128) {
            int ip = idx >> 6, jj = idx & 63;
            at2[idx] = pk(ab[(2 * ip) * NTOK + j0 + jj],
                          ab[(2 * ip + 1) * NTOK + j0 + jj]);
        }
        __syncthreads();
        const float* vp = vv + ((size_t)bB * NTOK + j0) * 256 + ch;
#pragma unroll 4
        for (int jj = 0; jj < 64; jj++) {
            float v = vp[(size_t)jj * 256];
            unsigned long long sv = pk(v, v);
#pragma unroll
            for (int ip = 0; ip < 11; ip++)
                acc[ip] = fma2(at2[ip * 64 + jj], sv, acc[ip]);
        }
        __syncthreads();
    }
#pragma unroll
    for (int ip = 0; ip < 11; ip++) {
        float u0, u1;
        upk(acc[ip], u0, u1);
        u0 *= sinv[2 * ip];
        u1 *= sinv[2 * ip + 1];
        __nv_bfloat16 h0 = __float2bfloat16(u0);
        __nv_bfloat16 h1 = __float2bfloat16(u1);
        size_t r0 = ((size_t)bB * SS + 2 * ip) * DD + ch;
        size_t r1 = ((size_t)bB * SS + 2 * ip + 1) * DD + ch;
        g_updh[r0] = h0; g_updl[r0] = __float2bfloat16(u0 - __bfloat162float(h0));
        g_updh[r1] = h1; g_updl[r1] = __float2bfloat16(u1 - __bfloat162float(h1));
    }
}

__global__ void k_gate(const float* __restrict__ slots) {
    int m = blockIdx.x, c = threadIdx.x;
    int Bi = m / NAC, i = m % NAC;
    size_t row = (size_t)Bi * SS + i;
    float ir = g_xg[row * 768 + c];
    float iz = g_xg[row * 768 + 256 + c];
    float in_ = g_xg[row * 768 + 512 + c];
    float hr = g_hg[i * 768 + c];
    float hz = g_hg[i * 768 + 256 + c];
    float hn = g_hg[i * 768 + 512 + c];
    float h = slots[i * DD + c];
    float r = 1.f / (1.f + __expf(-(ir + hr)));
    float z = 1.f / (1.f + __expf(-(iz + hz)));
    float n = tanhf(in_ + r * hn);
    g_so[(size_t)m * DD + c] = (1.f - z) * n + z * h;
}

__global__ void k_final(float* __restrict__ out) {
    int m = blockIdx.x, c = threadIdx.x;
    int Bi = m / NAC, sl = m % NAC;
    int wi = Bi / BATCH, bb = Bi % BATCH;
    out[(((size_t)bb * NWIN + wi) * NAC + sl) * DD + c] =
        g_so[(size_t)m * DD + c] + g_t3[(size_t)m * DD + c];
}

extern "C" void kernel_launch(void* const* d_in, const int* in_sizes, int n_in,
                              void* d_out, int out_size) {
    const float* inputs = (const float*)d_in[0];
    const float* slots  = (const float*)d_in[1];
    const float* pe_w   = (const float*)d_in[2];
    const float* pe_b   = (const float*)d_in[3];
    const float* LN_g   = (const float*)d_in[4];
    const float* LN_b   = (const float*)d_in[5];
    const float* ni_g   = (const float*)d_in[6];
    const float* ni_b   = (const float*)d_in[7];
    const float* ns_g   = (const float*)d_in[8];
    const float* ns_b   = (const float*)d_in[9];
    const float* npf_g  = (const float*)d_in[10];
    const float* npf_b  = (const float*)d_in[11];
    const float* FC1_w  = (const float*)d_in[12];
    const float* FC1_b  = (const float*)d_in[13];
    const float* FC2_w  = (const float*)d_in[14];
    const float* FC2_b  = (const float*)d_in[15];
    const float* q_w    = (const float*)d_in[16];
    const float* q_b    = (const float*)d_in[17];
    const float* k_w    = (const float*)d_in[18];
    const float* k_b    = (const float*)d_in[19];
    const float* v_w    = (const float*)d_in[20];
    const float* v_b    = (const float*)d_in[21];
    const float* ff1_w  = (const float*)d_in[22];
    const float* ff1_b  = (const float*)d_in[23];
    const float* ff2_w  = (const float*)d_in[24];
    const float* ff2_b  = (const float*)d_in[25];
    const float* gru_wi = (const float*)d_in[26];
    const float* gru_wh = (const float*)d_in[27];
    const float* gru_bi = (const float*)d_in[28];
    const float* gru_bh = (const float*)d_in[29];

    float* out = (float*)d_out;
    float* out_attn = out + SLOTS_OUT_ELEMS;

    float *b0, *b1, *b2, *xg_, *so_, *t3_;
    cudaGetSymbolAddress((void**)&b0, g_buf0);
    cudaGetSymbolAddress((void**)&b1, g_buf1);
    cudaGetSymbolAddress((void**)&b2, g_buf2);
    cudaGetSymbolAddress((void**)&xg_, g_xg);
    cudaGetSymbolAddress((void**)&so_, g_so);
    cudaGetSymbolAddress((void**)&t3_, g_t3);

    __nv_bfloat16 *w1h, *w1l, *w2h, *w2l, *wkh, *wkl, *wvh, *wvl;
    __nv_bfloat16 *wgh, *wgl, *wf1h, *wf1l, *wf2h, *wf2l;
    __nv_bfloat16 *x0h, *x0l, *x1h, *x1l, *x2h, *x2l;
    __nv_bfloat16 *uh, *ul, *snh, *snl, *t2h, *t2l;
    cudaGetSymbolAddress((void**)&w1h, g_w1h); cudaGetSymbolAddress((void**)&w1l, g_w1l);
    cudaGetSymbolAddress((void**)&w2h, g_w2h); cudaGetSymbolAddress((void**)&w2l, g_w2l);
    cudaGetSymbolAddress((void**)&wkh, g_wkh); cudaGetSymbolAddress((void**)&wkl, g_wkl);
    cudaGetSymbolAddress((void**)&wvh, g_wvh); cudaGetSymbolAddress((void**)&wvl, g_wvl);
    cudaGetSymbolAddress((void**)&wgh, g_wgh); cudaGetSymbolAddress((void**)&wgl, g_wgl);
    cudaGetSymbolAddress((void**)&wf1h, g_wf1h); cudaGetSymbolAddress((void**)&wf1l, g_wf1l);
    cudaGetSymbolAddress((void**)&wf2h, g_wf2h); cudaGetSymbolAddress((void**)&wf2l, g_wf2l);
    cudaGetSymbolAddress((void**)&x0h, g_x0h); cudaGetSymbolAddress((void**)&x0l, g_x0l);
    cudaGetSymbolAddress((void**)&x1h, g_x1h); cudaGetSymbolAddress((void**)&x1l, g_x1l);
    cudaGetSymbolAddress((void**)&x2h, g_x2h); cudaGetSymbolAddress((void**)&x2l, g_x2l);
    cudaGetSymbolAddress((void**)&uh, g_updh); cudaGetSymbolAddress((void**)&ul, g_updl);
    cudaGetSymbolAddress((void**)&snh, g_solnh); cudaGetSymbolAddress((void**)&snl, g_solnl);
    cudaGetSymbolAddress((void**)&t2h, g_t2h); cudaGetSymbolAddress((void**)&t2l, g_t2l);

    cudaFuncSetAttribute((const void*)k_mma<true, true, false>,
                         cudaFuncAttributeMaxDynamicSharedMemorySize, MM_SMEM);
    cudaFuncSetAttribute((const void*)k_mma<false, false, false>,
                         cudaFuncAttributeMaxDynamicSharedMemorySize, MM_SMEM);
    cudaFuncSetAttribute((const void*)k_mma<false, false, true>,
                         cudaFuncAttributeMaxDynamicSharedMemorySize, MM_SMEM);

    // split all weights (one launch)
    k_splitall<<<2304, 256>>>(FC1_w, FC2_w, k_w, v_w, gru_wi, ff1_w, ff2_w);

    // positional embedding + gather + LN (split bf16 out)
    k_pe<<<NTOK, 256>>>(pe_w, pe_b);
    k_winln<<<MBIG / 8, 256>>>(inputs, LN_g, LN_b);

    dim3 gBig(MBIG / 128, 2);
    // FC1 (relu, split out) -> FC2 (fp32 out)
    k_mma<true, true, false><<<gBig, 256, MM_SMEM>>>(x0h, x0l, w1h, w1l, FC1_b,
                                                     nullptr, x1h, x1l, MBIG, 256);
    k_mma<false, false, false><<<gBig, 256, MM_SMEM>>>(x1h, x1l, w2h, w2l, FC2_b,
                                                       b0, nullptr, nullptr, MBIG, 256);

    // norm_input (split out), K and V projections (fp32 out)
    k_ln2<<<MBIG / 8, 256>>>(b0, x2h, x2l, ni_g, ni_b);
    k_mma<false, false, false><<<gBig, 256, MM_SMEM>>>(x2h, x2l, wkh, wkl, k_b,
                                                       b1, nullptr, nullptr, MBIG, 256);
    k_mma<false, false, false><<<gBig, 256, MM_SMEM>>>(x2h, x2l, wvh, wvl, v_b,
                                                       b2, nullptr, nullptr, MBIG, 256);

    // batch-invariant q and hidden gates
    k_small<<<SS, 256>>>(slots, ns_g, ns_b, q_w, q_b, gru_wh, gru_bh);

    // dots + softmax-over-slots + EPS (writes attns output directly)
    dim3 gAttn(BWIN, 4);
    k_attn<<<gAttn, 192>>>(out_attn, b1);

    // renorm + weighted update (split bf16 out)
    dim3 gUpd(BWIN, 2);
    k_upd<<<gUpd, 128>>>(out_attn, b2);

    // GRU input gates GEMM on tensor cores: (4928x256)@(768x256)^T
    dim3 gGru(MGRUPAD / 128, 6);
    k_mma<false, false, true><<<gGru, 256, MM_SMEM>>>(uh, ul, wgh, wgl, gru_bi,
                                                      xg_, nullptr, nullptr, MGRU, 768);

    // gates -> slots (first 20)
    k_gate<<<MSO, 256>>>(slots);

    // residual MLP on tensor cores
    k_ln2<<<MSO / 8, 256>>>(so_, snh, snl, npf_g, npf_b);
    dim3 gSo(MSO / 128, 2);
    k_mma<true, true, false><<<gSo, 256, MM_SMEM>>>(snh, snl, wf1h, wf1l, ff1_b,
                                                    nullptr, t2h, t2l, MSO, 256);
    k_mma<false, false, false><<<gSo, 256, MM_SMEM>>>(t2h, t2l, wf2h, wf2l, ff2_b,
                                                      t3_, nullptr, nullptr, MSO, 256);

    // residual + permute into slots output
    k_final<<<MSO, 256>>>(out);
}

// round 8
// speedup vs baseline: 1.3320x; 1.0013x over previous
#include <cuda_runtime.h>
#include <cuda_bf16.h>
#include <math.h>
#include <stdint.h>

#define DD 256
#define SS 22
#define NAC 20
#define NTOK 768
#define NWIN 7
#define BATCH 32
#define BWIN 224
#define MBIG 172032
#define MGRU 4928
#define MGRUPAD 4992   // 39*128
#define MSO  4480
#define SLOTS_OUT_ELEMS 1146880  // 32*7*20*256

__device__ float g_pe[NTOK * DD];
__device__ float g_buf0[MBIG * DD];   // FC2 out (fp32, feeds LN)
__device__ float g_buf1[MBIG * DD];   // kk
__device__ float g_buf2[MBIG * DD];   // vv
__device__ __nv_bfloat16 g_x0h[MBIG * DD], g_x0l[MBIG * DD];  // winln out
__device__ __nv_bfloat16 g_x1h[MBIG * DD], g_x1l[MBIG * DD];  // FC1 out
__device__ __nv_bfloat16 g_x2h[MBIG * DD], g_x2l[MBIG * DD];  // ni-LN out
__device__ float g_qs[SS * DD];
__device__ float g_hg[SS * 768];
__device__ __nv_bfloat16 g_updh[MGRUPAD * DD], g_updl[MGRUPAD * DD];
__device__ float g_xg[MGRU * 768];
__device__ float g_so[MSO * DD];
__device__ __nv_bfloat16 g_solnh[MSO * DD], g_solnl[MSO * DD];
__device__ __nv_bfloat16 g_t2h[MSO * DD], g_t2l[MSO * DD];
__device__ float g_t3[MSO * DD];
// pre-split weights (hi/lo bf16)
__device__ __nv_bfloat16 g_w1h[65536], g_w1l[65536];
__device__ __nv_bfloat16 g_w2h[65536], g_w2l[65536];
__device__ __nv_bfloat16 g_wkvh[131072], g_wkvl[131072];   // K||V concat
__device__ float g_bkv[512];
__device__ __nv_bfloat16 g_wgh[196608], g_wgl[196608];
__device__ __nv_bfloat16 g_wf1h[65536], g_wf1l[65536];
__device__ __nv_bfloat16 g_wf2h[65536], g_wf2l[65536];

// ---------------- helpers ----------------
__device__ __forceinline__ uint32_t smem_u32(const void* p) {
    uint32_t a;
    asm("{ .reg .u64 t; cvta.to.shared.u64 t, %1; cvt.u32.u64 %0, t; }" : "=r"(a) : "l"(p));
    return a;
}
__device__ __forceinline__ unsigned long long pk(float x, float y) {
    unsigned long long r;
    asm("mov.b64 %0, {%1,%2};" : "=l"(r) : "f"(x), "f"(y));
    return r;
}
__device__ __forceinline__ void upk(unsigned long long v, float& x, float& y) {
    asm("mov.b64 {%0,%1}, %2;" : "=f"(x), "=f"(y) : "l"(v));
}
__device__ __forceinline__ unsigned long long fma2(unsigned long long a,
                                                   unsigned long long b,
                                                   unsigned long long c) {
    unsigned long long d;
    asm("fma.rn.f32x2 %0, %1, %2, %3;" : "=l"(d) : "l"(a), "l"(b), "l"(c));
    return d;
}
__device__ __forceinline__ uint32_t bfpack(float a, float b) {
    __nv_bfloat162 t = __floats2bfloat162_rn(a, b);
    return *reinterpret_cast<uint32_t*>(&t);
}
__device__ __forceinline__ void ldsm4(uint32_t* r, uint32_t addr) {
    asm volatile("ldmatrix.sync.aligned.m8n8.x4.shared.b16 {%0,%1,%2,%3}, [%4];"
        : "=r"(r[0]), "=r"(r[1]), "=r"(r[2]), "=r"(r[3]) : "r"(addr));
}
__device__ __forceinline__ void mma16816(float* d, const uint32_t* a,
                                         uint32_t b0, uint32_t b1) {
    asm volatile(
        "mma.sync.aligned.m16n8k16.row.col.f32.bf16.bf16.f32 "
        "{%0,%1,%2,%3}, {%4,%5,%6,%7}, {%8,%9}, {%0,%1,%2,%3};"
        : "+f"(d[0]), "+f"(d[1]), "+f"(d[2]), "+f"(d[3])
        : "r"(a[0]), "r"(a[1]), "r"(a[2]), "r"(a[3]), "r"(b0), "r"(b1));
}
__device__ __forceinline__ void cp16(uint32_t sm, const void* g) {
    asm volatile("cp.async.cg.shared.global [%0], [%1], 16;" :: "r"(sm), "l"(g));
}
__device__ __forceinline__ void cp_commit() {
    asm volatile("cp.async.commit_group;" ::: "memory");
}
template <int N>
__device__ __forceinline__ void cp_wait() {
    asm volatile("cp.async.wait_group %0;" :: "n"(N) : "memory");
}

__device__ __forceinline__ float blockSum(float v, float* s) {
    int tid = threadIdx.x;
#pragma unroll
    for (int o = 16; o > 0; o >>= 1) v += __shfl_down_sync(0xffffffffu, v, o);
    if ((tid & 31) == 0) s[tid >> 5] = v;
    __syncthreads();
    float r = (tid < (int)(blockDim.x >> 5)) ? s[tid] : 0.f;
    if (tid < 32) {
#pragma unroll
        for (int o = 4; o > 0; o >>= 1) r += __shfl_down_sync(0xffffffffu, r, o);
    }
    if (tid == 0) s[0] = r;
    __syncthreads();
    r = s[0];
    __syncthreads();
    return r;
}

// ---------------- small kernels ----------------
__global__ void k_pe(const float* __restrict__ pe_w, const float* __restrict__ pe_b) {
    int p = blockIdx.x, c = threadIdx.x;
    int t = p / 192, rem = p % 192, y = rem / 24, x = rem % 24;
    float g0 = t * (1.f / 3.f), g1 = y * (1.f / 7.f), g2 = x * (1.f / 23.f);
    const float* wr = pe_w + c * 6;
    g_pe[p * DD + c] = pe_b[c] + wr[0] * g0 + wr[1] * g1 + wr[2] * g2
        + wr[3] * (1.f - g0) + wr[4] * (1.f - g1) + wr[5] * (1.f - g2);
}

// warp-per-row: gather window + pe + LN -> split bf16
__global__ void __launch_bounds__(256) k_winln(const float* __restrict__ inp,
                                               const float* __restrict__ gam,
                                               const float* __restrict__ bet) {
    int m = (blockIdx.x * 256 + threadIdx.x) >> 5;
    int lane = threadIdx.x & 31;
    int wiB = m / NTOK, p = m % NTOK;
    int wi = wiB / BATCH, bb = wiB % BATCH;
    int t = p / 192, rem = p % 192;
    int f = 2 * wi + t;
    const float* src = inp + ((size_t)(bb * 16 + f) * 192 + rem) * DD;
    const float* pe = g_pe + p * DD;
    float x[8], s = 0.f, sq = 0.f;
#pragma unroll
    for (int i = 0; i < 8; i++) {
        int c = lane + i * 32;
        x[i] = src[c] + pe[c];
        s += x[i];
        sq += x[i] * x[i];
    }
#pragma unroll
    for (int o = 16; o > 0; o >>= 1) {
        s += __shfl_xor_sync(0xffffffffu, s, o);
        sq += __shfl_xor_sync(0xffffffffu, sq, o);
    }
    float mean = s * (1.f / 256.f);
    float var = sq * (1.f / 256.f) - mean * mean;
    float rs = rsqrtf(var + 1e-5f);
#pragma unroll
    for (int i = 0; i < 8; i++) {
        int c = lane + i * 32;
        float y = (x[i] - mean) * rs * gam[c] + bet[c];
        __nv_bfloat16 h = __float2bfloat16(y);
        g_x0h[(size_t)m * DD + c] = h;
        g_x0l[(size_t)m * DD + c] = __float2bfloat16(y - __bfloat162float(h));
    }
}

// warp-per-row LN -> split bf16
__global__ void __launch_bounds__(256) k_ln2(const float* __restrict__ src,
                                             __nv_bfloat16* __restrict__ dsth,
                                             __nv_bfloat16* __restrict__ dstl,
                                             const float* __restrict__ gam,
                                             const float* __restrict__ bet) {
    int m = (blockIdx.x * 256 + threadIdx.x) >> 5;
    int lane = threadIdx.x & 31;
    const float* sp = src + (size_t)m * DD;
    float x[8], s = 0.f, sq = 0.f;
#pragma unroll
    for (int i = 0; i < 8; i++) {
        x[i] = sp[lane + i * 32];
        s += x[i];
        sq += x[i] * x[i];
    }
#pragma unroll
    for (int o = 16; o > 0; o >>= 1) {
        s += __shfl_xor_sync(0xffffffffu, s, o);
        sq += __shfl_xor_sync(0xffffffffu, sq, o);
    }
    float mean = s * (1.f / 256.f);
    float var = sq * (1.f / 256.f) - mean * mean;
    float rs = rsqrtf(var + 1e-5f);
#pragma unroll
    for (int i = 0; i < 8; i++) {
        int c = lane + i * 32;
        float y = (x[i] - mean) * rs * gam[c] + bet[c];
        __nv_bfloat16 h = __float2bfloat16(y);
        dsth[(size_t)m * DD + c] = h;
        dstl[(size_t)m * DD + c] = __float2bfloat16(y - __bfloat162float(h));
    }
}

// split ALL weights in one launch: fp32 -> hi/lo bf16 (+ KV concat + KV bias)
__global__ void k_splitall(const float* __restrict__ w1, const float* __restrict__ w2,
                           const float* __restrict__ wk, const float* __restrict__ wv,
                           const float* __restrict__ wg, const float* __restrict__ wf1,
                           const float* __restrict__ wf2,
                           const float* __restrict__ kb, const float* __restrict__ vb) {
    int idx = blockIdx.x * 256 + threadIdx.x;
    if (idx >= 590336) return;
    if (idx >= 589824) {  // bias kv concat
        int j = idx - 589824;
        g_bkv[j] = (j < 256) ? kb[j] : vb[j - 256];
        return;
    }
    const float* src;
    __nv_bfloat16 *h, *l;
    int j;
    if (idx < 65536)       { j = idx;          src = w1;  h = g_w1h;  l = g_w1l; }
    else if (idx < 131072) { j = idx - 65536;  src = w2;  h = g_w2h;  l = g_w2l; }
    else if (idx < 262144) {
        int jj = idx - 131072;
        j = (jj < 65536) ? jj : jj - 65536;
        src = (jj < 65536) ? wk : wv;
        h = g_wkvh + ((jj < 65536) ? 0 : 65536);
        l = g_wkvl + ((jj < 65536) ? 0 : 65536);
    }
    else if (idx < 458752) { j = idx - 262144; src = wg;  h = g_wgh;  l = g_wgl; }
    else if (idx < 524288) { j = idx - 458752; src = wf1; h = g_wf1h; l = g_wf1l; }
    else                   { j = idx - 524288; src = wf2; h = g_wf2h; l = g_wf2l; }
    float x = src[j];
    __nv_bfloat16 hh = __float2bfloat16(x);
    h[j] = hh;
    l[j] = __float2bfloat16(x - __bfloat162float(hh));
}

// ---------------- 3-stage cp.async split-bf16 mma GEMM ----------------
// C[M,N] = A[M,256] @ W[N,256]^T + bias; A,W pre-split bf16 hi/lo.
// grid: x = n-tile (A-sharing CTAs adjacent), y = m-tile.
// CTA 128x128, BK=32, 8 chunks, 3-stage pipeline, ONE barrier per chunk,
// 2 CTAs/SM. smem row: [hi 64B | lo 64B | pad 16B] = 144B (conflict-free).
#define ROW3 144
#define AMAT 18432   // 128*144 (B matrix offset within stage)
#define STG3 36864
#define MM_SMEM 110592  // 3 stages

template <bool RELU, bool SPLIT, bool MBOUND, bool KV>
__global__ void __launch_bounds__(256, 2) k_mma(
    const __nv_bfloat16* __restrict__ Ah, const __nv_bfloat16* __restrict__ Al,
    const __nv_bfloat16* __restrict__ Wh, const __nv_bfloat16* __restrict__ Wl,
    const float* __restrict__ bias, float* __restrict__ C, float* __restrict__ C2,
    __nv_bfloat16* __restrict__ Ch, __nv_bfloat16* __restrict__ Cl,
    int M, int N) {
    extern __shared__ char sm[];
    int tid = threadIdx.x, lane = tid & 31, wid = tid >> 5;
    int n0 = blockIdx.x * 128, m0 = blockIdx.y * 128;
    int mw = wid & 3, nw = wid >> 2;
    uint32_t sb = smem_u32(sm);

    float acc[2][8][4];
#pragma unroll
    for (int i = 0; i < 2; i++)
#pragma unroll
        for (int j = 0; j < 8; j++)
#pragma unroll
            for (int k = 0; k < 4; k++) acc[i][j][k] = 0.f;

    auto cpStage = [&](int ch, int buf) {
        int k0 = ch * 32;
        uint32_t st = sb + (uint32_t)buf * STG3;
#pragma unroll
        for (int i = 0; i < 8; i++) {
            int idx = tid + i * 256;
            int mat = idx >> 10;      // 0 = A, 1 = B
            int j = idx & 1023;
            int row = j >> 3, part = j & 7;
            uint32_t off = (mat ? AMAT : 0) + (uint32_t)row * ROW3
                         + (part & 3) * 16 + (part >> 2) * 64;
            int kk0 = k0 + (part & 3) * 8;
            if (mat == 0) {
                const __nv_bfloat16* g =
                    ((part < 4) ? Ah : Al) + (size_t)(m0 + row) * 256 + kk0;
                cp16(st + off, g);
            } else {
                const __nv_bfloat16* g =
                    ((part < 4) ? Wh : Wl) + (size_t)(n0 + row) * 256 + kk0;
                cp16(st + off, g);
            }
        }
    };

    cpStage(0, 0); cp_commit();
    cpStage(1, 1); cp_commit();

#pragma unroll
    for (int ch = 0; ch < 8; ch++) {
        if (ch < 7) cp_wait<1>(); else cp_wait<0>();
        __syncthreads();
        if (ch < 6) { cpStage(ch + 2, (ch + 2) % 3); cp_commit(); }
        uint32_t st = sb + (uint32_t)(ch % 3) * STG3;
#pragma unroll
        for (int ks = 0; ks < 2; ks++) {
            int k = ks * 16;
            uint32_t koff = (uint32_t)(k + (lane >> 4) * 8) * 2;
            uint32_t ah[2][4], al[2][4];
#pragma unroll
            for (int mt = 0; mt < 2; mt++) {
                uint32_t addr = st
                    + (uint32_t)(mw * 32 + mt * 16 + (lane & 15)) * ROW3 + koff;
                ldsm4(ah[mt], addr);
                ldsm4(al[mt], addr + 64);
            }
#pragma unroll
            for (int p = 0; p < 4; p++) {
                uint32_t ba = st + AMAT
                    + (uint32_t)(nw * 64 + p * 16 + (lane & 15)) * ROW3 + koff;
                uint32_t bh[4], bl[4];
                ldsm4(bh, ba);
                ldsm4(bl, ba + 64);
                mma16816(acc[0][2 * p],     ah[0], bh[0], bh[2]);
                mma16816(acc[0][2 * p + 1], ah[0], bh[1], bh[3]);
                mma16816(acc[1][2 * p],     ah[1], bh[0], bh[2]);
                mma16816(acc[1][2 * p + 1], ah[1], bh[1], bh[3]);
                mma16816(acc[0][2 * p],     ah[0], bl[0], bl[2]);
                mma16816(acc[0][2 * p + 1], ah[0], bl[1], bl[3]);
                mma16816(acc[1][2 * p],     ah[1], bl[0], bl[2]);
                mma16816(acc[1][2 * p + 1], ah[1], bl[1], bl[3]);
                mma16816(acc[0][2 * p],     al[0], bh[0], bh[2]);
                mma16816(acc[0][2 * p + 1], al[0], bh[1], bh[3]);
                mma16816(acc[1][2 * p],     al[1], bh[0], bh[2]);
                mma16816(acc[1][2 * p + 1], al[1], bh[1], bh[3]);
            }
        }
    }

    // epilogue
#pragma unroll
    for (int nt = 0; nt < 8; nt++) {
        int col = n0 + nw * 64 + nt * 8 + (lane & 3) * 2;
        float bx = bias[col], by = bias[col + 1];
#pragma unroll
        for (int mt = 0; mt < 2; mt++) {
            int row = m0 + mw * 32 + mt * 16 + (lane >> 2);
            float* a = acc[mt][nt];
            float2 o0 = make_float2(a[0] + bx, a[1] + by);
            float2 o1 = make_float2(a[2] + bx, a[3] + by);
            if (RELU) {
                o0.x = fmaxf(o0.x, 0.f); o0.y = fmaxf(o0.y, 0.f);
                o1.x = fmaxf(o1.x, 0.f); o1.y = fmaxf(o1.y, 0.f);
            }
            bool w0 = !MBOUND || row < M;
            bool w1 = !MBOUND || row + 8 < M;
            if (SPLIT) {
                __nv_bfloat162 h0 = __floats2bfloat162_rn(o0.x, o0.y);
                __nv_bfloat162 h1 = __floats2bfloat162_rn(o1.x, o1.y);
                uint32_t L0 = bfpack(o0.x - __bfloat162float(h0.x),
                                     o0.y - __bfloat162float(h0.y));
                uint32_t L1 = bfpack(o1.x - __bfloat162float(h1.x),
                                     o1.y - __bfloat162float(h1.y));
                if (w0) {
                    *reinterpret_cast<uint32_t*>(Ch + (size_t)row * N + col) =
                        *reinterpret_cast<uint32_t*>(&h0);
                    *reinterpret_cast<uint32_t*>(Cl + (size_t)row * N + col) = L0;
                }
                if (w1) {
                    *reinterpret_cast<uint32_t*>(Ch + (size_t)(row + 8) * N + col) =
                        *reinterpret_cast<uint32_t*>(&h1);
                    *reinterpret_cast<uint32_t*>(Cl + (size_t)(row + 8) * N + col) = L1;
                }
            } else if (KV) {
                float* dst = (col < 256) ? C : C2;
                int cc = col & 255;
                if (w0) *reinterpret_cast<float2*>(dst + (size_t)row * 256 + cc) = o0;
                if (w1) *reinterpret_cast<float2*>(dst + (size_t)(row + 8) * 256 + cc) = o1;
            } else {
                if (w0) *reinterpret_cast<float2*>(C + (size_t)row * N + col) = o0;
                if (w1) *reinterpret_cast<float2*>(C + (size_t)(row + 8) * N + col) = o1;
            }
        }
    }
}

// q = LN_ns(slots)@q_w^T + q_b ; hg = slots@gru_wh^T + gru_bh (22 rows)
__global__ void k_small(const float* __restrict__ slots,
                        const float* __restrict__ nsg, const float* __restrict__ nsb,
                        const float* __restrict__ qw, const float* __restrict__ qb,
                        const float* __restrict__ wh, const float* __restrict__ bh) {
    __shared__ float red[32];
    __shared__ float sraw[DD];
    __shared__ float sln[DD];
    int i = blockIdx.x, c = threadIdx.x;
    float x = slots[i * DD + c];
    sraw[c] = x;
    float mean = blockSum(x, red) * (1.f / 256.f);
    float d0 = x - mean;
    float var = blockSum(d0 * d0, red) * (1.f / 256.f);
    sln[c] = d0 * rsqrtf(var + 1e-5f) * nsg[c] + nsb[c];
    __syncthreads();
    float acc = qb[c];
    const float* wr = qw + (size_t)c * 256;
#pragma unroll 8
    for (int k = 0; k < 256; k++) acc += sln[k] * wr[k];
    g_qs[i * DD + c] = acc;
#pragma unroll
    for (int j = 0; j < 3; j++) {
        int u = j * 256 + c;
        float a = bh[u];
        const float* hr = wh + (size_t)u * 256;
#pragma unroll 8
        for (int k = 0; k < 256; k++) a += sraw[k] * hr[k];
        g_hg[i * 768 + u] = a;
    }
}

__device__ __forceinline__ void softmax_store(const unsigned long long* d,
                                              float* __restrict__ dst, int j) {
    float v[SS];
#pragma unroll
    for (int ip = 0; ip < 11; ip++) {
        float a, b;
        upk(d[ip], a, b);
        v[2 * ip] = a * 0.0625f;
        v[2 * ip + 1] = b * 0.0625f;
    }
    float mx = v[0];
#pragma unroll
    for (int i = 1; i < SS; i++) mx = fmaxf(mx, v[i]);
    float s = 0.f;
#pragma unroll
    for (int i = 0; i < SS; i++) { v[i] = __expf(v[i] - mx); s += v[i]; }
    float inv = 1.f / s;
#pragma unroll
    for (int i = 0; i < SS; i++) dst[i * NTOK + j] = v[i] * inv + 1e-8f;
}

// dots + softmax-over-slots + EPS; grid (BWIN, 4), 192 tokens per block
__global__ void __launch_bounds__(192) k_attn(float* __restrict__ out_attn,
                                              const float* __restrict__ kk) {
    __shared__ unsigned long long q2[11 * 256];
    __shared__ float ks[8][192];
    int bB = blockIdx.x, qa = blockIdx.y, tid = threadIdx.x;
    for (int idx = tid; idx < 11 * 256; idx += 192) {
        int ip = idx >> 8, k = idx & 255;
        q2[idx] = pk(g_qs[(2 * ip) * DD + k], g_qs[(2 * ip + 1) * DD + k]);
    }
    unsigned long long d[11];
#pragma unroll
    for (int ip = 0; ip < 11; ip++) d[ip] = 0ULL;
    size_t rowbase = (size_t)bB * NTOK + qa * 192;
    for (int kc = 0; kc < 256; kc += 8) {
        __syncthreads();
        const float4* src = (const float4*)(kk + (rowbase + tid) * 256 + kc);
        float4 v0 = src[0], v1 = src[1];
        ks[0][tid] = v0.x; ks[1][tid] = v0.y; ks[2][tid] = v0.z; ks[3][tid] = v0.w;
        ks[4][tid] = v1.x; ks[5][tid] = v1.y; ks[6][tid] = v1.z; ks[7][tid] = v1.w;
        __syncthreads();
#pragma unroll
        for (int kl = 0; kl < 8; kl++) {
            float kv = ks[kl][tid];
            unsigned long long sv = pk(kv, kv);
#pragma unroll
            for (int ip = 0; ip < 11; ip++)
                d[ip] = fma2(q2[ip * 256 + kc + kl], sv, d[ip]);
        }
    }
    int wi = bB / BATCH, bb = bB % BATCH;
    float* dst = out_attn + ((size_t)(bb * NWIN + wi)) * SS * NTOK;
    softmax_store(d, dst, qa * 192 + tid);
}

// renorm + weighted update -> split bf16; grid (BWIN, 2), 128 channels per block
__global__ void __launch_bounds__(128) k_upd(const float* __restrict__ attn,
                                             const float* __restrict__ vv) {
    __shared__ float red[32];
    __shared__ float sinv[SS];
    __shared__ unsigned long long at2[11 * 64];
    int bB = blockIdx.x, half = blockIdx.y, tid = threadIdx.x;
    int wi = bB / BATCH, bb = bB % BATCH;
    const float* ab = attn + ((size_t)(bb * NWIN + wi)) * SS * NTOK;
    for (int i = 0; i < SS; i++) {
        float p = 0.f;
        for (int j = tid; j < NTOK; j += 128) p += ab[i * NTOK + j];
        float s = blockSum(p, red);
        if (tid == 0) sinv[i] = 1.f / s;
    }
    __syncthreads();
    unsigned long long acc[11];
#pragma unroll
    for (int ip = 0; ip < 11; ip++) acc[ip] = 0ULL;
    int ch = half * 128 + tid;
    for (int j0 = 0; j0 < NTOK; j0 += 64) {
        for (int idx = tid; idx < 11 * 64; idx += 128) {
            int ip = idx >> 6, jj = idx & 63;
            at2[idx] = pk(ab[(2 * ip) * NTOK + j0 + jj],
                          ab[(2 * ip + 1) * NTOK + j0 + jj]);
        }
        __syncthreads();
        const float* vp = vv + ((size_t)bB * NTOK + j0) * 256 + ch;
#pragma unroll 4
        for (int jj = 0; jj < 64; jj++) {
            float v = vp[(size_t)jj * 256];
            unsigned long long sv = pk(v, v);
#pragma unroll
            for (int ip = 0; ip < 11; ip++)
                acc[ip] = fma2(at2[ip * 64 + jj], sv, acc[ip]);
        }
        __syncthreads();
    }
#pragma unroll
    for (int ip = 0; ip < 11; ip++) {
        float u0, u1;
        upk(acc[ip], u0, u1);
        u0 *= sinv[2 * ip];
        u1 *= sinv[2 * ip + 1];
        __nv_bfloat16 h0 = __float2bfloat16(u0);
        __nv_bfloat16 h1 = __float2bfloat16(u1);
        size_t r0 = ((size_t)bB * SS + 2 * ip) * DD + ch;
        size_t r1 = ((size_t)bB * SS + 2 * ip + 1) * DD + ch;
        g_updh[r0] = h0; g_updl[r0] = __float2bfloat16(u0 - __bfloat162float(h0));
        g_updh[r1] = h1; g_updl[r1] = __float2bfloat16(u1 - __bfloat162float(h1));
    }
}

__global__ void k_gate(const float* __restrict__ slots) {
    int m = blockIdx.x, c = threadIdx.x;
    int Bi = m / NAC, i = m % NAC;
    size_t row = (size_t)Bi * SS + i;
    float ir = g_xg[row * 768 + c];
    float iz = g_xg[row * 768 + 256 + c];
    float in_ = g_xg[row * 768 + 512 + c];
    float hr = g_hg[i * 768 + c];
    float hz = g_hg[i * 768 + 256 + c];
    float hn = g_hg[i * 768 + 512 + c];
    float h = slots[i * DD + c];
    float r = 1.f / (1.f + __expf(-(ir + hr)));
    float z = 1.f / (1.f + __expf(-(iz + hz)));
    float n = tanhf(in_ + r * hn);
    g_so[(size_t)m * DD + c] = (1.f - z) * n + z * h;
}

__global__ void k_final(float* __restrict__ out) {
    int m = blockIdx.x, c = threadIdx.x;
    int Bi = m / NAC, sl = m % NAC;
    int wi = Bi / BATCH, bb = Bi % BATCH;
    out[(((size_t)bb * NWIN + wi) * NAC + sl) * DD + c] =
        g_so[(size_t)m * DD + c] + g_t3[(size_t)m * DD + c];
}

extern "C" void kernel_launch(void* const* d_in, const int* in_sizes, int n_in,
                              void* d_out, int out_size) {
    const float* inputs = (const float*)d_in[0];
    const float* slots  = (const float*)d_in[1];
    const float* pe_w   = (const float*)d_in[2];
    const float* pe_b   = (const float*)d_in[3];
    const float* LN_g   = (const float*)d_in[4];
    const float* LN_b   = (const float*)d_in[5];
    const float* ni_g   = (const float*)d_in[6];
    const float* ni_b   = (const float*)d_in[7];
    const float* ns_g   = (const float*)d_in[8];
    const float* ns_b   = (const float*)d_in[9];
    const float* npf_g  = (const float*)d_in[10];
    const float* npf_b  = (const float*)d_in[11];
    const float* FC1_w  = (const float*)d_in[12];
    const float* FC1_b  = (const float*)d_in[13];
    const float* FC2_w  = (const float*)d_in[14];
    const float* FC2_b  = (const float*)d_in[15];
    const float* q_w    = (const float*)d_in[16];
    const float* q_b    = (const float*)d_in[17];
    const float* k_w    = (const float*)d_in[18];
    const float* k_b    = (const float*)d_in[19];
    const float* v_w    = (const float*)d_in[20];
    const float* v_b    = (const float*)d_in[21];
    const float* ff1_w  = (const float*)d_in[22];
    const float* ff1_b  = (const float*)d_in[23];
    const float* ff2_w  = (const float*)d_in[24];
    const float* ff2_b  = (const float*)d_in[25];
    const float* gru_wi = (const float*)d_in[26];
    const float* gru_wh = (const float*)d_in[27];
    const float* gru_bi = (const float*)d_in[28];
    const float* gru_bh = (const float*)d_in[29];

    float* out = (float*)d_out;
    float* out_attn = out + SLOTS_OUT_ELEMS;

    float *b0, *b1, *b2, *xg_, *so_, *t3_, *bkv;
    cudaGetSymbolAddress((void**)&b0, g_buf0);
    cudaGetSymbolAddress((void**)&b1, g_buf1);
    cudaGetSymbolAddress((void**)&b2, g_buf2);
    cudaGetSymbolAddress((void**)&xg_, g_xg);
    cudaGetSymbolAddress((void**)&so_, g_so);
    cudaGetSymbolAddress((void**)&t3_, g_t3);
    cudaGetSymbolAddress((void**)&bkv, g_bkv);

    __nv_bfloat16 *w1h, *w1l, *w2h, *w2l, *wkvh, *wkvl;
    __nv_bfloat16 *wgh, *wgl, *wf1h, *wf1l, *wf2h, *wf2l;
    __nv_bfloat16 *x0h, *x0l, *x1h, *x1l, *x2h, *x2l;
    __nv_bfloat16 *uh, *ul, *snh, *snl, *t2h, *t2l;
    cudaGetSymbolAddress((void**)&w1h, g_w1h); cudaGetSymbolAddress((void**)&w1l, g_w1l);
    cudaGetSymbolAddress((void**)&w2h, g_w2h); cudaGetSymbolAddress((void**)&w2l, g_w2l);
    cudaGetSymbolAddress((void**)&wkvh, g_wkvh); cudaGetSymbolAddress((void**)&wkvl, g_wkvl);
    cudaGetSymbolAddress((void**)&wgh, g_wgh); cudaGetSymbolAddress((void**)&wgl, g_wgl);
    cudaGetSymbolAddress((void**)&wf1h, g_wf1h); cudaGetSymbolAddress((void**)&wf1l, g_wf1l);
    cudaGetSymbolAddress((void**)&wf2h, g_wf2h); cudaGetSymbolAddress((void**)&wf2l, g_wf2l);
    cudaGetSymbolAddress((void**)&x0h, g_x0h); cudaGetSymbolAddress((void**)&x0l, g_x0l);
    cudaGetSymbolAddress((void**)&x1h, g_x1h); cudaGetSymbolAddress((void**)&x1l, g_x1l);
    cudaGetSymbolAddress((void**)&x2h, g_x2h); cudaGetSymbolAddress((void**)&x2l, g_x2l);
    cudaGetSymbolAddress((void**)&uh, g_updh); cudaGetSymbolAddress((void**)&ul, g_updl);
    cudaGetSymbolAddress((void**)&snh, g_solnh); cudaGetSymbolAddress((void**)&snl, g_solnl);
    cudaGetSymbolAddress((void**)&t2h, g_t2h); cudaGetSymbolAddress((void**)&t2l, g_t2l);

    cudaFuncSetAttribute((const void*)k_mma<true, true, false, false>,
                         cudaFuncAttributeMaxDynamicSharedMemorySize, MM_SMEM);
    cudaFuncSetAttribute((const void*)k_mma<false, false, false, false>,
                         cudaFuncAttributeMaxDynamicSharedMemorySize, MM_SMEM);
    cudaFuncSetAttribute((const void*)k_mma<false, false, false, true>,
                         cudaFuncAttributeMaxDynamicSharedMemorySize, MM_SMEM);
    cudaFuncSetAttribute((const void*)k_mma<false, false, true, false>,
                         cudaFuncAttributeMaxDynamicSharedMemorySize, MM_SMEM);

    // split all weights + KV concat + KV bias (one launch)
    k_splitall<<<2306, 256>>>(FC1_w, FC2_w, k_w, v_w, gru_wi, ff1_w, ff2_w, k_b, v_b);

    // positional embedding + gather + LN (split bf16 out)
    k_pe<<<NTOK, 256>>>(pe_w, pe_b);
    k_winln<<<MBIG / 8, 256>>>(inputs, LN_g, LN_b);

    // FC1 (relu, split out) -> FC2 (fp32 out)
    k_mma<true, true, false, false><<<dim3(2, MBIG / 128), 256, MM_SMEM>>>(
        x0h, x0l, w1h, w1l, FC1_b, nullptr, nullptr, x1h, x1l, MBIG, 256);
    k_mma<false, false, false, false><<<dim3(2, MBIG / 128), 256, MM_SMEM>>>(
        x1h, x1l, w2h, w2l, FC2_b, b0, nullptr, nullptr, nullptr, MBIG, 256);

    // norm_input (split out), fused K+V projection (fp32 out x2)
    k_ln2<<<MBIG / 8, 256>>>(b0, x2h, x2l, ni_g, ni_b);
    k_mma<false, false, false, true><<<dim3(4, MBIG / 128), 256, MM_SMEM>>>(
        x2h, x2l, wkvh, wkvl, bkv, b1, b2, nullptr, nullptr, MBIG, 256);

    // batch-invariant q and hidden gates
    k_small<<<SS, 256>>>(slots, ns_g, ns_b, q_w, q_b, gru_wh, gru_bh);

    // dots + softmax-over-slots + EPS (writes attns output directly)
    dim3 gAttn(BWIN, 4);
    k_attn<<<gAttn, 192>>>(out_attn, b1);

    // renorm + weighted update (split bf16 out)
    dim3 gUpd(BWIN, 2);
    k_upd<<<gUpd, 128>>>(out_attn, b2);

    // GRU input gates GEMM on tensor cores: (4928x256)@(768x256)^T
    k_mma<false, false, true, false><<<dim3(6, MGRUPAD / 128), 256, MM_SMEM>>>(
        uh, ul, wgh, wgl, gru_bi, xg_, nullptr, nullptr, nullptr, MGRU, 768);

    // gates -> slots (first 20)
    k_gate<<<MSO, 256>>>(slots);

    // residual MLP on tensor cores
    k_ln2<<<MSO / 8, 256>>>(so_, snh, snl, npf_g, npf_b);
    k_mma<true, true, false, false><<<dim3(2, MSO / 128), 256, MM_SMEM>>>(
        snh, snl, wf1h, wf1l, ff1_b, nullptr, nullptr, t2h, t2l, MSO, 256);
    k_mma<false, false, false, false><<<dim3(2, MSO / 128), 256, MM_SMEM>>>(
        t2h, t2l, wf2h, wf2l, ff2_b, t3_, nullptr, nullptr, nullptr, MSO, 256);

    // residual + permute into slots output
    k_final<<<MSO, 256>>>(out);
}

// round 9
// speedup vs baseline: 1.3329x; 1.0007x over previous
#include <cuda_runtime.h>
#include <cuda_bf16.h>
#include <math.h>
#include <stdint.h>

#define DD 256
#define SS 22
#define NAC 20
#define NTOK 768
#define NWIN 7
#define BATCH 32
#define BWIN 224
#define MBIG 172032
#define MGRU 4928
#define MGRUPAD 4992   // 39*128
#define MSO  4480
#define SLOTS_OUT_ELEMS 1146880  // 32*7*20*256

__device__ float g_pe[NTOK * DD];
__device__ float g_buf0[MBIG * DD];   // FC2 out (fp32, feeds LN)
__device__ float g_buf1[MBIG * DD];   // kk
__device__ float g_buf2[MBIG * DD];   // vv
__device__ __nv_bfloat16 g_x0h[MBIG * DD], g_x0l[MBIG * DD];  // winln out
__device__ __nv_bfloat16 g_x1h[MBIG * DD], g_x1l[MBIG * DD];  // FC1 out
__device__ __nv_bfloat16 g_x2h[MBIG * DD], g_x2l[MBIG * DD];  // ni-LN out
__device__ float g_qs[SS * DD];
__device__ float g_hg[SS * 768];
__device__ __nv_bfloat16 g_updh[MGRUPAD * DD], g_updl[MGRUPAD * DD];
__device__ float g_xg[MGRU * 768];
__device__ float g_so[MSO * DD];
__device__ __nv_bfloat16 g_solnh[MSO * DD], g_solnl[MSO * DD];
__device__ __nv_bfloat16 g_t2h[MSO * DD], g_t2l[MSO * DD];
__device__ float g_t3[MSO * DD];
// pre-split weights (hi/lo bf16)
__device__ __nv_bfloat16 g_w1h[65536], g_w1l[65536];
__device__ __nv_bfloat16 g_w2h[65536], g_w2l[65536];
__device__ __nv_bfloat16 g_wkvh[131072], g_wkvl[131072];   // K||V concat
__device__ float g_bkv[512];
__device__ __nv_bfloat16 g_wgh[196608], g_wgl[196608];
__device__ __nv_bfloat16 g_wf1h[65536], g_wf1l[65536];
__device__ __nv_bfloat16 g_wf2h[65536], g_wf2l[65536];

// ---------------- helpers ----------------
__device__ __forceinline__ uint32_t smem_u32(const void* p) {
    uint32_t a;
    asm("{ .reg .u64 t; cvta.to.shared.u64 t, %1; cvt.u32.u64 %0, t; }" : "=r"(a) : "l"(p));
    return a;
}
__device__ __forceinline__ unsigned long long pk(float x, float y) {
    unsigned long long r;
    asm("mov.b64 %0, {%1,%2};" : "=l"(r) : "f"(x), "f"(y));
    return r;
}
__device__ __forceinline__ void upk(unsigned long long v, float& x, float& y) {
    asm("mov.b64 {%0,%1}, %2;" : "=f"(x), "=f"(y) : "l"(v));
}
__device__ __forceinline__ unsigned long long fma2(unsigned long long a,
                                                   unsigned long long b,
                                                   unsigned long long c) {
    unsigned long long d;
    asm("fma.rn.f32x2 %0, %1, %2, %3;" : "=l"(d) : "l"(a), "l"(b), "l"(c));
    return d;
}
__device__ __forceinline__ uint32_t bfpack(float a, float b) {
    __nv_bfloat162 t = __floats2bfloat162_rn(a, b);
    return *reinterpret_cast<uint32_t*>(&t);
}
// ldsm stays volatile: pinned between barriers (reads smem not visible to compiler)
__device__ __forceinline__ void ldsm4(uint32_t* r, uint32_t addr) {
    asm volatile("ldmatrix.sync.aligned.m8n8.x4.shared.b16 {%0,%1,%2,%3}, [%4];"
        : "=r"(r[0]), "=r"(r[1]), "=r"(r[2]), "=r"(r[3]) : "r"(addr));
}
// mma is NON-volatile: pure register op; ptxas may schedule it freely past later
// ldsm (data deps keep it after its own operands) -> hides LDS latency.
__device__ __forceinline__ void mma16816(float* d, const uint32_t* a,
                                         uint32_t b0, uint32_t b1) {
    asm("mma.sync.aligned.m16n8k16.row.col.f32.bf16.bf16.f32 "
        "{%0,%1,%2,%3}, {%4,%5,%6,%7}, {%8,%9}, {%0,%1,%2,%3};"
        : "+f"(d[0]), "+f"(d[1]), "+f"(d[2]), "+f"(d[3])
        : "r"(a[0]), "r"(a[1]), "r"(a[2]), "r"(a[3]), "r"(b0), "r"(b1));
}
__device__ __forceinline__ void cp16(uint32_t sm, const void* g) {
    asm volatile("cp.async.cg.shared.global [%0], [%1], 16;" :: "r"(sm), "l"(g));
}
__device__ __forceinline__ void cp_commit() {
    asm volatile("cp.async.commit_group;" ::: "memory");
}
template <int N>
__device__ __forceinline__ void cp_wait() {
    asm volatile("cp.async.wait_group %0;" :: "n"(N) : "memory");
}

__device__ __forceinline__ float blockSum(float v, float* s) {
    int tid = threadIdx.x;
#pragma unroll
    for (int o = 16; o > 0; o >>= 1) v += __shfl_down_sync(0xffffffffu, v, o);
    if ((tid & 31) == 0) s[tid >> 5] = v;
    __syncthreads();
    float r = (tid < (int)(blockDim.x >> 5)) ? s[tid] : 0.f;
    if (tid < 32) {
#pragma unroll
        for (int o = 4; o > 0; o >>= 1) r += __shfl_down_sync(0xffffffffu, r, o);
    }
    if (tid == 0) s[0] = r;
    __syncthreads();
    r = s[0];
    __syncthreads();
    return r;
}

// ---------------- small kernels ----------------
__global__ void k_pe(const float* __restrict__ pe_w, const float* __restrict__ pe_b) {
    int p = blockIdx.x, c = threadIdx.x;
    int t = p / 192, rem = p % 192, y = rem / 24, x = rem % 24;
    float g0 = t * (1.f / 3.f), g1 = y * (1.f / 7.f), g2 = x * (1.f / 23.f);
    const float* wr = pe_w + c * 6;
    g_pe[p * DD + c] = pe_b[c] + wr[0] * g0 + wr[1] * g1 + wr[2] * g2
        + wr[3] * (1.f - g0) + wr[4] * (1.f - g1) + wr[5] * (1.f - g2);
}

// warp-per-row: gather window + pe + LN -> split bf16
__global__ void __launch_bounds__(256) k_winln(const float* __restrict__ inp,
                                               const float* __restrict__ gam,
                                               const float* __restrict__ bet) {
    int m = (blockIdx.x * 256 + threadIdx.x) >> 5;
    int lane = threadIdx.x & 31;
    int wiB = m / NTOK, p = m % NTOK;
    int wi = wiB / BATCH, bb = wiB % BATCH;
    int t = p / 192, rem = p % 192;
    int f = 2 * wi + t;
    const float* src = inp + ((size_t)(bb * 16 + f) * 192 + rem) * DD;
    const float* pe = g_pe + p * DD;
    float x[8], s = 0.f, sq = 0.f;
#pragma unroll
    for (int i = 0; i < 8; i++) {
        int c = lane + i * 32;
        x[i] = src[c] + pe[c];
        s += x[i];
        sq += x[i] * x[i];
    }
#pragma unroll
    for (int o = 16; o > 0; o >>= 1) {
        s += __shfl_xor_sync(0xffffffffu, s, o);
        sq += __shfl_xor_sync(0xffffffffu, sq, o);
    }
    float mean = s * (1.f / 256.f);
    float var = sq * (1.f / 256.f) - mean * mean;
    float rs = rsqrtf(var + 1e-5f);
#pragma unroll
    for (int i = 0; i < 8; i++) {
        int c = lane + i * 32;
        float y = (x[i] - mean) * rs * gam[c] + bet[c];
        __nv_bfloat16 h = __float2bfloat16(y);
        g_x0h[(size_t)m * DD + c] = h;
        g_x0l[(size_t)m * DD + c] = __float2bfloat16(y - __bfloat162float(h));
    }
}

// warp-per-row LN -> split bf16
__global__ void __launch_bounds__(256) k_ln2(const float* __restrict__ src,
                                             __nv_bfloat16* __restrict__ dsth,
                                             __nv_bfloat16* __restrict__ dstl,
                                             const float* __restrict__ gam,
                                             const float* __restrict__ bet) {
    int m = (blockIdx.x * 256 + threadIdx.x) >> 5;
    int lane = threadIdx.x & 31;
    const float* sp = src + (size_t)m * DD;
    float x[8], s = 0.f, sq = 0.f;
#pragma unroll
    for (int i = 0; i < 8; i++) {
        x[i] = sp[lane + i * 32];
        s += x[i];
        sq += x[i] * x[i];
    }
#pragma unroll
    for (int o = 16; o > 0; o >>= 1) {
        s += __shfl_xor_sync(0xffffffffu, s, o);
        sq += __shfl_xor_sync(0xffffffffu, sq, o);
    }
    float mean = s * (1.f / 256.f);
    float var = sq * (1.f / 256.f) - mean * mean;
    float rs = rsqrtf(var + 1e-5f);
#pragma unroll
    for (int i = 0; i < 8; i++) {
        int c = lane + i * 32;
        float y = (x[i] - mean) * rs * gam[c] + bet[c];
        __nv_bfloat16 h = __float2bfloat16(y);
        dsth[(size_t)m * DD + c] = h;
        dstl[(size_t)m * DD + c] = __float2bfloat16(y - __bfloat162float(h));
    }
}

// split ALL weights in one launch: fp32 -> hi/lo bf16 (+ KV concat + KV bias)
__global__ void k_splitall(const float* __restrict__ w1, const float* __restrict__ w2,
                           const float* __restrict__ wk, const float* __restrict__ wv,
                           const float* __restrict__ wg, const float* __restrict__ wf1,
                           const float* __restrict__ wf2,
                           const float* __restrict__ kb, const float* __restrict__ vb) {
    int idx = blockIdx.x * 256 + threadIdx.x;
    if (idx >= 590336) return;
    if (idx >= 589824) {  // bias kv concat
        int j = idx - 589824;
        g_bkv[j] = (j < 256) ? kb[j] : vb[j - 256];
        return;
    }
    const float* src;
    __nv_bfloat16 *h, *l;
    int j;
    if (idx < 65536)       { j = idx;          src = w1;  h = g_w1h;  l = g_w1l; }
    else if (idx < 131072) { j = idx - 65536;  src = w2;  h = g_w2h;  l = g_w2l; }
    else if (idx < 262144) {
        int jj = idx - 131072;
        j = (jj < 65536) ? jj : jj - 65536;
        src = (jj < 65536) ? wk : wv;
        h = g_wkvh + ((jj < 65536) ? 0 : 65536);
        l = g_wkvl + ((jj < 65536) ? 0 : 65536);
    }
    else if (idx < 458752) { j = idx - 262144; src = wg;  h = g_wgh;  l = g_wgl; }
    else if (idx < 524288) { j = idx - 458752; src = wf1; h = g_wf1h; l = g_wf1l; }
    else                   { j = idx - 524288; src = wf2; h = g_wf2h; l = g_wf2l; }
    float x = src[j];
    __nv_bfloat16 hh = __float2bfloat16(x);
    h[j] = hh;
    l[j] = __float2bfloat16(x - __bfloat162float(hh));
}

// ---------------- 3-stage cp.async split-bf16 mma GEMM ----------------
// C[M,N] = A[M,256] @ W[N,256]^T + bias; A,W pre-split bf16 hi/lo.
// grid: x = n-tile (A-sharing CTAs adjacent), y = m-tile.
// CTA 128x128, BK=32, 8 chunks, 3-stage pipeline, ONE barrier per chunk,
// 2 CTAs/SM. mma asm is non-volatile so ptxas software-pipelines vs ldsm.
#define ROW3 144
#define AMAT 18432   // 128*144 (B matrix offset within stage)
#define STG3 36864
#define MM_SMEM 110592  // 3 stages

template <bool RELU, bool SPLIT, bool MBOUND, bool KV>
__global__ void __launch_bounds__(256, 2) k_mma(
    const __nv_bfloat16* __restrict__ Ah, const __nv_bfloat16* __restrict__ Al,
    const __nv_bfloat16* __restrict__ Wh, const __nv_bfloat16* __restrict__ Wl,
    const float* __restrict__ bias, float* __restrict__ C, float* __restrict__ C2,
    __nv_bfloat16* __restrict__ Ch, __nv_bfloat16* __restrict__ Cl,
    int M, int N) {
    extern __shared__ char sm[];
    int tid = threadIdx.x, lane = tid & 31, wid = tid >> 5;
    int n0 = blockIdx.x * 128, m0 = blockIdx.y * 128;
    int mw = wid & 3, nw = wid >> 2;
    uint32_t sb = smem_u32(sm);

    float acc[2][8][4];
#pragma unroll
    for (int i = 0; i < 2; i++)
#pragma unroll
        for (int j = 0; j < 8; j++)
#pragma unroll
            for (int k = 0; k < 4; k++) acc[i][j][k] = 0.f;

    auto cpStage = [&](int ch, int buf) {
        int k0 = ch * 32;
        uint32_t st = sb + (uint32_t)buf * STG3;
#pragma unroll
        for (int i = 0; i < 8; i++) {
            int idx = tid + i * 256;
            int mat = idx >> 10;      // 0 = A, 1 = B
            int j = idx & 1023;
            int row = j >> 3, part = j & 7;
            uint32_t off = (mat ? AMAT : 0) + (uint32_t)row * ROW3
                         + (part & 3) * 16 + (part >> 2) * 64;
            int kk0 = k0 + (part & 3) * 8;
            if (mat == 0) {
                const __nv_bfloat16* g =
                    ((part < 4) ? Ah : Al) + (size_t)(m0 + row) * 256 + kk0;
                cp16(st + off, g);
            } else {
                const __nv_bfloat16* g =
                    ((part < 4) ? Wh : Wl) + (size_t)(n0 + row) * 256 + kk0;
                cp16(st + off, g);
            }
        }
    };

    cpStage(0, 0); cp_commit();
    cpStage(1, 1); cp_commit();

#pragma unroll
    for (int ch = 0; ch < 8; ch++) {
        if (ch < 7) cp_wait<1>(); else cp_wait<0>();
        __syncthreads();
        if (ch < 6) { cpStage(ch + 2, (ch + 2) % 3); cp_commit(); }
        uint32_t st = sb + (uint32_t)(ch % 3) * STG3;
#pragma unroll
        for (int ks = 0; ks < 2; ks++) {
            int k = ks * 16;
            uint32_t koff = (uint32_t)(k + (lane >> 4) * 8) * 2;
            uint32_t ah[2][4], al[2][4];
#pragma unroll
            for (int mt = 0; mt < 2; mt++) {
                uint32_t addr = st
                    + (uint32_t)(mw * 32 + mt * 16 + (lane & 15)) * ROW3 + koff;
                ldsm4(ah[mt], addr);
                ldsm4(al[mt], addr + 64);
            }
#pragma unroll
            for (int p = 0; p < 4; p++) {
                uint32_t ba = st + AMAT
                    + (uint32_t)(nw * 64 + p * 16 + (lane & 15)) * ROW3 + koff;
                uint32_t bh[4], bl[4];
                ldsm4(bh, ba);
                ldsm4(bl, ba + 64);
                mma16816(acc[0][2 * p],     ah[0], bh[0], bh[2]);
                mma16816(acc[0][2 * p + 1], ah[0], bh[1], bh[3]);
                mma16816(acc[1][2 * p],     ah[1], bh[0], bh[2]);
                mma16816(acc[1][2 * p + 1], ah[1], bh[1], bh[3]);
                mma16816(acc[0][2 * p],     ah[0], bl[0], bl[2]);
                mma16816(acc[0][2 * p + 1], ah[0], bl[1], bl[3]);
                mma16816(acc[1][2 * p],     ah[1], bl[0], bl[2]);
                mma16816(acc[1][2 * p + 1], ah[1], bl[1], bl[3]);
                mma16816(acc[0][2 * p],     al[0], bh[0], bh[2]);
                mma16816(acc[0][2 * p + 1], al[0], bh[1], bh[3]);
                mma16816(acc[1][2 * p],     al[1], bh[0], bh[2]);
                mma16816(acc[1][2 * p + 1], al[1], bh[1], bh[3]);
            }
        }
    }

    // epilogue
#pragma unroll
    for (int nt = 0; nt < 8; nt++) {
        int col = n0 + nw * 64 + nt * 8 + (lane & 3) * 2;
        float bx = bias[col], by = bias[col + 1];
#pragma unroll
        for (int mt = 0; mt < 2; mt++) {
            int row = m0 + mw * 32 + mt * 16 + (lane >> 2);
            float* a = acc[mt][nt];
            float2 o0 = make_float2(a[0] + bx, a[1] + by);
            float2 o1 = make_float2(a[2] + bx, a[3] + by);
            if (RELU) {
                o0.x = fmaxf(o0.x, 0.f); o0.y = fmaxf(o0.y, 0.f);
                o1.x = fmaxf(o1.x, 0.f); o1.y = fmaxf(o1.y, 0.f);
            }
            bool w0 = !MBOUND || row < M;
            bool w1 = !MBOUND || row + 8 < M;
            if (SPLIT) {
                __nv_bfloat162 h0 = __floats2bfloat162_rn(o0.x, o0.y);
                __nv_bfloat162 h1 = __floats2bfloat162_rn(o1.x, o1.y);
                uint32_t L0 = bfpack(o0.x - __bfloat162float(h0.x),
                                     o0.y - __bfloat162float(h0.y));
                uint32_t L1 = bfpack(o1.x - __bfloat162float(h1.x),
                                     o1.y - __bfloat162float(h1.y));
                if (w0) {
                    *reinterpret_cast<uint32_t*>(Ch + (size_t)row * N + col) =
                        *reinterpret_cast<uint32_t*>(&h0);
                    *reinterpret_cast<uint32_t*>(Cl + (size_t)row * N + col) = L0;
                }
                if (w1) {
                    *reinterpret_cast<uint32_t*>(Ch + (size_t)(row + 8) * N + col) =
                        *reinterpret_cast<uint32_t*>(&h1);
                    *reinterpret_cast<uint32_t*>(Cl + (size_t)(row + 8) * N + col) = L1;
                }
            } else if (KV) {
                float* dst = (col < 256) ? C : C2;
                int cc = col & 255;
                if (w0) *reinterpret_cast<float2*>(dst + (size_t)row * 256 + cc) = o0;
                if (w1) *reinterpret_cast<float2*>(dst + (size_t)(row + 8) * 256 + cc) = o1;
            } else {
                if (w0) *reinterpret_cast<float2*>(C + (size_t)row * N + col) = o0;
                if (w1) *reinterpret_cast<float2*>(C + (size_t)(row + 8) * N + col) = o1;
            }
        }
    }
}

// q = LN_ns(slots)@q_w^T + q_b ; hg = slots@gru_wh^T + gru_bh (22 rows)
__global__ void k_small(const float* __restrict__ slots,
                        const float* __restrict__ nsg, const float* __restrict__ nsb,
                        const float* __restrict__ qw, const float* __restrict__ qb,
                        const float* __restrict__ wh, const float* __restrict__ bh) {
    __shared__ float red[32];
    __shared__ float sraw[DD];
    __shared__ float sln[DD];
    int i = blockIdx.x, c = threadIdx.x;
    float x = slots[i * DD + c];
    sraw[c] = x;
    float mean = blockSum(x, red) * (1.f / 256.f);
    float d0 = x - mean;
    float var = blockSum(d0 * d0, red) * (1.f / 256.f);
    sln[c] = d0 * rsqrtf(var + 1e-5f) * nsg[c] + nsb[c];
    __syncthreads();
    float acc = qb[c];
    const float* wr = qw + (size_t)c * 256;
#pragma unroll 8
    for (int k = 0; k < 256; k++) acc += sln[k] * wr[k];
    g_qs[i * DD + c] = acc;
#pragma unroll
    for (int j = 0; j < 3; j++) {
        int u = j * 256 + c;
        float a = bh[u];
        const float* hr = wh + (size_t)u * 256;
#pragma unroll 8
        for (int k = 0; k < 256; k++) a += sraw[k] * hr[k];
        g_hg[i * 768 + u] = a;
    }
}

__device__ __forceinline__ void softmax_store(const unsigned long long* d,
                                              float* __restrict__ dst, int j) {
    float v[SS];
#pragma unroll
    for (int ip = 0; ip < 11; ip++) {
        float a, b;
        upk(d[ip], a, b);
        v[2 * ip] = a * 0.0625f;
        v[2 * ip + 1] = b * 0.0625f;
    }
    float mx = v[0];
#pragma unroll
    for (int i = 1; i < SS; i++) mx = fmaxf(mx, v[i]);
    float s = 0.f;
#pragma unroll
    for (int i = 0; i < SS; i++) { v[i] = __expf(v[i] - mx); s += v[i]; }
    float inv = 1.f / s;
#pragma unroll
    for (int i = 0; i < SS; i++) dst[i * NTOK + j] = v[i] * inv + 1e-8f;
}

// dots + softmax-over-slots + EPS; grid (BWIN, 4), 192 tokens per block
__global__ void __launch_bounds__(192) k_attn(float* __restrict__ out_attn,
                                              const float* __restrict__ kk) {
    __shared__ unsigned long long q2[11 * 256];
    __shared__ float ks[8][192];
    int bB = blockIdx.x, qa = blockIdx.y, tid = threadIdx.x;
    for (int idx = tid; idx < 11 * 256; idx += 192) {
        int ip = idx >> 8, k = idx & 255;
        q2[idx] = pk(g_qs[(2 * ip) * DD + k], g_qs[(2 * ip + 1) * DD + k]);
    }
    unsigned long long d[11];
#pragma unroll
    for (int ip = 0; ip < 11; ip++) d[ip] = 0ULL;
    size_t rowbase = (size_t)bB * NTOK + qa * 192;
    for (int kc = 0; kc < 256; kc += 8) {
        __syncthreads();
        const float4* src = (const float4*)(kk + (rowbase + tid) * 256 + kc);
        float4 v0 = src[0], v1 = src[1];
        ks[0][tid] = v0.x; ks[1][tid] = v0.y; ks[2][tid] = v0.z; ks[3][tid] = v0.w;
        ks[4][tid] = v1.x; ks[5][tid] = v1.y; ks[6][tid] = v1.z; ks[7][tid] = v1.w;
        __syncthreads();
#pragma unroll
        for (int kl = 0; kl < 8; kl++) {
            float kv = ks[kl][tid];
            unsigned long long sv = pk(kv, kv);
#pragma unroll
            for (int ip = 0; ip < 11; ip++)
                d[ip] = fma2(q2[ip * 256 + kc + kl], sv, d[ip]);
        }
    }
    int wi = bB / BATCH, bb = bB % BATCH;
    float* dst = out_attn + ((size_t)(bb * NWIN + wi)) * SS * NTOK;
    softmax_store(d, dst, qa * 192 + tid);
}

// renorm + weighted update -> split bf16; grid (BWIN, 2), 128 channels per block
__global__ void __launch_bounds__(128) k_upd(const float* __restrict__ attn,
                                             const float* __restrict__ vv) {
    __shared__ float red[32];
    __shared__ float sinv[SS];
    __shared__ unsigned long long at2[11 * 64];
    int bB = blockIdx.x, half = blockIdx.y, tid = threadIdx.x;
    int wi = bB / BATCH, bb = bB % BATCH;
    const float* ab = attn + ((size_t)(bb * NWIN + wi)) * SS * NTOK;
    for (int i = 0; i < SS; i++) {
        float p = 0.f;
        for (int j = tid; j < NTOK; j += 128) p += ab[i * NTOK + j];
        float s = blockSum(p, red);
        if (tid == 0) sinv[i] = 1.f / s;
    }
    __syncthreads();
    unsigned long long acc[11];
#pragma unroll
    for (int ip = 0; ip < 11; ip++) acc[ip] = 0ULL;
    int ch = half * 128 + tid;
    for (int j0 = 0; j0 < NTOK; j0 += 64) {
        for (int idx = tid; idx < 11 * 64; idx += 128) {
            int ip = idx >> 6, jj = idx & 63;
            at2[idx] = pk(ab[(2 * ip) * NTOK + j0 + jj],
                          ab[(2 * ip + 1) * NTOK + j0 + jj]);
        }
        __syncthreads();
        const float* vp = vv + ((size_t)bB * NTOK + j0) * 256 + ch;
#pragma unroll 4
        for (int jj = 0; jj < 64; jj++) {
            float v = vp[(size_t)jj * 256];
            unsigned long long sv = pk(v, v);
#pragma unroll
            for (int ip = 0; ip < 11; ip++)
                acc[ip] = fma2(at2[ip * 64 + jj], sv, acc[ip]);
        }
        __syncthreads();
    }
#pragma unroll
    for (int ip = 0; ip < 11; ip++) {
        float u0, u1;
        upk(acc[ip], u0, u1);
        u0 *= sinv[2 * ip];
        u1 *= sinv[2 * ip + 1];
        __nv_bfloat16 h0 = __float2bfloat16(u0);
        __nv_bfloat16 h1 = __float2bfloat16(u1);
        size_t r0 = ((size_t)bB * SS + 2 * ip) * DD + ch;
        size_t r1 = ((size_t)bB * SS + 2 * ip + 1) * DD + ch;
        g_updh[r0] = h0; g_updl[r0] = __float2bfloat16(u0 - __bfloat162float(h0));
        g_updh[r1] = h1; g_updl[r1] = __float2bfloat16(u1 - __bfloat162float(h1));
    }
}

__global__ void k_gate(const float* __restrict__ slots) {
    int m = blockIdx.x, c = threadIdx.x;
    int Bi = m / NAC, i = m % NAC;
    size_t row = (size_t)Bi * SS + i;
    float ir = g_xg[row * 768 + c];
    float iz = g_xg[row * 768 + 256 + c];
    float in_ = g_xg[row * 768 + 512 + c];
    float hr = g_hg[i * 768 + c];
    float hz = g_hg[i * 768 + 256 + c];
    float hn = g_hg[i * 768 + 512 + c];
    float h = slots[i * DD + c];
    float r = 1.f / (1.f + __expf(-(ir + hr)));
    float z = 1.f / (1.f + __expf(-(iz + hz)));
    float n = tanhf(in_ + r * hn);
    g_so[(size_t)m * DD + c] = (1.f - z) * n + z * h;
}

__global__ void k_final(float* __restrict__ out) {
    int m = blockIdx.x, c = threadIdx.x;
    int Bi = m / NAC, sl = m % NAC;
    int wi = Bi / BATCH, bb = Bi % BATCH;
    out[(((size_t)bb * NWIN + wi) * NAC + sl) * DD + c] =
        g_so[(size_t)m * DD + c] + g_t3[(size_t)m * DD + c];
}

extern "C" void kernel_launch(void* const* d_in, const int* in_sizes, int n_in,
                              void* d_out, int out_size) {
    const float* inputs = (const float*)d_in[0];
    const float* slots  = (const float*)d_in[1];
    const float* pe_w   = (const float*)d_in[2];
    const float* pe_b   = (const float*)d_in[3];
    const float* LN_g   = (const float*)d_in[4];
    const float* LN_b   = (const float*)d_in[5];
    const float* ni_g   = (const float*)d_in[6];
    const float* ni_b   = (const float*)d_in[7];
    const float* ns_g   = (const float*)d_in[8];
    const float* ns_b   = (const float*)d_in[9];
    const float* npf_g  = (const float*)d_in[10];
    const float* npf_b  = (const float*)d_in[11];
    const float* FC1_w  = (const float*)d_in[12];
    const float* FC1_b  = (const float*)d_in[13];
    const float* FC2_w  = (const float*)d_in[14];
    const float* FC2_b  = (const float*)d_in[15];
    const float* q_w    = (const float*)d_in[16];
    const float* q_b    = (const float*)d_in[17];
    const float* k_w    = (const float*)d_in[18];
    const float* k_b    = (const float*)d_in[19];
    const float* v_w    = (const float*)d_in[20];
    const float* v_b    = (const float*)d_in[21];
    const float* ff1_w  = (const float*)d_in[22];
    const float* ff1_b  = (const float*)d_in[23];
    const float* ff2_w  = (const float*)d_in[24];
    const float* ff2_b  = (const float*)d_in[25];
    const float* gru_wi = (const float*)d_in[26];
    const float* gru_wh = (const float*)d_in[27];
    const float* gru_bi = (const float*)d_in[28];
    const float* gru_bh = (const float*)d_in[29];

    float* out = (float*)d_out;
    float* out_attn = out + SLOTS_OUT_ELEMS;

    float *b0, *b1, *b2, *xg_, *so_, *t3_, *bkv;
    cudaGetSymbolAddress((void**)&b0, g_buf0);
    cudaGetSymbolAddress((void**)&b1, g_buf1);
    cudaGetSymbolAddress((void**)&b2, g_buf2);
    cudaGetSymbolAddress((void**)&xg_, g_xg);
    cudaGetSymbolAddress((void**)&so_, g_so);
    cudaGetSymbolAddress((void**)&t3_, g_t3);
    cudaGetSymbolAddress((void**)&bkv, g_bkv);

    __nv_bfloat16 *w1h, *w1l, *w2h, *w2l, *wkvh, *wkvl;
    __nv_bfloat16 *wgh, *wgl, *wf1h, *wf1l, *wf2h, *wf2l;
    __nv_bfloat16 *x0h, *x0l, *x1h, *x1l, *x2h, *x2l;
    __nv_bfloat16 *uh, *ul, *snh, *snl, *t2h, *t2l;
    cudaGetSymbolAddress((void**)&w1h, g_w1h); cudaGetSymbolAddress((void**)&w1l, g_w1l);
    cudaGetSymbolAddress((void**)&w2h, g_w2h); cudaGetSymbolAddress((void**)&w2l, g_w2l);
    cudaGetSymbolAddress((void**)&wkvh, g_wkvh); cudaGetSymbolAddress((void**)&wkvl, g_wkvl);
    cudaGetSymbolAddress((void**)&wgh, g_wgh); cudaGetSymbolAddress((void**)&wgl, g_wgl);
    cudaGetSymbolAddress((void**)&wf1h, g_wf1h); cudaGetSymbolAddress((void**)&wf1l, g_wf1l);
    cudaGetSymbolAddress((void**)&wf2h, g_wf2h); cudaGetSymbolAddress((void**)&wf2l, g_wf2l);
    cudaGetSymbolAddress((void**)&x0h, g_x0h); cudaGetSymbolAddress((void**)&x0l, g_x0l);
    cudaGetSymbolAddress((void**)&x1h, g_x1h); cudaGetSymbolAddress((void**)&x1l, g_x1l);
    cudaGetSymbolAddress((void**)&x2h, g_x2h); cudaGetSymbolAddress((void**)&x2l, g_x2l);
    cudaGetSymbolAddress((void**)&uh, g_updh); cudaGetSymbolAddress((void**)&ul, g_updl);
    cudaGetSymbolAddress((void**)&snh, g_solnh); cudaGetSymbolAddress((void**)&snl, g_solnl);
    cudaGetSymbolAddress((void**)&t2h, g_t2h); cudaGetSymbolAddress((void**)&t2l, g_t2l);

    cudaFuncSetAttribute((const void*)k_mma<true, true, false, false>,
                         cudaFuncAttributeMaxDynamicSharedMemorySize, MM_SMEM);
    cudaFuncSetAttribute((const void*)k_mma<false, false, false, false>,
                         cudaFuncAttributeMaxDynamicSharedMemorySize, MM_SMEM);
    cudaFuncSetAttribute((const void*)k_mma<false, false, false, true>,
                         cudaFuncAttributeMaxDynamicSharedMemorySize, MM_SMEM);
    cudaFuncSetAttribute((const void*)k_mma<false, false, true, false>,
                         cudaFuncAttributeMaxDynamicSharedMemorySize, MM_SMEM);

    // split all weights + KV concat + KV bias (one launch)
    k_splitall<<<2306, 256>>>(FC1_w, FC2_w, k_w, v_w, gru_wi, ff1_w, ff2_w, k_b, v_b);

    // positional embedding + gather + LN (split bf16 out)
    k_pe<<<NTOK, 256>>>(pe_w, pe_b);
    k_winln<<<MBIG / 8, 256>>>(inputs, LN_g, LN_b);

    // FC1 (relu, split out) -> FC2 (fp32 out)
    k_mma<true, true, false, false><<<dim3(2, MBIG / 128), 256, MM_SMEM>>>(
        x0h, x0l, w1h, w1l, FC1_b, nullptr, nullptr, x1h, x1l, MBIG, 256);
    k_mma<false, false, false, false><<<dim3(2, MBIG / 128), 256, MM_SMEM>>>(
        x1h, x1l, w2h, w2l, FC2_b, b0, nullptr, nullptr, nullptr, MBIG, 256);

    // norm_input (split out), fused K+V projection (fp32 out x2)
    k_ln2<<<MBIG / 8, 256>>>(b0, x2h, x2l, ni_g, ni_b);
    k_mma<false, false, false, true><<<dim3(4, MBIG / 128), 256, MM_SMEM>>>(
        x2h, x2l, wkvh, wkvl, bkv, b1, b2, nullptr, nullptr, MBIG, 256);

    // batch-invariant q and hidden gates
    k_small<<<SS, 256>>>(slots, ns_g, ns_b, q_w, q_b, gru_wh, gru_bh);

    // dots + softmax-over-slots + EPS (writes attns output directly)
    dim3 gAttn(BWIN, 4);
    k_attn<<<gAttn, 192>>>(out_attn, b1);

    // renorm + weighted update (split bf16 out)
    dim3 gUpd(BWIN, 2);
    k_upd<<<gUpd, 128>>>(out_attn, b2);

    // GRU input gates GEMM on tensor cores: (4928x256)@(768x256)^T
    k_mma<false, false, true, false><<<dim3(6, MGRUPAD / 128), 256, MM_SMEM>>>(
        uh, ul, wgh, wgl, gru_bi, xg_, nullptr, nullptr, nullptr, MGRU, 768);

    // gates -> slots (first 20)
    k_gate<<<MSO, 256>>>(slots);

    // residual MLP on tensor cores
    k_ln2<<<MSO / 8, 256>>>(so_, snh, snl, npf_g, npf_b);
    k_mma<true, true, false, false><<<dim3(2, MSO / 128), 256, MM_SMEM>>>(
        snh, snl, wf1h, wf1l, ff1_b, nullptr, nullptr, t2h, t2l, MSO, 256);
    k_mma<false, false, false, false><<<dim3(2, MSO / 128), 256, MM_SMEM>>>(
        t2h, t2l, wf2h, wf2l, ff2_b, t3_, nullptr, nullptr, nullptr, MSO, 256);

    // residual + permute into slots output
    k_final<<<MSO, 256>>>(out);
}

// round 10
// speedup vs baseline: 1.4311x; 1.0737x over previous
#include <cuda_runtime.h>
#include <cuda_bf16.h>
#include <math.h>
#include <stdint.h>

#define DD 256
#define SS 22
#define NAC 20
#define NTOK 768
#define NWIN 7
#define BATCH 32
#define BWIN 224
#define MBIG 172032
#define MGRU 4928
#define MGRUPAD 4992
#define MSO  4480
#define SLOTS_OUT_ELEMS 1146880

__device__ float g_pe[NTOK * DD];
__device__ float g_buf1[MBIG * DD];   // kk
__device__ float g_buf2[MBIG * DD];   // vv
__device__ __nv_bfloat16 g_x0h[MBIG * DD], g_x0l[MBIG * DD];  // winln out
__device__ __nv_bfloat16 g_x1h[MBIG * DD], g_x1l[MBIG * DD];  // FC1 out
__device__ __nv_bfloat16 g_x2h[MBIG * DD], g_x2l[MBIG * DD];  // fc2+LN out
__device__ float g_qs[SS * DD];
__device__ float g_hg[SS * 768];
__device__ __nv_bfloat16 g_updh[MGRUPAD * DD], g_updl[MGRUPAD * DD];
__device__ float g_xg[MGRU * 768];
__device__ float g_so[MSO * DD];
__device__ __nv_bfloat16 g_solnh[MSO * DD], g_solnl[MSO * DD];
__device__ __nv_bfloat16 g_t2h[MSO * DD], g_t2l[MSO * DD];
__device__ float g_t3[MSO * DD];
__device__ __nv_bfloat16 g_w1h[65536], g_w1l[65536];
__device__ __nv_bfloat16 g_w2h[65536], g_w2l[65536];
__device__ __nv_bfloat16 g_wkvh[131072], g_wkvl[131072];
__device__ float g_bkv[512];
__device__ __nv_bfloat16 g_wgh[196608], g_wgl[196608];
__device__ __nv_bfloat16 g_wf1h[65536], g_wf1l[65536];
__device__ __nv_bfloat16 g_wf2h[65536], g_wf2l[65536];

// ---------------- helpers ----------------
__device__ __forceinline__ uint32_t smem_u32(const void* p) {
    uint32_t a;
    asm("{ .reg .u64 t; cvta.to.shared.u64 t, %1; cvt.u32.u64 %0, t; }" : "=r"(a) : "l"(p));
    return a;
}
__device__ __forceinline__ unsigned long long pk(float x, float y) {
    unsigned long long r;
    asm("mov.b64 %0, {%1,%2};" : "=l"(r) : "f"(x), "f"(y));
    return r;
}
__device__ __forceinline__ void upk(unsigned long long v, float& x, float& y) {
    asm("mov.b64 {%0,%1}, %2;" : "=f"(x), "=f"(y) : "l"(v));
}
__device__ __forceinline__ unsigned long long fma2(unsigned long long a,
                                                   unsigned long long b,
                                                   unsigned long long c) {
    unsigned long long d;
    asm("fma.rn.f32x2 %0, %1, %2, %3;" : "=l"(d) : "l"(a), "l"(b), "l"(c));
    return d;
}
__device__ __forceinline__ uint32_t bfpack(float a, float b) {
    __nv_bfloat162 t = __floats2bfloat162_rn(a, b);
    return *reinterpret_cast<uint32_t*>(&t);
}
__device__ __forceinline__ void ldsm4(uint32_t* r, uint32_t addr) {
    asm volatile("ldmatrix.sync.aligned.m8n8.x4.shared.b16 {%0,%1,%2,%3}, [%4];"
        : "=r"(r[0]), "=r"(r[1]), "=r"(r[2]), "=r"(r[3]) : "r"(addr));
}
__device__ __forceinline__ void mma16816(float* d, const uint32_t* a,
                                         uint32_t b0, uint32_t b1) {
    asm("mma.sync.aligned.m16n8k16.row.col.f32.bf16.bf16.f32 "
        "{%0,%1,%2,%3}, {%4,%5,%6,%7}, {%8,%9}, {%0,%1,%2,%3};"
        : "+f"(d[0]), "+f"(d[1]), "+f"(d[2]), "+f"(d[3])
        : "r"(a[0]), "r"(a[1]), "r"(a[2]), "r"(a[3]), "r"(b0), "r"(b1));
}
__device__ __forceinline__ void cp16(uint32_t sm, const void* g) {
    asm volatile("cp.async.cg.shared.global [%0], [%1], 16;" :: "r"(sm), "l"(g));
}
__device__ __forceinline__ void cp_commit() {
    asm volatile("cp.async.commit_group;" ::: "memory");
}
template <int N>
__device__ __forceinline__ void cp_wait() {
    asm volatile("cp.async.wait_group %0;" :: "n"(N) : "memory");
}

__device__ __forceinline__ float blockSum(float v, float* s) {
    int tid = threadIdx.x;
#pragma unroll
    for (int o = 16; o > 0; o >>= 1) v += __shfl_down_sync(0xffffffffu, v, o);
    if ((tid & 31) == 0) s[tid >> 5] = v;
    __syncthreads();
    float r = (tid < (int)(blockDim.x >> 5)) ? s[tid] : 0.f;
    if (tid < 32) {
#pragma unroll
        for (int o = 4; o > 0; o >>= 1) r += __shfl_down_sync(0xffffffffu, r, o);
    }
    if (tid == 0) s[0] = r;
    __syncthreads();
    r = s[0];
    __syncthreads();
    return r;
}

// ---------------- small kernels ----------------
__global__ void k_pe(const float* __restrict__ pe_w, const float* __restrict__ pe_b) {
    int p = blockIdx.x, c = threadIdx.x;
    int t = p / 192, rem = p % 192, y = rem / 24, x = rem % 24;
    float g0 = t * (1.f / 3.f), g1 = y * (1.f / 7.f), g2 = x * (1.f / 23.f);
    const float* wr = pe_w + c * 6;
    g_pe[p * DD + c] = pe_b[c] + wr[0] * g0 + wr[1] * g1 + wr[2] * g2
        + wr[3] * (1.f - g0) + wr[4] * (1.f - g1) + wr[5] * (1.f - g2);
}

__global__ void __launch_bounds__(256) k_winln(const float* __restrict__ inp,
                                               const float* __restrict__ gam,
                                               const float* __restrict__ bet) {
    int m = (blockIdx.x * 256 + threadIdx.x) >> 5;
    int lane = threadIdx.x & 31;
    int wiB = m / NTOK, p = m % NTOK;
    int wi = wiB / BATCH, bb = wiB % BATCH;
    int t = p / 192, rem = p % 192;
    int f = 2 * wi + t;
    const float* src = inp + ((size_t)(bb * 16 + f) * 192 + rem) * DD;
    const float* pe = g_pe + p * DD;
    float x[8], s = 0.f, sq = 0.f;
#pragma unroll
    for (int i = 0; i < 8; i++) {
        int c = lane + i * 32;
        x[i] = src[c] + pe[c];
        s += x[i];
        sq += x[i] * x[i];
    }
#pragma unroll
    for (int o = 16; o > 0; o >>= 1) {
        s += __shfl_xor_sync(0xffffffffu, s, o);
        sq += __shfl_xor_sync(0xffffffffu, sq, o);
    }
    float mean = s * (1.f / 256.f);
    float var = sq * (1.f / 256.f) - mean * mean;
    float rs = rsqrtf(var + 1e-5f);
#pragma unroll
    for (int i = 0; i < 8; i++) {
        int c = lane + i * 32;
        float y = (x[i] - mean) * rs * gam[c] + bet[c];
        __nv_bfloat16 h = __float2bfloat16(y);
        g_x0h[(size_t)m * DD + c] = h;
        g_x0l[(size_t)m * DD + c] = __float2bfloat16(y - __bfloat162float(h));
    }
}

__global__ void __launch_bounds__(256) k_ln2(const float* __restrict__ src,
                                             __nv_bfloat16* __restrict__ dsth,
                                             __nv_bfloat16* __restrict__ dstl,
                                             const float* __restrict__ gam,
                                             const float* __restrict__ bet) {
    int m = (blockIdx.x * 256 + threadIdx.x) >> 5;
    int lane = threadIdx.x & 31;
    const float* sp = src + (size_t)m * DD;
    float x[8], s = 0.f, sq = 0.f;
#pragma unroll
    for (int i = 0; i < 8; i++) {
        x[i] = sp[lane + i * 32];
        s += x[i];
        sq += x[i] * x[i];
    }
#pragma unroll
    for (int o = 16; o > 0; o >>= 1) {
        s += __shfl_xor_sync(0xffffffffu, s, o);
        sq += __shfl_xor_sync(0xffffffffu, sq, o);
    }
    float mean = s * (1.f / 256.f);
    float var = sq * (1.f / 256.f) - mean * mean;
    float rs = rsqrtf(var + 1e-5f);
#pragma unroll
    for (int i = 0; i < 8; i++) {
        int c = lane + i * 32;
        float y = (x[i] - mean) * rs * gam[c] + bet[c];
        __nv_bfloat16 h = __float2bfloat16(y);
        dsth[(size_t)m * DD + c] = h;
        dstl[(size_t)m * DD + c] = __float2bfloat16(y - __bfloat162float(h));
    }
}

__global__ void k_splitall(const float* __restrict__ w1, const float* __restrict__ w2,
                           const float* __restrict__ wk, const float* __restrict__ wv,
                           const float* __restrict__ wg, const float* __restrict__ wf1,
                           const float* __restrict__ wf2,
                           const float* __restrict__ kb, const float* __restrict__ vb) {
    int idx = blockIdx.x * 256 + threadIdx.x;
    if (idx >= 590336) return;
    if (idx >= 589824) {
        int j = idx - 589824;
        g_bkv[j] = (j < 256) ? kb[j] : vb[j - 256];
        return;
    }
    const float* src;
    __nv_bfloat16 *h, *l;
    int j;
    if (idx < 65536)       { j = idx;          src = w1;  h = g_w1h;  l = g_w1l; }
    else if (idx < 131072) { j = idx - 65536;  src = w2;  h = g_w2h;  l = g_w2l; }
    else if (idx < 262144) {
        int jj = idx - 131072;
        j = (jj < 65536) ? jj : jj - 65536;
        src = (jj < 65536) ? wk : wv;
        h = g_wkvh + ((jj < 65536) ? 0 : 65536);
        l = g_wkvl + ((jj < 65536) ? 0 : 65536);
    }
    else if (idx < 458752) { j = idx - 262144; src = wg;  h = g_wgh;  l = g_wgl; }
    else if (idx < 524288) { j = idx - 458752; src = wf1; h = g_wf1h; l = g_wf1l; }
    else                   { j = idx - 524288; src = wf2; h = g_wf2h; l = g_wf2l; }
    float x = src[j];
    __nv_bfloat16 hh = __float2bfloat16(x);
    h[j] = hh;
    l[j] = __float2bfloat16(x - __bfloat162float(hh));
}

// ---------------- generic 3-stage split-bf16 mma GEMM (FC1/KV/gru/ff) ----------------
#define ROW3 144
#define AMAT 18432
#define STG3 36864
#define MM_SMEM 110592

template <bool RELU, bool SPLIT, bool MBOUND, bool KV>
__global__ void __launch_bounds__(256, 2) k_mma(
    const __nv_bfloat16* __restrict__ Ah, const __nv_bfloat16* __restrict__ Al,
    const __nv_bfloat16* __restrict__ Wh, const __nv_bfloat16* __restrict__ Wl,
    const float* __restrict__ bias, float* __restrict__ C, float* __restrict__ C2,
    __nv_bfloat16* __restrict__ Ch, __nv_bfloat16* __restrict__ Cl,
    int M, int N) {
    extern __shared__ char sm[];
    int tid = threadIdx.x, lane = tid & 31, wid = tid >> 5;
    int n0 = blockIdx.x * 128, m0 = blockIdx.y * 128;
    int mw = wid & 3, nw = wid >> 2;
    uint32_t sb = smem_u32(sm);

    float acc[2][8][4];
#pragma unroll
    for (int i = 0; i < 2; i++)
#pragma unroll
        for (int j = 0; j < 8; j++)
#pragma unroll
            for (int k = 0; k < 4; k++) acc[i][j][k] = 0.f;

    auto cpStage = [&](int ch, int buf) {
        int k0 = ch * 32;
        uint32_t st = sb + (uint32_t)buf * STG3;
#pragma unroll
        for (int i = 0; i < 8; i++) {
            int idx = tid + i * 256;
            int mat = idx >> 10;
            int j = idx & 1023;
            int row = j >> 3, part = j & 7;
            uint32_t off = (mat ? AMAT : 0) + (uint32_t)row * ROW3
                         + (part & 3) * 16 + (part >> 2) * 64;
            int kk0 = k0 + (part & 3) * 8;
            if (mat == 0) {
                const __nv_bfloat16* g =
                    ((part < 4) ? Ah : Al) + (size_t)(m0 + row) * 256 + kk0;
                cp16(st + off, g);
            } else {
                const __nv_bfloat16* g =
                    ((part < 4) ? Wh : Wl) + (size_t)(n0 + row) * 256 + kk0;
                cp16(st + off, g);
            }
        }
    };

    cpStage(0, 0); cp_commit();
    cpStage(1, 1); cp_commit();

#pragma unroll
    for (int ch = 0; ch < 8; ch++) {
        if (ch < 7) cp_wait<1>(); else cp_wait<0>();
        __syncthreads();
        if (ch < 6) { cpStage(ch + 2, (ch + 2) % 3); cp_commit(); }
        uint32_t st = sb + (uint32_t)(ch % 3) * STG3;
#pragma unroll
        for (int ks = 0; ks < 2; ks++) {
            int k = ks * 16;
            uint32_t koff = (uint32_t)(k + (lane >> 4) * 8) * 2;
            uint32_t ah[2][4], al[2][4];
#pragma unroll
            for (int mt = 0; mt < 2; mt++) {
                uint32_t addr = st
                    + (uint32_t)(mw * 32 + mt * 16 + (lane & 15)) * ROW3 + koff;
                ldsm4(ah[mt], addr);
                ldsm4(al[mt], addr + 64);
            }
#pragma unroll
            for (int p = 0; p < 4; p++) {
                uint32_t ba = st + AMAT
                    + (uint32_t)(nw * 64 + p * 16 + (lane & 15)) * ROW3 + koff;
                uint32_t bh[4], bl[4];
                ldsm4(bh, ba);
                ldsm4(bl, ba + 64);
                mma16816(acc[0][2 * p],     ah[0], bh[0], bh[2]);
                mma16816(acc[0][2 * p + 1], ah[0], bh[1], bh[3]);
                mma16816(acc[1][2 * p],     ah[1], bh[0], bh[2]);
                mma16816(acc[1][2 * p + 1], ah[1], bh[1], bh[3]);
                mma16816(acc[0][2 * p],     ah[0], bl[0], bl[2]);
                mma16816(acc[0][2 * p + 1], ah[0], bl[1], bl[3]);
                mma16816(acc[1][2 * p],     ah[1], bl[0], bl[2]);
                mma16816(acc[1][2 * p + 1], ah[1], bl[1], bl[3]);
                mma16816(acc[0][2 * p],     al[0], bh[0], bh[2]);
                mma16816(acc[0][2 * p + 1], al[0], bh[1], bh[3]);
                mma16816(acc[1][2 * p],     al[1], bh[0], bh[2]);
                mma16816(acc[1][2 * p + 1], al[1], bh[1], bh[3]);
            }
        }
    }

#pragma unroll
    for (int nt = 0; nt < 8; nt++) {
        int col = n0 + nw * 64 + nt * 8 + (lane & 3) * 2;
        float bx = bias[col], by = bias[col + 1];
#pragma unroll
        for (int mt = 0; mt < 2; mt++) {
            int row = m0 + mw * 32 + mt * 16 + (lane >> 2);
            float* a = acc[mt][nt];
            float2 o0 = make_float2(a[0] + bx, a[1] + by);
            float2 o1 = make_float2(a[2] + bx, a[3] + by);
            if (RELU) {
                o0.x = fmaxf(o0.x, 0.f); o0.y = fmaxf(o0.y, 0.f);
                o1.x = fmaxf(o1.x, 0.f); o1.y = fmaxf(o1.y, 0.f);
            }
            bool w0 = !MBOUND || row < M;
            bool w1 = !MBOUND || row + 8 < M;
            if (SPLIT) {
                __nv_bfloat162 h0 = __floats2bfloat162_rn(o0.x, o0.y);
                __nv_bfloat162 h1 = __floats2bfloat162_rn(o1.x, o1.y);
                uint32_t L0 = bfpack(o0.x - __bfloat162float(h0.x),
                                     o0.y - __bfloat162float(h0.y));
                uint32_t L1 = bfpack(o1.x - __bfloat162float(h1.x),
                                     o1.y - __bfloat162float(h1.y));
                if (w0) {
                    *reinterpret_cast<uint32_t*>(Ch + (size_t)row * N + col) =
                        *reinterpret_cast<uint32_t*>(&h0);
                    *reinterpret_cast<uint32_t*>(Cl + (size_t)row * N + col) = L0;
                }
                if (w1) {
                    *reinterpret_cast<uint32_t*>(Ch + (size_t)(row + 8) * N + col) =
                        *reinterpret_cast<uint32_t*>(&h1);
                    *reinterpret_cast<uint32_t*>(Cl + (size_t)(row + 8) * N + col) = L1;
                }
            } else if (KV) {
                float* dst = (col < 256) ? C : C2;
                int cc = col & 255;
                if (w0) *reinterpret_cast<float2*>(dst + (size_t)row * 256 + cc) = o0;
                if (w1) *reinterpret_cast<float2*>(dst + (size_t)(row + 8) * 256 + cc) = o1;
            } else {
                if (w0) *reinterpret_cast<float2*>(C + (size_t)row * N + col) = o0;
                if (w1) *reinterpret_cast<float2*>(C + (size_t)(row + 8) * N + col) = o1;
            }
        }
    }
}

// ---------------- fused FC2 + LayerNorm GEMM ----------------
// tile 64x256 (full rows per CTA), 2-stage cp.async, LN in epilogue, split-bf16 out.
#define F_AROWS 64
#define F_BOFF 9216        // 64*144
#define F_STG 46080        // 9216 + 256*144
#define F_GB 92160         // 2 stages
#define F_RED 95232        // gb: 3*256 floats
#define F_SMEM 96256

__global__ void __launch_bounds__(256, 2) k_fc2ln(
    const __nv_bfloat16* __restrict__ Ah, const __nv_bfloat16* __restrict__ Al,
    const __nv_bfloat16* __restrict__ Wh, const __nv_bfloat16* __restrict__ Wl,
    const float* __restrict__ bias, const float* __restrict__ gam,
    const float* __restrict__ bet,
    __nv_bfloat16* __restrict__ Ch, __nv_bfloat16* __restrict__ Cl) {
    extern __shared__ char sm[];
    int tid = threadIdx.x, lane = tid & 31, wid = tid >> 5;
    int m0 = blockIdx.x * F_AROWS;
    int mw = wid & 3, nw = wid >> 2;
    uint32_t sb = smem_u32(sm);
    float* gb = (float*)(sm + F_GB);          // [bias|gam|bet] x 256
    float2* red = (float2*)(sm + F_RED);      // [64][2]

    // preload bias/gamma/beta
    {
        int c = tid;
        gb[c] = bias[c];
        gb[256 + c] = gam[c];
        gb[512 + c] = bet[c];
    }

    float acc[16][4];
#pragma unroll
    for (int j = 0; j < 16; j++)
#pragma unroll
        for (int k = 0; k < 4; k++) acc[j][k] = 0.f;

    auto cpStage = [&](int ch, int buf) {
        int k0 = ch * 32;
        uint32_t st = sb + (uint32_t)buf * F_STG;
#pragma unroll
        for (int i = 0; i < 10; i++) {
            int idx = tid + i * 256;
            if (idx < 512) {
                int row = idx >> 3, part = idx & 7;
                uint32_t off = (uint32_t)row * ROW3 + (part & 3) * 16 + (part >> 2) * 64;
                const __nv_bfloat16* g =
                    ((part < 4) ? Ah : Al) + (size_t)(m0 + row) * 256 + k0 + (part & 3) * 8;
                cp16(st + off, g);
            } else {
                int j = idx - 512;
                int row = j >> 3, part = j & 7;
                uint32_t off = F_BOFF + (uint32_t)row * ROW3 + (part & 3) * 16 + (part >> 2) * 64;
                const __nv_bfloat16* g =
                    ((part < 4) ? Wh : Wl) + (size_t)row * 256 + k0 + (part & 3) * 8;
                cp16(st + off, g);
            }
        }
    };

    cpStage(0, 0); cp_commit();

#pragma unroll
    for (int ch = 0; ch < 8; ch++) {
        cp_wait<0>();
        __syncthreads();
        if (ch < 7) { cpStage(ch + 1, (ch + 1) & 1); cp_commit(); }
        uint32_t st = sb + (uint32_t)(ch & 1) * F_STG;
#pragma unroll
        for (int ks = 0; ks < 2; ks++) {
            uint32_t koff = (uint32_t)(ks * 16 + (lane >> 4) * 8) * 2;
            uint32_t ah[4], al[4];
            uint32_t aaddr = st + (uint32_t)(mw * 16 + (lane & 15)) * ROW3 + koff;
            ldsm4(ah, aaddr);
            ldsm4(al, aaddr + 64);
#pragma unroll
            for (int p = 0; p < 8; p++) {
                uint32_t ba = st + F_BOFF
                    + (uint32_t)(nw * 128 + p * 16 + (lane & 15)) * ROW3 + koff;
                uint32_t bh[4], bl[4];
                ldsm4(bh, ba);
                ldsm4(bl, ba + 64);
                mma16816(acc[2 * p],     ah, bh[0], bh[2]);
                mma16816(acc[2 * p + 1], ah, bh[1], bh[3]);
                mma16816(acc[2 * p],     ah, bl[0], bl[2]);
                mma16816(acc[2 * p + 1], ah, bl[1], bl[3]);
                mma16816(acc[2 * p],     al, bh[0], bh[2]);
                mma16816(acc[2 * p + 1], al, bh[1], bh[3]);
            }
        }
    }

    // epilogue: +bias, row stats, LN, split-bf16 write
    float s0 = 0.f, q0 = 0.f, s1 = 0.f, q1 = 0.f;
#pragma unroll
    for (int nt = 0; nt < 16; nt++) {
        int col = nw * 128 + nt * 8 + (lane & 3) * 2;
        float bx = gb[col], by = gb[col + 1];
        acc[nt][0] += bx; acc[nt][1] += by;
        acc[nt][2] += bx; acc[nt][3] += by;
        s0 += acc[nt][0] + acc[nt][1];
        q0 += acc[nt][0] * acc[nt][0] + acc[nt][1] * acc[nt][1];
        s1 += acc[nt][2] + acc[nt][3];
        q1 += acc[nt][2] * acc[nt][2] + acc[nt][3] * acc[nt][3];
    }
#pragma unroll
    for (int o = 1; o <= 2; o <<= 1) {
        s0 += __shfl_xor_sync(0xffffffffu, s0, o);
        q0 += __shfl_xor_sync(0xffffffffu, q0, o);
        s1 += __shfl_xor_sync(0xffffffffu, s1, o);
        q1 += __shfl_xor_sync(0xffffffffu, q1, o);
    }
    int rloc = mw * 16 + (lane >> 2);
    if ((lane & 3) == 0) {
        red[rloc * 2 + nw] = make_float2(s0, q0);
        red[(rloc + 8) * 2 + nw] = make_float2(s1, q1);
    }
    __syncthreads();
    float2 a0 = red[rloc * 2], b0f = red[rloc * 2 + 1];
    float ss = a0.x + b0f.x, qq = a0.y + b0f.y;
    float mean0 = ss * (1.f / 256.f);
    float rs0 = rsqrtf(qq * (1.f / 256.f) - mean0 * mean0 + 1e-5f);
    float2 a1 = red[(rloc + 8) * 2], b1f = red[(rloc + 8) * 2 + 1];
    float ss1 = a1.x + b1f.x, qq1 = a1.y + b1f.y;
    float mean1 = ss1 * (1.f / 256.f);
    float rs1 = rsqrtf(qq1 * (1.f / 256.f) - mean1 * mean1 + 1e-5f);

    int row0 = m0 + rloc, row1 = row0 + 8;
#pragma unroll
    for (int nt = 0; nt < 16; nt++) {
        int col = nw * 128 + nt * 8 + (lane & 3) * 2;
        float gx = gb[256 + col], gy = gb[256 + col + 1];
        float ex = gb[512 + col], ey = gb[512 + col + 1];
        float y00 = (acc[nt][0] - mean0) * rs0 * gx + ex;
        float y01 = (acc[nt][1] - mean0) * rs0 * gy + ey;
        float y10 = (acc[nt][2] - mean1) * rs1 * gx + ex;
        float y11 = (acc[nt][3] - mean1) * rs1 * gy + ey;
        __nv_bfloat162 h0 = __floats2bfloat162_rn(y00, y01);
        __nv_bfloat162 h1 = __floats2bfloat162_rn(y10, y11);
        uint32_t L0 = bfpack(y00 - __bfloat162float(h0.x), y01 - __bfloat162float(h0.y));
        uint32_t L1 = bfpack(y10 - __bfloat162float(h1.x), y11 - __bfloat162float(h1.y));
        *reinterpret_cast<uint32_t*>(Ch + (size_t)row0 * 256 + col) =
            *reinterpret_cast<uint32_t*>(&h0);
        *reinterpret_cast<uint32_t*>(Cl + (size_t)row0 * 256 + col) = L0;
        *reinterpret_cast<uint32_t*>(Ch + (size_t)row1 * 256 + col) =
            *reinterpret_cast<uint32_t*>(&h1);
        *reinterpret_cast<uint32_t*>(Cl + (size_t)row1 * 256 + col) = L1;
    }
}

// q = LN_ns(slots)@q_w^T + q_b ; hg = slots@gru_wh^T + gru_bh (22 rows)
__global__ void k_small(const float* __restrict__ slots,
                        const float* __restrict__ nsg, const float* __restrict__ nsb,
                        const float* __restrict__ qw, const float* __restrict__ qb,
                        const float* __restrict__ wh, const float* __restrict__ bh) {
    __shared__ float red[32];
    __shared__ float sraw[DD];
    __shared__ float sln[DD];
    int i = blockIdx.x, c = threadIdx.x;
    float x = slots[i * DD + c];
    sraw[c] = x;
    float mean = blockSum(x, red) * (1.f / 256.f);
    float d0 = x - mean;
    float var = blockSum(d0 * d0, red) * (1.f / 256.f);
    sln[c] = d0 * rsqrtf(var + 1e-5f) * nsg[c] + nsb[c];
    __syncthreads();
    float acc = qb[c];
    const float* wr = qw + (size_t)c * 256;
#pragma unroll 8
    for (int k = 0; k < 256; k++) acc += sln[k] * wr[k];
    g_qs[i * DD + c] = acc;
#pragma unroll
    for (int j = 0; j < 3; j++) {
        int u = j * 256 + c;
        float a = bh[u];
        const float* hr = wh + (size_t)u * 256;
#pragma unroll 8
        for (int k = 0; k < 256; k++) a += sraw[k] * hr[k];
        g_hg[i * 768 + u] = a;
    }
}

__device__ __forceinline__ void softmax_store2(const unsigned long long* d,
                                               float* __restrict__ gdst,
                                               float* __restrict__ sdst, int j) {
    float v[SS];
#pragma unroll
    for (int ip = 0; ip < 11; ip++) {
        float a, b;
        upk(d[ip], a, b);
        v[2 * ip] = a * 0.0625f;
        v[2 * ip + 1] = b * 0.0625f;
    }
    float mx = v[0];
#pragma unroll
    for (int i = 1; i < SS; i++) mx = fmaxf(mx, v[i]);
    float s = 0.f;
#pragma unroll
    for (int i = 0; i < SS; i++) { v[i] = __expf(v[i] - mx); s += v[i]; }
    float inv = 1.f / s;
#pragma unroll
    for (int i = 0; i < SS; i++) {
        float val = v[i] * inv + 1e-8f;
        gdst[i * NTOK + j] = val;
        sdst[i * NTOK + j] = val;
    }
}

// ---------------- fused attn (dots+softmax) + renorm + update ----------------
// one block per window-batch B; attn_ori tile kept in smem.
// smem: q2 ull[2816] @0 (22528) | ks f[8*768] @22528 (24576; reused as at2 ull[11*96])
//       | at f[22*768] @47104 (67584) | red f[32] @114688 | sinv f[22] @114816
#define AT_SMEM 114944

__global__ void __launch_bounds__(256) k_attup(float* __restrict__ out_attn,
                                               const float* __restrict__ kk,
                                               const float* __restrict__ vv) {
    extern __shared__ char sm[];
    unsigned long long* q2 = (unsigned long long*)sm;
    float* ks = (float*)(sm + 22528);
    unsigned long long* at2 = (unsigned long long*)(sm + 22528);
    float* at = (float*)(sm + 47104);
    float* red = (float*)(sm + 114688);
    float* sinv = (float*)(sm + 114816);
    int bB = blockIdx.x, tid = threadIdx.x;

    for (int idx = tid; idx < 11 * 256; idx += 256) {
        int ip = idx >> 8, k = idx & 255;
        q2[idx] = pk(g_qs[(2 * ip) * DD + k], g_qs[(2 * ip + 1) * DD + k]);
    }
    unsigned long long d0[11], d1[11], d2[11];
#pragma unroll
    for (int ip = 0; ip < 11; ip++) { d0[ip] = 0ULL; d1[ip] = 0ULL; d2[ip] = 0ULL; }
    size_t rowbase = (size_t)bB * NTOK;
    for (int kc = 0; kc < 256; kc += 8) {
        __syncthreads();
#pragma unroll
        for (int rr = 0; rr < 3; rr++) {
            int r = tid + rr * 256;
            const float4* src = (const float4*)(kk + (rowbase + r) * 256 + kc);
            float4 v0 = src[0], v1 = src[1];
            ks[0 * 768 + r] = v0.x; ks[1 * 768 + r] = v0.y;
            ks[2 * 768 + r] = v0.z; ks[3 * 768 + r] = v0.w;
            ks[4 * 768 + r] = v1.x; ks[5 * 768 + r] = v1.y;
            ks[6 * 768 + r] = v1.z; ks[7 * 768 + r] = v1.w;
        }
        __syncthreads();
#pragma unroll
        for (int kl = 0; kl < 8; kl++) {
            float kv0 = ks[kl * 768 + tid];
            float kv1 = ks[kl * 768 + tid + 256];
            float kv2 = ks[kl * 768 + tid + 512];
            unsigned long long s0 = pk(kv0, kv0), s1 = pk(kv1, kv1), s2 = pk(kv2, kv2);
#pragma unroll
            for (int ip = 0; ip < 11; ip++) {
                unsigned long long qv = q2[ip * 256 + kc + kl];
                d0[ip] = fma2(qv, s0, d0[ip]);
                d1[ip] = fma2(qv, s1, d1[ip]);
                d2[ip] = fma2(qv, s2, d2[ip]);
            }
        }
    }
    int wi = bB / BATCH, bb = bB % BATCH;
    float* gdst = out_attn + ((size_t)(bb * NWIN + wi)) * SS * NTOK;
    softmax_store2(d0, gdst, at, tid);
    softmax_store2(d1, gdst, at, tid + 256);
    softmax_store2(d2, gdst, at, tid + 512);
    __syncthreads();

    // renorm sums
    for (int i = 0; i < SS; i++) {
        float p = at[i * 768 + tid] + at[i * 768 + tid + 256] + at[i * 768 + tid + 512];
        float s = blockSum(p, red);
        if (tid == 0) sinv[i] = 1.f / s;
    }
    __syncthreads();

    // update: channel = tid
    unsigned long long acc[11];
#pragma unroll
    for (int ip = 0; ip < 11; ip++) acc[ip] = 0ULL;
    for (int j0 = 0; j0 < NTOK; j0 += 96) {
        __syncthreads();
        for (int idx = tid; idx < 11 * 96; idx += 256) {
            int ip = idx / 96, jj = idx % 96;
            at2[ip * 96 + jj] = pk(at[(2 * ip) * 768 + j0 + jj],
                                   at[(2 * ip + 1) * 768 + j0 + jj]);
        }
        __syncthreads();
        const float* vp = vv + (rowbase + j0) * 256 + tid;
#pragma unroll 4
        for (int jj = 0; jj < 96; jj++) {
            float v = vp[(size_t)jj * 256];
            unsigned long long sv = pk(v, v);
#pragma unroll
            for (int ip = 0; ip < 11; ip++)
                acc[ip] = fma2(at2[ip * 96 + jj], sv, acc[ip]);
        }
    }
#pragma unroll
    for (int ip = 0; ip < 11; ip++) {
        float u0, u1;
        upk(acc[ip], u0, u1);
        u0 *= sinv[2 * ip];
        u1 *= sinv[2 * ip + 1];
        __nv_bfloat16 h0 = __float2bfloat16(u0);
        __nv_bfloat16 h1 = __float2bfloat16(u1);
        size_t r0 = ((size_t)bB * SS + 2 * ip) * DD + tid;
        size_t r1 = ((size_t)bB * SS + 2 * ip + 1) * DD + tid;
        g_updh[r0] = h0; g_updl[r0] = __float2bfloat16(u0 - __bfloat162float(h0));
        g_updh[r1] = h1; g_updl[r1] = __float2bfloat16(u1 - __bfloat162float(h1));
    }
}

__global__ void k_gate(const float* __restrict__ slots) {
    int m = blockIdx.x, c = threadIdx.x;
    int Bi = m / NAC, i = m % NAC;
    size_t row = (size_t)Bi * SS + i;
    float ir = g_xg[row * 768 + c];
    float iz = g_xg[row * 768 + 256 + c];
    float in_ = g_xg[row * 768 + 512 + c];
    float hr = g_hg[i * 768 + c];
    float hz = g_hg[i * 768 + 256 + c];
    float hn = g_hg[i * 768 + 512 + c];
    float h = slots[i * DD + c];
    float r = 1.f / (1.f + __expf(-(ir + hr)));
    float z = 1.f / (1.f + __expf(-(iz + hz)));
    float n = tanhf(in_ + r * hn);
    g_so[(size_t)m * DD + c] = (1.f - z) * n + z * h;
}

__global__ void k_final(float* __restrict__ out) {
    int m = blockIdx.x, c = threadIdx.x;
    int Bi = m / NAC, sl = m % NAC;
    int wi = Bi / BATCH, bb = Bi % BATCH;
    out[(((size_t)bb * NWIN + wi) * NAC + sl) * DD + c] =
        g_so[(size_t)m * DD + c] + g_t3[(size_t)m * DD + c];
}

extern "C" void kernel_launch(void* const* d_in, const int* in_sizes, int n_in,
                              void* d_out, int out_size) {
    const float* inputs = (const float*)d_in[0];
    const float* slots  = (const float*)d_in[1];
    const float* pe_w   = (const float*)d_in[2];
    const float* pe_b   = (const float*)d_in[3];
    const float* LN_g   = (const float*)d_in[4];
    const float* LN_b   = (const float*)d_in[5];
    const float* ni_g   = (const float*)d_in[6];
    const float* ni_b   = (const float*)d_in[7];
    const float* ns_g   = (const float*)d_in[8];
    const float* ns_b   = (const float*)d_in[9];
    const float* npf_g  = (const float*)d_in[10];
    const float* npf_b  = (const float*)d_in[11];
    const float* FC1_w  = (const float*)d_in[12];
    const float* FC1_b  = (const float*)d_in[13];
    const float* FC2_w  = (const float*)d_in[14];
    const float* FC2_b  = (const float*)d_in[15];
    const float* q_w    = (const float*)d_in[16];
    const float* q_b    = (const float*)d_in[17];
    const float* k_w    = (const float*)d_in[18];
    const float* k_b    = (const float*)d_in[19];
    const float* v_w    = (const float*)d_in[20];
    const float* v_b    = (const float*)d_in[21];
    const float* ff1_w  = (const float*)d_in[22];
    const float* ff1_b  = (const float*)d_in[23];
    const float* ff2_w  = (const float*)d_in[24];
    const float* ff2_b  = (const float*)d_in[25];
    const float* gru_wi = (const float*)d_in[26];
    const float* gru_wh = (const float*)d_in[27];
    const float* gru_bi = (const float*)d_in[28];
    const float* gru_bh = (const float*)d_in[29];

    float* out = (float*)d_out;
    float* out_attn = out + SLOTS_OUT_ELEMS;

    float *b1, *b2, *xg_, *so_, *t3_, *bkv;
    cudaGetSymbolAddress((void**)&b1, g_buf1);
    cudaGetSymbolAddress((void**)&b2, g_buf2);
    cudaGetSymbolAddress((void**)&xg_, g_xg);
    cudaGetSymbolAddress((void**)&so_, g_so);
    cudaGetSymbolAddress((void**)&t3_, g_t3);
    cudaGetSymbolAddress((void**)&bkv, g_bkv);

    __nv_bfloat16 *w1h, *w1l, *w2h, *w2l, *wkvh, *wkvl;
    __nv_bfloat16 *wgh, *wgl, *wf1h, *wf1l, *wf2h, *wf2l;
    __nv_bfloat16 *x0h, *x0l, *x1h, *x1l, *x2h, *x2l;
    __nv_bfloat16 *uh, *ul, *snh, *snl, *t2h, *t2l;
    cudaGetSymbolAddress((void**)&w1h, g_w1h); cudaGetSymbolAddress((void**)&w1l, g_w1l);
    cudaGetSymbolAddress((void**)&w2h, g_w2h); cudaGetSymbolAddress((void**)&w2l, g_w2l);
    cudaGetSymbolAddress((void**)&wkvh, g_wkvh); cudaGetSymbolAddress((void**)&wkvl, g_wkvl);
    cudaGetSymbolAddress((void**)&wgh, g_wgh); cudaGetSymbolAddress((void**)&wgl, g_wgl);
    cudaGetSymbolAddress((void**)&wf1h, g_wf1h); cudaGetSymbolAddress((void**)&wf1l, g_wf1l);
    cudaGetSymbolAddress((void**)&wf2h, g_wf2h); cudaGetSymbolAddress((void**)&wf2l, g_wf2l);
    cudaGetSymbolAddress((void**)&x0h, g_x0h); cudaGetSymbolAddress((void**)&x0l, g_x0l);
    cudaGetSymbolAddress((void**)&x1h, g_x1h); cudaGetSymbolAddress((void**)&x1l, g_x1l);
    cudaGetSymbolAddress((void**)&x2h, g_x2h); cudaGetSymbolAddress((void**)&x2l, g_x2l);
    cudaGetSymbolAddress((void**)&uh, g_updh); cudaGetSymbolAddress((void**)&ul, g_updl);
    cudaGetSymbolAddress((void**)&snh, g_solnh); cudaGetSymbolAddress((void**)&snl, g_solnl);
    cudaGetSymbolAddress((void**)&t2h, g_t2h); cudaGetSymbolAddress((void**)&t2l, g_t2l);

    cudaFuncSetAttribute((const void*)k_mma<true, true, false, false>,
                         cudaFuncAttributeMaxDynamicSharedMemorySize, MM_SMEM);
    cudaFuncSetAttribute((const void*)k_mma<false, false, false, true>,
                         cudaFuncAttributeMaxDynamicSharedMemorySize, MM_SMEM);
    cudaFuncSetAttribute((const void*)k_mma<false, false, true, false>,
                         cudaFuncAttributeMaxDynamicSharedMemorySize, MM_SMEM);
    cudaFuncSetAttribute((const void*)k_mma<false, false, false, false>,
                         cudaFuncAttributeMaxDynamicSharedMemorySize, MM_SMEM);
    cudaFuncSetAttribute((const void*)k_fc2ln,
                         cudaFuncAttributeMaxDynamicSharedMemorySize, F_SMEM);
    cudaFuncSetAttribute((const void*)k_attup,
                         cudaFuncAttributeMaxDynamicSharedMemorySize, AT_SMEM);

    k_splitall<<<2306, 256>>>(FC1_w, FC2_w, k_w, v_w, gru_wi, ff1_w, ff2_w, k_b, v_b);

    k_pe<<<NTOK, 256>>>(pe_w, pe_b);
    k_winln<<<MBIG / 8, 256>>>(inputs, LN_g, LN_b);

    // FC1 (relu, split out)
    k_mma<true, true, false, false><<<dim3(2, MBIG / 128), 256, MM_SMEM>>>(
        x0h, x0l, w1h, w1l, FC1_b, nullptr, nullptr, x1h, x1l, MBIG, 256);

    // FC2 + norm_input LN fused (split out)
    k_fc2ln<<<MBIG / 64, 256, F_SMEM>>>(x1h, x1l, w2h, w2l, FC2_b, ni_g, ni_b,
                                        x2h, x2l);

    // fused K+V projection
    k_mma<false, false, false, true><<<dim3(4, MBIG / 128), 256, MM_SMEM>>>(
        x2h, x2l, wkvh, wkvl, bkv, b1, b2, nullptr, nullptr, MBIG, 256);

    k_small<<<SS, 256>>>(slots, ns_g, ns_b, q_w, q_b, gru_wh, gru_bh);

    // fused dots+softmax+renorm+update
    k_attup<<<BWIN, 256, AT_SMEM>>>(out_attn, b1, b2);

    // GRU input gates GEMM
    k_mma<false, false, true, false><<<dim3(6, MGRUPAD / 128), 256, MM_SMEM>>>(
        uh, ul, wgh, wgl, gru_bi, xg_, nullptr, nullptr, nullptr, MGRU, 768);

    k_gate<<<MSO, 256>>>(slots);

    k_ln2<<<MSO / 8, 256>>>(so_, snh, snl, npf_g, npf_b);
    k_mma<true, true, false, false><<<dim3(2, MSO / 128), 256, MM_SMEM>>>(
        snh, snl, wf1h, wf1l, ff1_b, nullptr, nullptr, t2h, t2l, MSO, 256);
    k_mma<false, false, false, false><<<dim3(2, MSO / 128), 256, MM_SMEM>>>(
        t2h, t2l, wf2h, wf2l, ff2_b, t3_, nullptr, nullptr, nullptr, MSO, 256);

    k_final<<<MSO, 256>>>(out);
}

// round 11
// speedup vs baseline: 1.9589x; 1.3688x over previous
#include <cuda_runtime.h>
#include <cuda_bf16.h>
#include <math.h>
#include <stdint.h>

#define DD 256
#define SS 22
#define NAC 20
#define NTOK 768
#define NWIN 7
#define BATCH 32
#define BWIN 224
#define MBIG 172032
#define MGRU 4928
#define MGRUPAD 4992
#define MSO  4480
#define SLOTS_OUT_ELEMS 1146880

__device__ float g_pe[NTOK * DD];
__device__ __nv_bfloat16 g_x0h[MBIG * DD], g_x0l[MBIG * DD];  // winln out; reused as mid
__device__ __nv_bfloat16 g_x1h[MBIG * DD], g_x1l[MBIG * DD];  // FC1 out
__device__ __nv_bfloat16 g_x2h[MBIG * DD], g_x2l[MBIG * DD];  // fc2+LN out
__device__ float g_qs[SS * DD];     // holds qk = q @ k_w
__device__ float g_qkb[SS];
__device__ float g_hg[SS * 768];
__device__ __nv_bfloat16 g_updh[MGRUPAD * DD], g_updl[MGRUPAD * DD];
__device__ float g_xg[MGRU * 768];
__device__ float g_so[MSO * DD];
__device__ __nv_bfloat16 g_solnh[MSO * DD], g_solnl[MSO * DD];
__device__ __nv_bfloat16 g_t2h[MSO * DD], g_t2l[MSO * DD];
__device__ float g_t3[MSO * DD];
__device__ __nv_bfloat16 g_w1h[65536], g_w1l[65536];
__device__ __nv_bfloat16 g_w2h[65536], g_w2l[65536];
__device__ __nv_bfloat16 g_wvh[65536], g_wvl[65536];
__device__ __nv_bfloat16 g_wgh[196608], g_wgl[196608];
__device__ __nv_bfloat16 g_wf1h[65536], g_wf1l[65536];
__device__ __nv_bfloat16 g_wf2h[65536], g_wf2l[65536];

// ---------------- helpers ----------------
__device__ __forceinline__ uint32_t smem_u32(const void* p) {
    uint32_t a;
    asm("{ .reg .u64 t; cvta.to.shared.u64 t, %1; cvt.u32.u64 %0, t; }" : "=r"(a) : "l"(p));
    return a;
}
__device__ __forceinline__ unsigned long long pk(float x, float y) {
    unsigned long long r;
    asm("mov.b64 %0, {%1,%2};" : "=l"(r) : "f"(x), "f"(y));
    return r;
}
__device__ __forceinline__ void upk(unsigned long long v, float& x, float& y) {
    asm("mov.b64 {%0,%1}, %2;" : "=f"(x), "=f"(y) : "l"(v));
}
__device__ __forceinline__ unsigned long long fma2(unsigned long long a,
                                                   unsigned long long b,
                                                   unsigned long long c) {
    unsigned long long d;
    asm("fma.rn.f32x2 %0, %1, %2, %3;" : "=l"(d) : "l"(a), "l"(b), "l"(c));
    return d;
}
__device__ __forceinline__ uint32_t bfpack(float a, float b) {
    __nv_bfloat162 t = __floats2bfloat162_rn(a, b);
    return *reinterpret_cast<uint32_t*>(&t);
}
__device__ __forceinline__ void ldsm4(uint32_t* r, uint32_t addr) {
    asm volatile("ldmatrix.sync.aligned.m8n8.x4.shared.b16 {%0,%1,%2,%3}, [%4];"
        : "=r"(r[0]), "=r"(r[1]), "=r"(r[2]), "=r"(r[3]) : "r"(addr));
}
__device__ __forceinline__ void mma16816(float* d, const uint32_t* a,
                                         uint32_t b0, uint32_t b1) {
    asm("mma.sync.aligned.m16n8k16.row.col.f32.bf16.bf16.f32 "
        "{%0,%1,%2,%3}, {%4,%5,%6,%7}, {%8,%9}, {%0,%1,%2,%3};"
        : "+f"(d[0]), "+f"(d[1]), "+f"(d[2]), "+f"(d[3])
        : "r"(a[0]), "r"(a[1]), "r"(a[2]), "r"(a[3]), "r"(b0), "r"(b1));
}
__device__ __forceinline__ void cp16(uint32_t sm, const void* g) {
    asm volatile("cp.async.cg.shared.global [%0], [%1], 16;" :: "r"(sm), "l"(g));
}
__device__ __forceinline__ void cp_commit() {
    asm volatile("cp.async.commit_group;" ::: "memory");
}
template <int N>
__device__ __forceinline__ void cp_wait() {
    asm volatile("cp.async.wait_group %0;" :: "n"(N) : "memory");
}
// reconstruct 8 fp32 from bf16 hi/lo uint4 pairs
__device__ __forceinline__ void rec8(uint4 H, uint4 L, float* o) {
    const uint32_t hw[4] = {H.x, H.y, H.z, H.w};
    const uint32_t lw[4] = {L.x, L.y, L.z, L.w};
#pragma unroll
    for (int i = 0; i < 4; i++) {
        __nv_bfloat162 hb = *reinterpret_cast<const __nv_bfloat162*>(&hw[i]);
        __nv_bfloat162 lb = *reinterpret_cast<const __nv_bfloat162*>(&lw[i]);
        float2 hf = __bfloat1622float2(hb);
        float2 lf = __bfloat1622float2(lb);
        o[2 * i] = hf.x + lf.x;
        o[2 * i + 1] = hf.y + lf.y;
    }
}

__device__ __forceinline__ float blockSum(float v, float* s) {
    int tid = threadIdx.x;
#pragma unroll
    for (int o = 16; o > 0; o >>= 1) v += __shfl_down_sync(0xffffffffu, v, o);
    if ((tid & 31) == 0) s[tid >> 5] = v;
    __syncthreads();
    float r = (tid < (int)(blockDim.x >> 5)) ? s[tid] : 0.f;
    if (tid < 32) {
#pragma unroll
        for (int o = 4; o > 0; o >>= 1) r += __shfl_down_sync(0xffffffffu, r, o);
    }
    if (tid == 0) s[0] = r;
    __syncthreads();
    r = s[0];
    __syncthreads();
    return r;
}

// ---------------- small kernels ----------------
__global__ void k_pe(const float* __restrict__ pe_w, const float* __restrict__ pe_b) {
    int p = blockIdx.x, c = threadIdx.x;
    int t = p / 192, rem = p % 192, y = rem / 24, x = rem % 24;
    float g0 = t * (1.f / 3.f), g1 = y * (1.f / 7.f), g2 = x * (1.f / 23.f);
    const float* wr = pe_w + c * 6;
    g_pe[p * DD + c] = pe_b[c] + wr[0] * g0 + wr[1] * g1 + wr[2] * g2
        + wr[3] * (1.f - g0) + wr[4] * (1.f - g1) + wr[5] * (1.f - g2);
}

__global__ void __launch_bounds__(256) k_winln(const float* __restrict__ inp,
                                               const float* __restrict__ gam,
                                               const float* __restrict__ bet) {
    int m = (blockIdx.x * 256 + threadIdx.x) >> 5;
    int lane = threadIdx.x & 31;
    int wiB = m / NTOK, p = m % NTOK;
    int wi = wiB / BATCH, bb = wiB % BATCH;
    int t = p / 192, rem = p % 192;
    int f = 2 * wi + t;
    const float* src = inp + ((size_t)(bb * 16 + f) * 192 + rem) * DD;
    const float* pe = g_pe + p * DD;
    float x[8], s = 0.f, sq = 0.f;
#pragma unroll
    for (int i = 0; i < 8; i++) {
        int c = lane + i * 32;
        x[i] = src[c] + pe[c];
        s += x[i];
        sq += x[i] * x[i];
    }
#pragma unroll
    for (int o = 16; o > 0; o >>= 1) {
        s += __shfl_xor_sync(0xffffffffu, s, o);
        sq += __shfl_xor_sync(0xffffffffu, sq, o);
    }
    float mean = s * (1.f / 256.f);
    float var = sq * (1.f / 256.f) - mean * mean;
    float rs = rsqrtf(var + 1e-5f);
#pragma unroll
    for (int i = 0; i < 8; i++) {
        int c = lane + i * 32;
        float y = (x[i] - mean) * rs * gam[c] + bet[c];
        __nv_bfloat16 h = __float2bfloat16(y);
        g_x0h[(size_t)m * DD + c] = h;
        g_x0l[(size_t)m * DD + c] = __float2bfloat16(y - __bfloat162float(h));
    }
}

__global__ void __launch_bounds__(256) k_ln2(const float* __restrict__ src,
                                             __nv_bfloat16* __restrict__ dsth,
                                             __nv_bfloat16* __restrict__ dstl,
                                             const float* __restrict__ gam,
                                             const float* __restrict__ bet) {
    int m = (blockIdx.x * 256 + threadIdx.x) >> 5;
    int lane = threadIdx.x & 31;
    const float* sp = src + (size_t)m * DD;
    float x[8], s = 0.f, sq = 0.f;
#pragma unroll
    for (int i = 0; i < 8; i++) {
        x[i] = sp[lane + i * 32];
        s += x[i];
        sq += x[i] * x[i];
    }
#pragma unroll
    for (int o = 16; o > 0; o >>= 1) {
        s += __shfl_xor_sync(0xffffffffu, s, o);
        sq += __shfl_xor_sync(0xffffffffu, sq, o);
    }
    float mean = s * (1.f / 256.f);
    float var = sq * (1.f / 256.f) - mean * mean;
    float rs = rsqrtf(var + 1e-5f);
#pragma unroll
    for (int i = 0; i < 8; i++) {
        int c = lane + i * 32;
        float y = (x[i] - mean) * rs * gam[c] + bet[c];
        __nv_bfloat16 h = __float2bfloat16(y);
        dsth[(size_t)m * DD + c] = h;
        dstl[(size_t)m * DD + c] = __float2bfloat16(y - __bfloat162float(h));
    }
}

// split weights: w1, w2, wv, wg, wf1, wf2 = 524288 elements
__global__ void k_splitall(const float* __restrict__ w1, const float* __restrict__ w2,
                           const float* __restrict__ wv, const float* __restrict__ wg,
                           const float* __restrict__ wf1, const float* __restrict__ wf2) {
    int idx = blockIdx.x * 256 + threadIdx.x;
    if (idx >= 524288) return;
    const float* src;
    __nv_bfloat16 *h, *l;
    int j;
    if (idx < 65536)       { j = idx;          src = w1;  h = g_w1h;  l = g_w1l; }
    else if (idx < 131072) { j = idx - 65536;  src = w2;  h = g_w2h;  l = g_w2l; }
    else if (idx < 196608) { j = idx - 131072; src = wv;  h = g_wvh;  l = g_wvl; }
    else if (idx < 393216) { j = idx - 196608; src = wg;  h = g_wgh;  l = g_wgl; }
    else if (idx < 458752) { j = idx - 393216; src = wf1; h = g_wf1h; l = g_wf1l; }
    else                   { j = idx - 458752; src = wf2; h = g_wf2h; l = g_wf2l; }
    float x = src[j];
    __nv_bfloat16 hh = __float2bfloat16(x);
    h[j] = hh;
    l[j] = __float2bfloat16(x - __bfloat162float(hh));
}

// ---------------- generic 3-stage split-bf16 mma GEMM ----------------
#define ROW3 144
#define AMAT 18432
#define STG3 36864
#define MM_SMEM 110592

template <bool RELU, bool SPLIT, bool MBOUND>
__global__ void __launch_bounds__(256, 2) k_mma(
    const __nv_bfloat16* __restrict__ Ah, const __nv_bfloat16* __restrict__ Al,
    const __nv_bfloat16* __restrict__ Wh, const __nv_bfloat16* __restrict__ Wl,
    const float* __restrict__ bias, float* __restrict__ C,
    __nv_bfloat16* __restrict__ Ch, __nv_bfloat16* __restrict__ Cl,
    int M, int N) {
    extern __shared__ char sm[];
    int tid = threadIdx.x, lane = tid & 31, wid = tid >> 5;
    int n0 = blockIdx.x * 128, m0 = blockIdx.y * 128;
    int mw = wid & 3, nw = wid >> 2;
    uint32_t sb = smem_u32(sm);

    float acc[2][8][4];
#pragma unroll
    for (int i = 0; i < 2; i++)
#pragma unroll
        for (int j = 0; j < 8; j++)
#pragma unroll
            for (int k = 0; k < 4; k++) acc[i][j][k] = 0.f;

    auto cpStage = [&](int ch, int buf) {
        int k0 = ch * 32;
        uint32_t st = sb + (uint32_t)buf * STG3;
#pragma unroll
        for (int i = 0; i < 8; i++) {
            int idx = tid + i * 256;
            int mat = idx >> 10;
            int j = idx & 1023;
            int row = j >> 3, part = j & 7;
            uint32_t off = (mat ? AMAT : 0) + (uint32_t)row * ROW3
                         + (part & 3) * 16 + (part >> 2) * 64;
            int kk0 = k0 + (part & 3) * 8;
            if (mat == 0) {
                const __nv_bfloat16* g =
                    ((part < 4) ? Ah : Al) + (size_t)(m0 + row) * 256 + kk0;
                cp16(st + off, g);
            } else {
                const __nv_bfloat16* g =
                    ((part < 4) ? Wh : Wl) + (size_t)(n0 + row) * 256 + kk0;
                cp16(st + off, g);
            }
        }
    };

    cpStage(0, 0); cp_commit();
    cpStage(1, 1); cp_commit();

#pragma unroll
    for (int ch = 0; ch < 8; ch++) {
        if (ch < 7) cp_wait<1>(); else cp_wait<0>();
        __syncthreads();
        if (ch < 6) { cpStage(ch + 2, (ch + 2) % 3); cp_commit(); }
        uint32_t st = sb + (uint32_t)(ch % 3) * STG3;
#pragma unroll
        for (int ks = 0; ks < 2; ks++) {
            int k = ks * 16;
            uint32_t koff = (uint32_t)(k + (lane >> 4) * 8) * 2;
            uint32_t ah[2][4], al[2][4];
#pragma unroll
            for (int mt = 0; mt < 2; mt++) {
                uint32_t addr = st
                    + (uint32_t)(mw * 32 + mt * 16 + (lane & 15)) * ROW3 + koff;
                ldsm4(ah[mt], addr);
                ldsm4(al[mt], addr + 64);
            }
#pragma unroll
            for (int p = 0; p < 4; p++) {
                uint32_t ba = st + AMAT
                    + (uint32_t)(nw * 64 + p * 16 + (lane & 15)) * ROW3 + koff;
                uint32_t bh[4], bl[4];
                ldsm4(bh, ba);
                ldsm4(bl, ba + 64);
                mma16816(acc[0][2 * p],     ah[0], bh[0], bh[2]);
                mma16816(acc[0][2 * p + 1], ah[0], bh[1], bh[3]);
                mma16816(acc[1][2 * p],     ah[1], bh[0], bh[2]);
                mma16816(acc[1][2 * p + 1], ah[1], bh[1], bh[3]);
                mma16816(acc[0][2 * p],     ah[0], bl[0], bl[2]);
                mma16816(acc[0][2 * p + 1], ah[0], bl[1], bl[3]);
                mma16816(acc[1][2 * p],     ah[1], bl[0], bl[2]);
                mma16816(acc[1][2 * p + 1], ah[1], bl[1], bl[3]);
                mma16816(acc[0][2 * p],     al[0], bh[0], bh[2]);
                mma16816(acc[0][2 * p + 1], al[0], bh[1], bh[3]);
                mma16816(acc[1][2 * p],     al[1], bh[0], bh[2]);
                mma16816(acc[1][2 * p + 1], al[1], bh[1], bh[3]);
            }
        }
    }

#pragma unroll
    for (int nt = 0; nt < 8; nt++) {
        int col = n0 + nw * 64 + nt * 8 + (lane & 3) * 2;
        float bx = bias[col], by = bias[col + 1];
#pragma unroll
        for (int mt = 0; mt < 2; mt++) {
            int row = m0 + mw * 32 + mt * 16 + (lane >> 2);
            float* a = acc[mt][nt];
            float2 o0 = make_float2(a[0] + bx, a[1] + by);
            float2 o1 = make_float2(a[2] + bx, a[3] + by);
            if (RELU) {
                o0.x = fmaxf(o0.x, 0.f); o0.y = fmaxf(o0.y, 0.f);
                o1.x = fmaxf(o1.x, 0.f); o1.y = fmaxf(o1.y, 0.f);
            }
            bool w0 = !MBOUND || row < M;
            bool w1 = !MBOUND || row + 8 < M;
            if (SPLIT) {
                __nv_bfloat162 h0 = __floats2bfloat162_rn(o0.x, o0.y);
                __nv_bfloat162 h1 = __floats2bfloat162_rn(o1.x, o1.y);
                uint32_t L0 = bfpack(o0.x - __bfloat162float(h0.x),
                                     o0.y - __bfloat162float(h0.y));
                uint32_t L1 = bfpack(o1.x - __bfloat162float(h1.x),
                                     o1.y - __bfloat162float(h1.y));
                if (w0) {
                    *reinterpret_cast<uint32_t*>(Ch + (size_t)row * N + col) =
                        *reinterpret_cast<uint32_t*>(&h0);
                    *reinterpret_cast<uint32_t*>(Cl + (size_t)row * N + col) = L0;
                }
                if (w1) {
                    *reinterpret_cast<uint32_t*>(Ch + (size_t)(row + 8) * N + col) =
                        *reinterpret_cast<uint32_t*>(&h1);
                    *reinterpret_cast<uint32_t*>(Cl + (size_t)(row + 8) * N + col) = L1;
                }
            } else {
                if (w0) *reinterpret_cast<float2*>(C + (size_t)row * N + col) = o0;
                if (w1) *reinterpret_cast<float2*>(C + (size_t)(row + 8) * N + col) = o1;
            }
        }
    }
}

// ---------------- fused FC2 + LayerNorm GEMM ----------------
#define F_AROWS 64
#define F_BOFF 9216
#define F_STG 46080
#define F_GB 92160
#define F_RED 95232
#define F_SMEM 96256

__global__ void __launch_bounds__(256, 2) k_fc2ln(
    const __nv_bfloat16* __restrict__ Ah, const __nv_bfloat16* __restrict__ Al,
    const __nv_bfloat16* __restrict__ Wh, const __nv_bfloat16* __restrict__ Wl,
    const float* __restrict__ bias, const float* __restrict__ gam,
    const float* __restrict__ bet,
    __nv_bfloat16* __restrict__ Ch, __nv_bfloat16* __restrict__ Cl) {
    extern __shared__ char sm[];
    int tid = threadIdx.x, lane = tid & 31, wid = tid >> 5;
    int m0 = blockIdx.x * F_AROWS;
    int mw = wid & 3, nw = wid >> 2;
    uint32_t sb = smem_u32(sm);
    float* gb = (float*)(sm + F_GB);
    float2* red = (float2*)(sm + F_RED);

    {
        int c = tid;
        gb[c] = bias[c];
        gb[256 + c] = gam[c];
        gb[512 + c] = bet[c];
    }

    float acc[16][4];
#pragma unroll
    for (int j = 0; j < 16; j++)
#pragma unroll
        for (int k = 0; k < 4; k++) acc[j][k] = 0.f;

    auto cpStage = [&](int ch, int buf) {
        int k0 = ch * 32;
        uint32_t st = sb + (uint32_t)buf * F_STG;
#pragma unroll
        for (int i = 0; i < 10; i++) {
            int idx = tid + i * 256;
            if (idx < 512) {
                int row = idx >> 3, part = idx & 7;
                uint32_t off = (uint32_t)row * ROW3 + (part & 3) * 16 + (part >> 2) * 64;
                const __nv_bfloat16* g =
                    ((part < 4) ? Ah : Al) + (size_t)(m0 + row) * 256 + k0 + (part & 3) * 8;
                cp16(st + off, g);
            } else {
                int j = idx - 512;
                int row = j >> 3, part = j & 7;
                uint32_t off = F_BOFF + (uint32_t)row * ROW3 + (part & 3) * 16 + (part >> 2) * 64;
                const __nv_bfloat16* g =
                    ((part < 4) ? Wh : Wl) + (size_t)row * 256 + k0 + (part & 3) * 8;
                cp16(st + off, g);
            }
        }
    };

    cpStage(0, 0); cp_commit();

#pragma unroll
    for (int ch = 0; ch < 8; ch++) {
        cp_wait<0>();
        __syncthreads();
        if (ch < 7) { cpStage(ch + 1, (ch + 1) & 1); cp_commit(); }
        uint32_t st = sb + (uint32_t)(ch & 1) * F_STG;
#pragma unroll
        for (int ks = 0; ks < 2; ks++) {
            uint32_t koff = (uint32_t)(ks * 16 + (lane >> 4) * 8) * 2;
            uint32_t ah[4], al[4];
            uint32_t aaddr = st + (uint32_t)(mw * 16 + (lane & 15)) * ROW3 + koff;
            ldsm4(ah, aaddr);
            ldsm4(al, aaddr + 64);
#pragma unroll
            for (int p = 0; p < 8; p++) {
                uint32_t ba = st + F_BOFF
                    + (uint32_t)(nw * 128 + p * 16 + (lane & 15)) * ROW3 + koff;
                uint32_t bh[4], bl[4];
                ldsm4(bh, ba);
                ldsm4(bl, ba + 64);
                mma16816(acc[2 * p],     ah, bh[0], bh[2]);
                mma16816(acc[2 * p + 1], ah, bh[1], bh[3]);
                mma16816(acc[2 * p],     ah, bl[0], bl[2]);
                mma16816(acc[2 * p + 1], ah, bl[1], bl[3]);
                mma16816(acc[2 * p],     al, bh[0], bh[2]);
                mma16816(acc[2 * p + 1], al, bh[1], bh[3]);
            }
        }
    }

    float s0 = 0.f, q0 = 0.f, s1 = 0.f, q1 = 0.f;
#pragma unroll
    for (int nt = 0; nt < 16; nt++) {
        int col = nw * 128 + nt * 8 + (lane & 3) * 2;
        float bx = gb[col], by = gb[col + 1];
        acc[nt][0] += bx; acc[nt][1] += by;
        acc[nt][2] += bx; acc[nt][3] += by;
        s0 += acc[nt][0] + acc[nt][1];
        q0 += acc[nt][0] * acc[nt][0] + acc[nt][1] * acc[nt][1];
        s1 += acc[nt][2] + acc[nt][3];
        q1 += acc[nt][2] * acc[nt][2] + acc[nt][3] * acc[nt][3];
    }
#pragma unroll
    for (int o = 1; o <= 2; o <<= 1) {
        s0 += __shfl_xor_sync(0xffffffffu, s0, o);
        q0 += __shfl_xor_sync(0xffffffffu, q0, o);
        s1 += __shfl_xor_sync(0xffffffffu, s1, o);
        q1 += __shfl_xor_sync(0xffffffffu, q1, o);
    }
    int rloc = mw * 16 + (lane >> 2);
    if ((lane & 3) == 0) {
        red[rloc * 2 + nw] = make_float2(s0, q0);
        red[(rloc + 8) * 2 + nw] = make_float2(s1, q1);
    }
    __syncthreads();
    float2 a0 = red[rloc * 2], b0f = red[rloc * 2 + 1];
    float ss = a0.x + b0f.x, qq = a0.y + b0f.y;
    float mean0 = ss * (1.f / 256.f);
    float rs0 = rsqrtf(qq * (1.f / 256.f) - mean0 * mean0 + 1e-5f);
    float2 a1 = red[(rloc + 8) * 2], b1f = red[(rloc + 8) * 2 + 1];
    float ss1 = a1.x + b1f.x, qq1 = a1.y + b1f.y;
    float mean1 = ss1 * (1.f / 256.f);
    float rs1 = rsqrtf(qq1 * (1.f / 256.f) - mean1 * mean1 + 1e-5f);

    int row0 = m0 + rloc, row1 = row0 + 8;
#pragma unroll
    for (int nt = 0; nt < 16; nt++) {
        int col = nw * 128 + nt * 8 + (lane & 3) * 2;
        float gx = gb[256 + col], gy = gb[256 + col + 1];
        float ex = gb[512 + col], ey = gb[512 + col + 1];
        float y00 = (acc[nt][0] - mean0) * rs0 * gx + ex;
        float y01 = (acc[nt][1] - mean0) * rs0 * gy + ey;
        float y10 = (acc[nt][2] - mean1) * rs1 * gx + ex;
        float y11 = (acc[nt][3] - mean1) * rs1 * gy + ey;
        __nv_bfloat162 h0 = __floats2bfloat162_rn(y00, y01);
        __nv_bfloat162 h1 = __floats2bfloat162_rn(y10, y11);
        uint32_t L0 = bfpack(y00 - __bfloat162float(h0.x), y01 - __bfloat162float(h0.y));
        uint32_t L1 = bfpack(y10 - __bfloat162float(h1.x), y11 - __bfloat162float(h1.y));
        *reinterpret_cast<uint32_t*>(Ch + (size_t)row0 * 256 + col) =
            *reinterpret_cast<uint32_t*>(&h0);
        *reinterpret_cast<uint32_t*>(Cl + (size_t)row0 * 256 + col) = L0;
        *reinterpret_cast<uint32_t*>(Ch + (size_t)row1 * 256 + col) =
            *reinterpret_cast<uint32_t*>(&h1);
        *reinterpret_cast<uint32_t*>(Cl + (size_t)row1 * 256 + col) = L1;
    }
}

// k_small: q = LN_ns(slots)@q_w^T + q_b ; qk = q @ k_w ; qkb = q . k_b ;
//          hg = slots@gru_wh^T + gru_bh   (22 rows)
__global__ void k_small(const float* __restrict__ slots,
                        const float* __restrict__ nsg, const float* __restrict__ nsb,
                        const float* __restrict__ qw, const float* __restrict__ qb,
                        const float* __restrict__ kw, const float* __restrict__ kb,
                        const float* __restrict__ wh, const float* __restrict__ bh) {
    __shared__ float red[32];
    __shared__ float sraw[DD];
    __shared__ float sln[DD];
    __shared__ float sq[DD];
    int i = blockIdx.x, c = threadIdx.x;
    float x = slots[i * DD + c];
    sraw[c] = x;
    float mean = blockSum(x, red) * (1.f / 256.f);
    float d0 = x - mean;
    float var = blockSum(d0 * d0, red) * (1.f / 256.f);
    sln[c] = d0 * rsqrtf(var + 1e-5f) * nsg[c] + nsb[c];
    __syncthreads();
    float acc = qb[c];
    const float* wr = qw + (size_t)c * 256;
#pragma unroll 8
    for (int k = 0; k < 256; k++) acc += sln[k] * wr[k];
    sq[c] = acc;                       // q[i,c]
    float qkb = blockSum(acc * kb[c], red);  // also syncs sq
    if (c == 0) g_qkb[i] = qkb;
    // qk[i,c] = sum_d q[i,d] * k_w[d, c]
    float qk = 0.f;
#pragma unroll 8
    for (int d = 0; d < 256; d++) qk += sq[d] * kw[(size_t)d * 256 + c];
    g_qs[i * DD + c] = qk;
#pragma unroll
    for (int j = 0; j < 3; j++) {
        int u = j * 256 + c;
        float a = bh[u];
        const float* hr = wh + (size_t)u * 256;
#pragma unroll 8
        for (int k = 0; k < 256; k++) a += sraw[k] * hr[k];
        g_hg[i * 768 + u] = a;
    }
}

__device__ __forceinline__ void softmax_store2(const unsigned long long* d,
                                               const float* __restrict__ qkbs,
                                               float* __restrict__ gdst,
                                               float* __restrict__ sdst, int j) {
    float v[SS];
#pragma unroll
    for (int ip = 0; ip < 11; ip++) {
        float a, b;
        upk(d[ip], a, b);
        v[2 * ip] = (a + qkbs[2 * ip]) * 0.0625f;
        v[2 * ip + 1] = (b + qkbs[2 * ip + 1]) * 0.0625f;
    }
    float mx = v[0];
#pragma unroll
    for (int i = 1; i < SS; i++) mx = fmaxf(mx, v[i]);
    float s = 0.f;
#pragma unroll
    for (int i = 0; i < SS; i++) { v[i] = __expf(v[i] - mx); s += v[i]; }
    float inv = 1.f / s;
#pragma unroll
    for (int i = 0; i < SS; i++) {
        float val = v[i] * inv + 1e-8f;
        gdst[i * NTOK + j] = val;
        sdst[i * NTOK + j] = val;
    }
}

// ---------------- fused dots+softmax+renorm+mid (K/V-free) ----------------
// dots = qk @ x2^T + qkb ; softmax-over-slots + EPS -> out_attn & smem
// mid = attn_norm @ x2 -> split bf16 (rows bB*22+i of g_x0)
// smem: at f[22*768] @0 (67584) | at2 ull[11*96] @67584 (8448)
//       red @76032 (128) | sinv @76160 (88) | qkbs @76256 (88)
// q2 aliases [0,22528), ks aliases [22528,47104) during phase 1.
#define AT_SMEM 76416

__global__ void __launch_bounds__(256, 2) k_attup(
    float* __restrict__ out_attn,
    const __nv_bfloat16* __restrict__ x2h, const __nv_bfloat16* __restrict__ x2l,
    __nv_bfloat16* __restrict__ midh, __nv_bfloat16* __restrict__ midl) {
    extern __shared__ char sm[];
    unsigned long long* q2 = (unsigned long long*)sm;
    float* ks = (float*)(sm + 22528);
    float* at = (float*)sm;
    unsigned long long* at2 = (unsigned long long*)(sm + 67584);
    float* red = (float*)(sm + 76032);
    float* sinv = (float*)(sm + 76160);
    float* qkbs = (float*)(sm + 76256);
    int bB = blockIdx.x, tid = threadIdx.x;

    for (int idx = tid; idx < 11 * 256; idx += 256) {
        int ip = idx >> 8, k = idx & 255;
        q2[idx] = pk(g_qs[(2 * ip) * DD + k], g_qs[(2 * ip + 1) * DD + k]);
    }
    if (tid < SS) qkbs[tid] = g_qkb[tid];

    unsigned long long d0[11], d1[11], d2[11];
#pragma unroll
    for (int ip = 0; ip < 11; ip++) { d0[ip] = 0ULL; d1[ip] = 0ULL; d2[ip] = 0ULL; }
    size_t rowbase = (size_t)bB * NTOK;
    for (int kc = 0; kc < 256; kc += 8) {
        __syncthreads();
#pragma unroll
        for (int rr = 0; rr < 3; rr++) {
            int r = tid + rr * 256;
            uint4 H = *(const uint4*)(x2h + (rowbase + r) * 256 + kc);
            uint4 L = *(const uint4*)(x2l + (rowbase + r) * 256 + kc);
            float o[8];
            rec8(H, L, o);
#pragma unroll
            for (int w = 0; w < 8; w++) ks[w * 768 + r] = o[w];
        }
        __syncthreads();
#pragma unroll
        for (int kl = 0; kl < 8; kl++) {
            float kv0 = ks[kl * 768 + tid];
            float kv1 = ks[kl * 768 + tid + 256];
            float kv2 = ks[kl * 768 + tid + 512];
            unsigned long long s0 = pk(kv0, kv0), s1 = pk(kv1, kv1), s2 = pk(kv2, kv2);
#pragma unroll
            for (int ip = 0; ip < 11; ip++) {
                unsigned long long qv = q2[ip * 256 + kc + kl];
                d0[ip] = fma2(qv, s0, d0[ip]);
                d1[ip] = fma2(qv, s1, d1[ip]);
                d2[ip] = fma2(qv, s2, d2[ip]);
            }
        }
    }
    __syncthreads();  // all q2/ks reads done before at overwrite
    int wi = bB / BATCH, bb = bB % BATCH;
    float* gdst = out_attn + ((size_t)(bb * NWIN + wi)) * SS * NTOK;
    softmax_store2(d0, qkbs, gdst, at, tid);
    softmax_store2(d1, qkbs, gdst, at, tid + 256);
    softmax_store2(d2, qkbs, gdst, at, tid + 512);
    __syncthreads();

    for (int i = 0; i < SS; i++) {
        float p = at[i * 768 + tid] + at[i * 768 + tid + 256] + at[i * 768 + tid + 512];
        float s = blockSum(p, red);
        if (tid == 0) sinv[i] = 1.f / s;
    }
    __syncthreads();

    // mid = attn @ x2 (then renorm scale); channel = tid
    unsigned long long acc[11];
#pragma unroll
    for (int ip = 0; ip < 11; ip++) acc[ip] = 0ULL;
    for (int j0 = 0; j0 < NTOK; j0 += 96) {
        __syncthreads();
        for (int idx = tid; idx < 11 * 96; idx += 256) {
            int ip = idx / 96, jj = idx % 96;
            at2[ip * 96 + jj] = pk(at[(2 * ip) * 768 + j0 + jj],
                                   at[(2 * ip + 1) * 768 + j0 + jj]);
        }
        __syncthreads();
        const __nv_bfloat16* vph = x2h + (rowbase + j0) * 256 + tid;
        const __nv_bfloat16* vpl = x2l + (rowbase + j0) * 256 + tid;
#pragma unroll 4
        for (int jj = 0; jj < 96; jj++) {
            float v = __bfloat162float(vph[(size_t)jj * 256])
                    + __bfloat162float(vpl[(size_t)jj * 256]);
            unsigned long long sv = pk(v, v);
#pragma unroll
            for (int ip = 0; ip < 11; ip++)
                acc[ip] = fma2(at2[ip * 96 + jj], sv, acc[ip]);
        }
    }
#pragma unroll
    for (int ip = 0; ip < 11; ip++) {
        float u0, u1;
        upk(acc[ip], u0, u1);
        u0 *= sinv[2 * ip];
        u1 *= sinv[2 * ip + 1];
        __nv_bfloat16 h0 = __float2bfloat16(u0);
        __nv_bfloat16 h1 = __float2bfloat16(u1);
        size_t r0 = ((size_t)bB * SS + 2 * ip) * DD + tid;
        size_t r1 = ((size_t)bB * SS + 2 * ip + 1) * DD + tid;
        midh[r0] = h0; midl[r0] = __float2bfloat16(u0 - __bfloat162float(h0));
        midh[r1] = h1; midl[r1] = __float2bfloat16(u1 - __bfloat162float(h1));
    }
}

__global__ void k_gate(const float* __restrict__ slots) {
    int m = blockIdx.x, c = threadIdx.x;
    int Bi = m / NAC, i = m % NAC;
    size_t row = (size_t)Bi * SS + i;
    float ir = g_xg[row * 768 + c];
    float iz = g_xg[row * 768 + 256 + c];
    float in_ = g_xg[row * 768 + 512 + c];
    float hr = g_hg[i * 768 + c];
    float hz = g_hg[i * 768 + 256 + c];
    float hn = g_hg[i * 768 + 512 + c];
    float h = slots[i * DD + c];
    float r = 1.f / (1.f + __expf(-(ir + hr)));
    float z = 1.f / (1.f + __expf(-(iz + hz)));
    float n = tanhf(in_ + r * hn);
    g_so[(size_t)m * DD + c] = (1.f - z) * n + z * h;
}

__global__ void k_final(float* __restrict__ out) {
    int m = blockIdx.x, c = threadIdx.x;
    int Bi = m / NAC, sl = m % NAC;
    int wi = Bi / BATCH, bb = Bi % BATCH;
    out[(((size_t)bb * NWIN + wi) * NAC + sl) * DD + c] =
        g_so[(size_t)m * DD + c] + g_t3[(size_t)m * DD + c];
}

extern "C" void kernel_launch(void* const* d_in, const int* in_sizes, int n_in,
                              void* d_out, int out_size) {
    const float* inputs = (const float*)d_in[0];
    const float* slots  = (const float*)d_in[1];
    const float* pe_w   = (const float*)d_in[2];
    const float* pe_b   = (const float*)d_in[3];
    const float* LN_g   = (const float*)d_in[4];
    const float* LN_b   = (const float*)d_in[5];
    const float* ni_g   = (const float*)d_in[6];
    const float* ni_b   = (const float*)d_in[7];
    const float* ns_g   = (const float*)d_in[8];
    const float* ns_b   = (const float*)d_in[9];
    const float* npf_g  = (const float*)d_in[10];
    const float* npf_b  = (const float*)d_in[11];
    const float* FC1_w  = (const float*)d_in[12];
    const float* FC1_b  = (const float*)d_in[13];
    const float* FC2_w  = (const float*)d_in[14];
    const float* FC2_b  = (const float*)d_in[15];
    const float* q_w    = (const float*)d_in[16];
    const float* q_b    = (const float*)d_in[17];
    const float* k_w    = (const float*)d_in[18];
    const float* k_b    = (const float*)d_in[19];
    const float* v_w    = (const float*)d_in[20];
    const float* v_b    = (const float*)d_in[21];
    const float* ff1_w  = (const float*)d_in[22];
    const float* ff1_b  = (const float*)d_in[23];
    const float* ff2_w  = (const float*)d_in[24];
    const float* ff2_b  = (const float*)d_in[25];
    const float* gru_wi = (const float*)d_in[26];
    const float* gru_wh = (const float*)d_in[27];
    const float* gru_bi = (const float*)d_in[28];
    const float* gru_bh = (const float*)d_in[29];

    float* out = (float*)d_out;
    float* out_attn = out + SLOTS_OUT_ELEMS;

    float *xg_, *so_, *t3_;
    cudaGetSymbolAddress((void**)&xg_, g_xg);
    cudaGetSymbolAddress((void**)&so_, g_so);
    cudaGetSymbolAddress((void**)&t3_, g_t3);

    __nv_bfloat16 *w1h, *w1l, *w2h, *w2l, *wvh, *wvl;
    __nv_bfloat16 *wgh, *wgl, *wf1h, *wf1l, *wf2h, *wf2l;
    __nv_bfloat16 *x0h, *x0l, *x1h, *x1l, *x2h, *x2l;
    __nv_bfloat16 *uh, *ul, *snh, *snl, *t2h, *t2l;
    cudaGetSymbolAddress((void**)&w1h, g_w1h); cudaGetSymbolAddress((void**)&w1l, g_w1l);
    cudaGetSymbolAddress((void**)&w2h, g_w2h); cudaGetSymbolAddress((void**)&w2l, g_w2l);
    cudaGetSymbolAddress((void**)&wvh, g_wvh); cudaGetSymbolAddress((void**)&wvl, g_wvl);
    cudaGetSymbolAddress((void**)&wgh, g_wgh); cudaGetSymbolAddress((void**)&wgl, g_wgl);
    cudaGetSymbolAddress((void**)&wf1h, g_wf1h); cudaGetSymbolAddress((void**)&wf1l, g_wf1l);
    cudaGetSymbolAddress((void**)&wf2h, g_wf2h); cudaGetSymbolAddress((void**)&wf2l, g_wf2l);
    cudaGetSymbolAddress((void**)&x0h, g_x0h); cudaGetSymbolAddress((void**)&x0l, g_x0l);
    cudaGetSymbolAddress((void**)&x1h, g_x1h); cudaGetSymbolAddress((void**)&x1l, g_x1l);
    cudaGetSymbolAddress((void**)&x2h, g_x2h); cudaGetSymbolAddress((void**)&x2l, g_x2l);
    cudaGetSymbolAddress((void**)&uh, g_updh); cudaGetSymbolAddress((void**)&ul, g_updl);
    cudaGetSymbolAddress((void**)&snh, g_solnh); cudaGetSymbolAddress((void**)&snl, g_solnl);
    cudaGetSymbolAddress((void**)&t2h, g_t2h); cudaGetSymbolAddress((void**)&t2l, g_t2l);

    cudaFuncSetAttribute((const void*)k_mma<true, true, false>,
                         cudaFuncAttributeMaxDynamicSharedMemorySize, MM_SMEM);
    cudaFuncSetAttribute((const void*)k_mma<false, true, true>,
                         cudaFuncAttributeMaxDynamicSharedMemorySize, MM_SMEM);
    cudaFuncSetAttribute((const void*)k_mma<false, false, true>,
                         cudaFuncAttributeMaxDynamicSharedMemorySize, MM_SMEM);
    cudaFuncSetAttribute((const void*)k_mma<false, false, false>,
                         cudaFuncAttributeMaxDynamicSharedMemorySize, MM_SMEM);
    cudaFuncSetAttribute((const void*)k_fc2ln,
                         cudaFuncAttributeMaxDynamicSharedMemorySize, F_SMEM);
    cudaFuncSetAttribute((const void*)k_attup,
                         cudaFuncAttributeMaxDynamicSharedMemorySize, AT_SMEM);

    k_splitall<<<2048, 256>>>(FC1_w, FC2_w, v_w, gru_wi, ff1_w, ff2_w);

    k_pe<<<NTOK, 256>>>(pe_w, pe_b);
    k_winln<<<MBIG / 8, 256>>>(inputs, LN_g, LN_b);

    // FC1 (relu, split out)
    k_mma<true, true, false><<<dim3(2, MBIG / 128), 256, MM_SMEM>>>(
        x0h, x0l, w1h, w1l, FC1_b, nullptr, x1h, x1l, MBIG, 256);

    // FC2 + norm_input LN fused (split out)
    k_fc2ln<<<MBIG / 64, 256, F_SMEM>>>(x1h, x1l, w2h, w2l, FC2_b, ni_g, ni_b,
                                        x2h, x2l);

    // batch-invariant q, qk = q@k_w, qkb, hidden gates
    k_small<<<SS, 256>>>(slots, ns_g, ns_b, q_w, q_b, k_w, k_b, gru_wh, gru_bh);

    // fused dots+softmax+renorm+mid (no K/V GEMM needed!)
    k_attup<<<BWIN, 256, AT_SMEM>>>(out_attn, x2h, x2l, x0h, x0l);

    // upd = mid @ v_w^T + v_b (small GEMM, split out)
    k_mma<false, true, true><<<dim3(2, MGRUPAD / 128), 256, MM_SMEM>>>(
        x0h, x0l, wvh, wvl, v_b, nullptr, uh, ul, MGRU, 256);

    // GRU input gates GEMM
    k_mma<false, false, true><<<dim3(6, MGRUPAD / 128), 256, MM_SMEM>>>(
        uh, ul, wgh, wgl, gru_bi, xg_, nullptr, nullptr, MGRU, 768);

    k_gate<<<MSO, 256>>>(slots);

    k_ln2<<<MSO / 8, 256>>>(so_, snh, snl, npf_g, npf_b);
    k_mma<true, true, false><<<dim3(2, MSO / 128), 256, MM_SMEM>>>(
        snh, snl, wf1h, wf1l, ff1_b, nullptr, t2h, t2l, MSO, 256);
    k_mma<false, false, false><<<dim3(2, MSO / 128), 256, MM_SMEM>>>(
        t2h, t2l, wf2h, wf2l, ff2_b, t3_, nullptr, nullptr, MSO, 256);

    k_final<<<MSO, 256>>>(out);
}

// round 12
// speedup vs baseline: 2.0737x; 1.0586x over previous
#include <cuda_runtime.h>
#include <cuda_bf16.h>
#include <math.h>
#include <stdint.h>

#define DD 256
#define SS 22
#define NAC 20
#define NTOK 768
#define NWIN 7
#define BATCH 32
#define BWIN 224
#define MBIG 172032
#define MGRU 4928
#define MGRUPAD 4992
#define MSO  4480
#define SLOTS_OUT_ELEMS 1146880

__device__ float g_pe[NTOK * DD];
__device__ __nv_bfloat16 g_x0h[MBIG * DD], g_x0l[MBIG * DD];  // winln out; rows 0..4927 reused as mid
__device__ __nv_bfloat16 g_x1h[MBIG * DD], g_x1l[MBIG * DD];  // FC1 out
__device__ __nv_bfloat16 g_x2h[MBIG * DD], g_x2l[MBIG * DD];  // fc2+LN out
__device__ float g_qs[SS * DD];     // qk = q @ k_w
__device__ float g_qkb[SS];
__device__ float g_hg[SS * 768];
__device__ float g_pmid[672 * SS * 256];   // partial mids (3 segs per bB)
__device__ float g_pden[672 * SS];
__device__ float g_xg[MGRU * 768];
__device__ float g_so[MSO * DD];
__device__ __nv_bfloat16 g_solnh[MSO * DD], g_solnl[MSO * DD];
__device__ __nv_bfloat16 g_t2h[MSO * DD], g_t2l[MSO * DD];
__device__ float g_t3[MSO * DD];
__device__ __nv_bfloat16 g_w1h[65536], g_w1l[65536];
__device__ __nv_bfloat16 g_w2h[65536], g_w2l[65536];
__device__ __nv_bfloat16 g_wgvh[196608], g_wgvl[196608];  // gru_wi @ v_w (split)
__device__ float g_bgp[768];                               // fused gru bias
__device__ __nv_bfloat16 g_wf1h[65536], g_wf1l[65536];
__device__ __nv_bfloat16 g_wf2h[65536], g_wf2l[65536];

// ---------------- helpers ----------------
__device__ __forceinline__ uint32_t smem_u32(const void* p) {
    uint32_t a;
    asm("{ .reg .u64 t; cvta.to.shared.u64 t, %1; cvt.u32.u64 %0, t; }" : "=r"(a) : "l"(p));
    return a;
}
__device__ __forceinline__ unsigned long long pk(float x, float y) {
    unsigned long long r;
    asm("mov.b64 %0, {%1,%2};" : "=l"(r) : "f"(x), "f"(y));
    return r;
}
__device__ __forceinline__ void upk(unsigned long long v, float& x, float& y) {
    asm("mov.b64 {%0,%1}, %2;" : "=f"(x), "=f"(y) : "l"(v));
}
__device__ __forceinline__ unsigned long long fma2(unsigned long long a,
                                                   unsigned long long b,
                                                   unsigned long long c) {
    unsigned long long d;
    asm("fma.rn.f32x2 %0, %1, %2, %3;" : "=l"(d) : "l"(a), "l"(b), "l"(c));
    return d;
}
__device__ __forceinline__ uint32_t bfpack(float a, float b) {
    __nv_bfloat162 t = __floats2bfloat162_rn(a, b);
    return *reinterpret_cast<uint32_t*>(&t);
}
__device__ __forceinline__ void ldsm4(uint32_t* r, uint32_t addr) {
    asm volatile("ldmatrix.sync.aligned.m8n8.x4.shared.b16 {%0,%1,%2,%3}, [%4];"
        : "=r"(r[0]), "=r"(r[1]), "=r"(r[2]), "=r"(r[3]) : "r"(addr));
}
__device__ __forceinline__ void mma16816(float* d, const uint32_t* a,
                                         uint32_t b0, uint32_t b1) {
    asm("mma.sync.aligned.m16n8k16.row.col.f32.bf16.bf16.f32 "
        "{%0,%1,%2,%3}, {%4,%5,%6,%7}, {%8,%9}, {%0,%1,%2,%3};"
        : "+f"(d[0]), "+f"(d[1]), "+f"(d[2]), "+f"(d[3])
        : "r"(a[0]), "r"(a[1]), "r"(a[2]), "r"(a[3]), "r"(b0), "r"(b1));
}
__device__ __forceinline__ void cp16(uint32_t sm, const void* g) {
    asm volatile("cp.async.cg.shared.global [%0], [%1], 16;" :: "r"(sm), "l"(g));
}
__device__ __forceinline__ void cp_commit() {
    asm volatile("cp.async.commit_group;" ::: "memory");
}
template <int N>
__device__ __forceinline__ void cp_wait() {
    asm volatile("cp.async.wait_group %0;" :: "n"(N) : "memory");
}
__device__ __forceinline__ void rec8(uint4 H, uint4 L, float* o) {
    const uint32_t hw[4] = {H.x, H.y, H.z, H.w};
    const uint32_t lw[4] = {L.x, L.y, L.z, L.w};
#pragma unroll
    for (int i = 0; i < 4; i++) {
        __nv_bfloat162 hb = *reinterpret_cast<const __nv_bfloat162*>(&hw[i]);
        __nv_bfloat162 lb = *reinterpret_cast<const __nv_bfloat162*>(&lw[i]);
        float2 hf = __bfloat1622float2(hb);
        float2 lf = __bfloat1622float2(lb);
        o[2 * i] = hf.x + lf.x;
        o[2 * i + 1] = hf.y + lf.y;
    }
}

__device__ __forceinline__ float blockSum(float v, float* s) {
    int tid = threadIdx.x;
#pragma unroll
    for (int o = 16; o > 0; o >>= 1) v += __shfl_down_sync(0xffffffffu, v, o);
    if ((tid & 31) == 0) s[tid >> 5] = v;
    __syncthreads();
    float r = (tid < (int)(blockDim.x >> 5)) ? s[tid] : 0.f;
    if (tid < 32) {
#pragma unroll
        for (int o = 4; o > 0; o >>= 1) r += __shfl_down_sync(0xffffffffu, r, o);
    }
    if (tid == 0) s[0] = r;
    __syncthreads();
    r = s[0];
    __syncthreads();
    return r;
}

// ---------------- small kernels ----------------
__global__ void k_pe(const float* __restrict__ pe_w, const float* __restrict__ pe_b) {
    int p = blockIdx.x, c = threadIdx.x;
    int t = p / 192, rem = p % 192, y = rem / 24, x = rem % 24;
    float g0 = t * (1.f / 3.f), g1 = y * (1.f / 7.f), g2 = x * (1.f / 23.f);
    const float* wr = pe_w + c * 6;
    g_pe[p * DD + c] = pe_b[c] + wr[0] * g0 + wr[1] * g1 + wr[2] * g2
        + wr[3] * (1.f - g0) + wr[4] * (1.f - g1) + wr[5] * (1.f - g2);
}

__global__ void __launch_bounds__(256) k_winln(const float* __restrict__ inp,
                                               const float* __restrict__ gam,
                                               const float* __restrict__ bet) {
    int m = (blockIdx.x * 256 + threadIdx.x) >> 5;
    int lane = threadIdx.x & 31;
    int wiB = m / NTOK, p = m % NTOK;
    int wi = wiB / BATCH, bb = wiB % BATCH;
    int t = p / 192, rem = p % 192;
    int f = 2 * wi + t;
    const float* src = inp + ((size_t)(bb * 16 + f) * 192 + rem) * DD;
    const float* pe = g_pe + p * DD;
    float x[8], s = 0.f, sq = 0.f;
#pragma unroll
    for (int i = 0; i < 8; i++) {
        int c = lane + i * 32;
        x[i] = src[c] + pe[c];
        s += x[i];
        sq += x[i] * x[i];
    }
#pragma unroll
    for (int o = 16; o > 0; o >>= 1) {
        s += __shfl_xor_sync(0xffffffffu, s, o);
        sq += __shfl_xor_sync(0xffffffffu, sq, o);
    }
    float mean = s * (1.f / 256.f);
    float var = sq * (1.f / 256.f) - mean * mean;
    float rs = rsqrtf(var + 1e-5f);
#pragma unroll
    for (int i = 0; i < 8; i++) {
        int c = lane + i * 32;
        float y = (x[i] - mean) * rs * gam[c] + bet[c];
        __nv_bfloat16 h = __float2bfloat16(y);
        g_x0h[(size_t)m * DD + c] = h;
        g_x0l[(size_t)m * DD + c] = __float2bfloat16(y - __bfloat162float(h));
    }
}

__global__ void __launch_bounds__(256) k_ln2(const float* __restrict__ src,
                                             __nv_bfloat16* __restrict__ dsth,
                                             __nv_bfloat16* __restrict__ dstl,
                                             const float* __restrict__ gam,
                                             const float* __restrict__ bet) {
    int m = (blockIdx.x * 256 + threadIdx.x) >> 5;
    int lane = threadIdx.x & 31;
    const float* sp = src + (size_t)m * DD;
    float x[8], s = 0.f, sq = 0.f;
#pragma unroll
    for (int i = 0; i < 8; i++) {
        x[i] = sp[lane + i * 32];
        s += x[i];
        sq += x[i] * x[i];
    }
#pragma unroll
    for (int o = 16; o > 0; o >>= 1) {
        s += __shfl_xor_sync(0xffffffffu, s, o);
        sq += __shfl_xor_sync(0xffffffffu, sq, o);
    }
    float mean = s * (1.f / 256.f);
    float var = sq * (1.f / 256.f) - mean * mean;
    float rs = rsqrtf(var + 1e-5f);
#pragma unroll
    for (int i = 0; i < 8; i++) {
        int c = lane + i * 32;
        float y = (x[i] - mean) * rs * gam[c] + bet[c];
        __nv_bfloat16 h = __float2bfloat16(y);
        dsth[(size_t)m * DD + c] = h;
        dstl[(size_t)m * DD + c] = __float2bfloat16(y - __bfloat162float(h));
    }
}

// split weights: w1, w2, wf1, wf2 = 262144 elements
__global__ void k_splitall(const float* __restrict__ w1, const float* __restrict__ w2,
                           const float* __restrict__ wf1, const float* __restrict__ wf2) {
    int idx = blockIdx.x * 256 + threadIdx.x;
    if (idx >= 262144) return;
    const float* src;
    __nv_bfloat16 *h, *l;
    int j;
    if (idx < 65536)       { j = idx;          src = w1;  h = g_w1h;  l = g_w1l; }
    else if (idx < 131072) { j = idx - 65536;  src = w2;  h = g_w2h;  l = g_w2l; }
    else if (idx < 196608) { j = idx - 131072; src = wf1; h = g_wf1h; l = g_wf1l; }
    else                   { j = idx - 196608; src = wf2; h = g_wf2h; l = g_wf2l; }
    float x = src[j];
    __nv_bfloat16 hh = __float2bfloat16(x);
    h[j] = hh;
    l[j] = __float2bfloat16(x - __bfloat162float(hh));
}

// wgv = gru_wi @ v_w (768x256), split bf16; bgp = gru_bi + gru_wi @ v_b
__global__ void k_prep(const float* __restrict__ wg, const float* __restrict__ wv,
                       const float* __restrict__ vb, const float* __restrict__ bg) {
    __shared__ float swg[256];
    __shared__ float red[32];
    int u = blockIdx.x, c = threadIdx.x;
    swg[c] = wg[u * 256 + c];
    __syncthreads();
    float acc = 0.f;
#pragma unroll 8
    for (int d = 0; d < 256; d++) acc += swg[d] * wv[(size_t)d * 256 + c];
    __nv_bfloat16 h = __float2bfloat16(acc);
    g_wgvh[(size_t)u * 256 + c] = h;
    g_wgvl[(size_t)u * 256 + c] = __float2bfloat16(acc - __bfloat162float(h));
    float bp = blockSum(swg[c] * vb[c], red);
    if (c == 0) g_bgp[u] = bg[u] + bp;
}

// ---------------- generic 3-stage split-bf16 mma GEMM ----------------
#define ROW3 144
#define AMAT 18432
#define STG3 36864
#define MM_SMEM 110592

template <bool RELU, bool SPLIT, bool MBOUND>
__global__ void __launch_bounds__(256, 2) k_mma(
    const __nv_bfloat16* __restrict__ Ah, const __nv_bfloat16* __restrict__ Al,
    const __nv_bfloat16* __restrict__ Wh, const __nv_bfloat16* __restrict__ Wl,
    const float* __restrict__ bias, float* __restrict__ C,
    __nv_bfloat16* __restrict__ Ch, __nv_bfloat16* __restrict__ Cl,
    int M, int N) {
    extern __shared__ char sm[];
    int tid = threadIdx.x, lane = tid & 31, wid = tid >> 5;
    int n0 = blockIdx.x * 128, m0 = blockIdx.y * 128;
    int mw = wid & 3, nw = wid >> 2;
    uint32_t sb = smem_u32(sm);

    float acc[2][8][4];
#pragma unroll
    for (int i = 0; i < 2; i++)
#pragma unroll
        for (int j = 0; j < 8; j++)
#pragma unroll
            for (int k = 0; k < 4; k++) acc[i][j][k] = 0.f;

    auto cpStage = [&](int ch, int buf) {
        int k0 = ch * 32;
        uint32_t st = sb + (uint32_t)buf * STG3;
#pragma unroll
        for (int i = 0; i < 8; i++) {
            int idx = tid + i * 256;
            int mat = idx >> 10;
            int j = idx & 1023;
            int row = j >> 3, part = j & 7;
            uint32_t off = (mat ? AMAT : 0) + (uint32_t)row * ROW3
                         + (part & 3) * 16 + (part >> 2) * 64;
            int kk0 = k0 + (part & 3) * 8;
            if (mat == 0) {
                const __nv_bfloat16* g =
                    ((part < 4) ? Ah : Al) + (size_t)(m0 + row) * 256 + kk0;
                cp16(st + off, g);
            } else {
                const __nv_bfloat16* g =
                    ((part < 4) ? Wh : Wl) + (size_t)(n0 + row) * 256 + kk0;
                cp16(st + off, g);
            }
        }
    };

    cpStage(0, 0); cp_commit();
    cpStage(1, 1); cp_commit();

#pragma unroll
    for (int ch = 0; ch < 8; ch++) {
        if (ch < 7) cp_wait<1>(); else cp_wait<0>();
        __syncthreads();
        if (ch < 6) { cpStage(ch + 2, (ch + 2) % 3); cp_commit(); }
        uint32_t st = sb + (uint32_t)(ch % 3) * STG3;
#pragma unroll
        for (int ks = 0; ks < 2; ks++) {
            int k = ks * 16;
            uint32_t koff = (uint32_t)(k + (lane >> 4) * 8) * 2;
            uint32_t ah[2][4], al[2][4];
#pragma unroll
            for (int mt = 0; mt < 2; mt++) {
                uint32_t addr = st
                    + (uint32_t)(mw * 32 + mt * 16 + (lane & 15)) * ROW3 + koff;
                ldsm4(ah[mt], addr);
                ldsm4(al[mt], addr + 64);
            }
#pragma unroll
            for (int p = 0; p < 4; p++) {
                uint32_t ba = st + AMAT
                    + (uint32_t)(nw * 64 + p * 16 + (lane & 15)) * ROW3 + koff;
                uint32_t bh[4], bl[4];
                ldsm4(bh, ba);
                ldsm4(bl, ba + 64);
                mma16816(acc[0][2 * p],     ah[0], bh[0], bh[2]);
                mma16816(acc[0][2 * p + 1], ah[0], bh[1], bh[3]);
                mma16816(acc[1][2 * p],     ah[1], bh[0], bh[2]);
                mma16816(acc[1][2 * p + 1], ah[1], bh[1], bh[3]);
                mma16816(acc[0][2 * p],     ah[0], bl[0], bl[2]);
                mma16816(acc[0][2 * p + 1], ah[0], bl[1], bl[3]);
                mma16816(acc[1][2 * p],     ah[1], bl[0], bl[2]);
                mma16816(acc[1][2 * p + 1], ah[1], bl[1], bl[3]);
                mma16816(acc[0][2 * p],     al[0], bh[0], bh[2]);
                mma16816(acc[0][2 * p + 1], al[0], bh[1], bh[3]);
                mma16816(acc[1][2 * p],     al[1], bh[0], bh[2]);
                mma16816(acc[1][2 * p + 1], al[1], bh[1], bh[3]);
            }
        }
    }

#pragma unroll
    for (int nt = 0; nt < 8; nt++) {
        int col = n0 + nw * 64 + nt * 8 + (lane & 3) * 2;
        float bx = bias[col], by = bias[col + 1];
#pragma unroll
        for (int mt = 0; mt < 2; mt++) {
            int row = m0 + mw * 32 + mt * 16 + (lane >> 2);
            float* a = acc[mt][nt];
            float2 o0 = make_float2(a[0] + bx, a[1] + by);
            float2 o1 = make_float2(a[2] + bx, a[3] + by);
            if (RELU) {
                o0.x = fmaxf(o0.x, 0.f); o0.y = fmaxf(o0.y, 0.f);
                o1.x = fmaxf(o1.x, 0.f); o1.y = fmaxf(o1.y, 0.f);
            }
            bool w0 = !MBOUND || row < M;
            bool w1 = !MBOUND || row + 8 < M;
            if (SPLIT) {
                __nv_bfloat162 h0 = __floats2bfloat162_rn(o0.x, o0.y);
                __nv_bfloat162 h1 = __floats2bfloat162_rn(o1.x, o1.y);
                uint32_t L0 = bfpack(o0.x - __bfloat162float(h0.x),
                                     o0.y - __bfloat162float(h0.y));
                uint32_t L1 = bfpack(o1.x - __bfloat162float(h1.x),
                                     o1.y - __bfloat162float(h1.y));
                if (w0) {
                    *reinterpret_cast<uint32_t*>(Ch + (size_t)row * N + col) =
                        *reinterpret_cast<uint32_t*>(&h0);
                    *reinterpret_cast<uint32_t*>(Cl + (size_t)row * N + col) = L0;
                }
                if (w1) {
                    *reinterpret_cast<uint32_t*>(Ch + (size_t)(row + 8) * N + col) =
                        *reinterpret_cast<uint32_t*>(&h1);
                    *reinterpret_cast<uint32_t*>(Cl + (size_t)(row + 8) * N + col) = L1;
                }
            } else {
                if (w0) *reinterpret_cast<float2*>(C + (size_t)row * N + col) = o0;
                if (w1) *reinterpret_cast<float2*>(C + (size_t)(row + 8) * N + col) = o1;
            }
        }
    }
}

// ---------------- fused FC2 + LayerNorm GEMM ----------------
#define F_AROWS 64
#define F_BOFF 9216
#define F_STG 46080
#define F_GB 92160
#define F_RED 95232
#define F_SMEM 96256

__global__ void __launch_bounds__(256, 2) k_fc2ln(
    const __nv_bfloat16* __restrict__ Ah, const __nv_bfloat16* __restrict__ Al,
    const __nv_bfloat16* __restrict__ Wh, const __nv_bfloat16* __restrict__ Wl,
    const float* __restrict__ bias, const float* __restrict__ gam,
    const float* __restrict__ bet,
    __nv_bfloat16* __restrict__ Ch, __nv_bfloat16* __restrict__ Cl) {
    extern __shared__ char sm[];
    int tid = threadIdx.x, lane = tid & 31, wid = tid >> 5;
    int m0 = blockIdx.x * F_AROWS;
    int mw = wid & 3, nw = wid >> 2;
    uint32_t sb = smem_u32(sm);
    float* gb = (float*)(sm + F_GB);
    float2* red = (float2*)(sm + F_RED);

    {
        int c = tid;
        gb[c] = bias[c];
        gb[256 + c] = gam[c];
        gb[512 + c] = bet[c];
    }

    float acc[16][4];
#pragma unroll
    for (int j = 0; j < 16; j++)
#pragma unroll
        for (int k = 0; k < 4; k++) acc[j][k] = 0.f;

    auto cpStage = [&](int ch, int buf) {
        int k0 = ch * 32;
        uint32_t st = sb + (uint32_t)buf * F_STG;
#pragma unroll
        for (int i = 0; i < 10; i++) {
            int idx = tid + i * 256;
            if (idx < 512) {
                int row = idx >> 3, part = idx & 7;
                uint32_t off = (uint32_t)row * ROW3 + (part & 3) * 16 + (part >> 2) * 64;
                const __nv_bfloat16* g =
                    ((part < 4) ? Ah : Al) + (size_t)(m0 + row) * 256 + k0 + (part & 3) * 8;
                cp16(st + off, g);
            } else {
                int j = idx - 512;
                int row = j >> 3, part = j & 7;
                uint32_t off = F_BOFF + (uint32_t)row * ROW3 + (part & 3) * 16 + (part >> 2) * 64;
                const __nv_bfloat16* g =
                    ((part < 4) ? Wh : Wl) + (size_t)row * 256 + k0 + (part & 3) * 8;
                cp16(st + off, g);
            }
        }
    };

    cpStage(0, 0); cp_commit();

#pragma unroll
    for (int ch = 0; ch < 8; ch++) {
        cp_wait<0>();
        __syncthreads();
        if (ch < 7) { cpStage(ch + 1, (ch + 1) & 1); cp_commit(); }
        uint32_t st = sb + (uint32_t)(ch & 1) * F_STG;
#pragma unroll
        for (int ks = 0; ks < 2; ks++) {
            uint32_t koff = (uint32_t)(ks * 16 + (lane >> 4) * 8) * 2;
            uint32_t ah[4], al[4];
            uint32_t aaddr = st + (uint32_t)(mw * 16 + (lane & 15)) * ROW3 + koff;
            ldsm4(ah, aaddr);
            ldsm4(al, aaddr + 64);
#pragma unroll
            for (int p = 0; p < 8; p++) {
                uint32_t ba = st + F_BOFF
                    + (uint32_t)(nw * 128 + p * 16 + (lane & 15)) * ROW3 + koff;
                uint32_t bh[4], bl[4];
                ldsm4(bh, ba);
                ldsm4(bl, ba + 64);
                mma16816(acc[2 * p],     ah, bh[0], bh[2]);
                mma16816(acc[2 * p + 1], ah, bh[1], bh[3]);
                mma16816(acc[2 * p],     ah, bl[0], bl[2]);
                mma16816(acc[2 * p + 1], ah, bl[1], bl[3]);
                mma16816(acc[2 * p],     al, bh[0], bh[2]);
                mma16816(acc[2 * p + 1], al, bh[1], bh[3]);
            }
        }
    }

    float s0 = 0.f, q0 = 0.f, s1 = 0.f, q1 = 0.f;
#pragma unroll
    for (int nt = 0; nt < 16; nt++) {
        int col = nw * 128 + nt * 8 + (lane & 3) * 2;
        float bx = gb[col], by = gb[col + 1];
        acc[nt][0] += bx; acc[nt][1] += by;
        acc[nt][2] += bx; acc[nt][3] += by;
        s0 += acc[nt][0] + acc[nt][1];
        q0 += acc[nt][0] * acc[nt][0] + acc[nt][1] * acc[nt][1];
        s1 += acc[nt][2] + acc[nt][3];
        q1 += acc[nt][2] * acc[nt][2] + acc[nt][3] * acc[nt][3];
    }
#pragma unroll
    for (int o = 1; o <= 2; o <<= 1) {
        s0 += __shfl_xor_sync(0xffffffffu, s0, o);
        q0 += __shfl_xor_sync(0xffffffffu, q0, o);
        s1 += __shfl_xor_sync(0xffffffffu, s1, o);
        q1 += __shfl_xor_sync(0xffffffffu, q1, o);
    }
    int rloc = mw * 16 + (lane >> 2);
    if ((lane & 3) == 0) {
        red[rloc * 2 + nw] = make_float2(s0, q0);
        red[(rloc + 8) * 2 + nw] = make_float2(s1, q1);
    }
    __syncthreads();
    float2 a0 = red[rloc * 2], b0f = red[rloc * 2 + 1];
    float ss = a0.x + b0f.x, qq = a0.y + b0f.y;
    float mean0 = ss * (1.f / 256.f);
    float rs0 = rsqrtf(qq * (1.f / 256.f) - mean0 * mean0 + 1e-5f);
    float2 a1 = red[(rloc + 8) * 2], b1f = red[(rloc + 8) * 2 + 1];
    float ss1 = a1.x + b1f.x, qq1 = a1.y + b1f.y;
    float mean1 = ss1 * (1.f / 256.f);
    float rs1 = rsqrtf(qq1 * (1.f / 256.f) - mean1 * mean1 + 1e-5f);

    int row0 = m0 + rloc, row1 = row0 + 8;
#pragma unroll
    for (int nt = 0; nt < 16; nt++) {
        int col = nw * 128 + nt * 8 + (lane & 3) * 2;
        float gx = gb[256 + col], gy = gb[256 + col + 1];
        float ex = gb[512 + col], ey = gb[512 + col + 1];
        float y00 = (acc[nt][0] - mean0) * rs0 * gx + ex;
        float y01 = (acc[nt][1] - mean0) * rs0 * gy + ey;
        float y10 = (acc[nt][2] - mean1) * rs1 * gx + ex;
        float y11 = (acc[nt][3] - mean1) * rs1 * gy + ey;
        __nv_bfloat162 h0 = __floats2bfloat162_rn(y00, y01);
        __nv_bfloat162 h1 = __floats2bfloat162_rn(y10, y11);
        uint32_t L0 = bfpack(y00 - __bfloat162float(h0.x), y01 - __bfloat162float(h0.y));
        uint32_t L1 = bfpack(y10 - __bfloat162float(h1.x), y11 - __bfloat162float(h1.y));
        *reinterpret_cast<uint32_t*>(Ch + (size_t)row0 * 256 + col) =
            *reinterpret_cast<uint32_t*>(&h0);
        *reinterpret_cast<uint32_t*>(Cl + (size_t)row0 * 256 + col) = L0;
        *reinterpret_cast<uint32_t*>(Ch + (size_t)row1 * 256 + col) =
            *reinterpret_cast<uint32_t*>(&h1);
        *reinterpret_cast<uint32_t*>(Cl + (size_t)row1 * 256 + col) = L1;
    }
}

// k_small: q = LN_ns(slots)@q_w^T + q_b ; qk = q @ k_w ; qkb = q . k_b ;
//          hg = slots@gru_wh^T + gru_bh
__global__ void k_small(const float* __restrict__ slots,
                        const float* __restrict__ nsg, const float* __restrict__ nsb,
                        const float* __restrict__ qw, const float* __restrict__ qb,
                        const float* __restrict__ kw, const float* __restrict__ kb,
                        const float* __restrict__ wh, const float* __restrict__ bh) {
    __shared__ float red[32];
    __shared__ float sraw[DD];
    __shared__ float sln[DD];
    __shared__ float sq[DD];
    int i = blockIdx.x, c = threadIdx.x;
    float x = slots[i * DD + c];
    sraw[c] = x;
    float mean = blockSum(x, red) * (1.f / 256.f);
    float d0 = x - mean;
    float var = blockSum(d0 * d0, red) * (1.f / 256.f);
    sln[c] = d0 * rsqrtf(var + 1e-5f) * nsg[c] + nsb[c];
    __syncthreads();
    float acc = qb[c];
    const float* wr = qw + (size_t)c * 256;
#pragma unroll 8
    for (int k = 0; k < 256; k++) acc += sln[k] * wr[k];
    sq[c] = acc;
    float qkb = blockSum(acc * kb[c], red);
    if (c == 0) g_qkb[i] = qkb;
    float qk = 0.f;
#pragma unroll 8
    for (int d = 0; d < 256; d++) qk += sq[d] * kw[(size_t)d * 256 + c];
    g_qs[i * DD + c] = qk;
#pragma unroll
    for (int j = 0; j < 3; j++) {
        int u = j * 256 + c;
        float a = bh[u];
        const float* hr = wh + (size_t)u * 256;
#pragma unroll 8
        for (int k = 0; k < 256; k++) a += sraw[k] * hr[k];
        g_hg[i * 768 + u] = a;
    }
}

// ---------------- 3-way-split fused dots+softmax+partial(renorm,mid) ----------------
// grid (BWIN, 3): seg owns 256 tokens. Writes out_attn slice + fp32 partial
// denominators & mids; k_comb reduces the 3 segments.
#define AT3_SMEM 45280

__global__ void __launch_bounds__(256, 4) k_attup3(
    float* __restrict__ out_attn,
    const __nv_bfloat16* __restrict__ x2h, const __nv_bfloat16* __restrict__ x2l) {
    extern __shared__ char sm[];
    unsigned long long* q2 = (unsigned long long*)sm;                // 22528
    unsigned long long* apk = (unsigned long long*)(sm + 22528);     // 22528
    float* red = (float*)(sm + 45056);                               // 128
    float* qkbs = (float*)(sm + 45184);                              // 88
    int bB = blockIdx.x, seg = blockIdx.y, tid = threadIdx.x;

    for (int idx = tid; idx < 11 * 256; idx += 256) {
        int ip = idx >> 8, k = idx & 255;
        q2[idx] = pk(g_qs[(2 * ip) * DD + k], g_qs[(2 * ip + 1) * DD + k]);
    }
    if (tid < SS) qkbs[tid] = g_qkb[tid];
    __syncthreads();

    size_t row = (size_t)bB * NTOK + seg * 256 + tid;
    unsigned long long d[11];
#pragma unroll
    for (int ip = 0; ip < 11; ip++) d[ip] = 0ULL;
    for (int kc = 0; kc < 256; kc += 8) {
        uint4 H = *(const uint4*)(x2h + row * 256 + kc);
        uint4 L = *(const uint4*)(x2l + row * 256 + kc);
        float o[8];
        rec8(H, L, o);
#pragma unroll
        for (int kl = 0; kl < 8; kl++) {
            unsigned long long sv = pk(o[kl], o[kl]);
#pragma unroll
            for (int ip = 0; ip < 11; ip++)
                d[ip] = fma2(q2[ip * 256 + kc + kl], sv, d[ip]);
        }
    }
    // softmax over 22 slots (reg-lean 3-pass)
    float mx = -1e30f;
#pragma unroll
    for (int ip = 0; ip < 11; ip++) {
        float a, b;
        upk(d[ip], a, b);
        a = (a + qkbs[2 * ip]) * 0.0625f;
        b = (b + qkbs[2 * ip + 1]) * 0.0625f;
        mx = fmaxf(mx, fmaxf(a, b));
    }
    float s = 0.f;
#pragma unroll
    for (int ip = 0; ip < 11; ip++) {
        float a, b;
        upk(d[ip], a, b);
        s += __expf((a + qkbs[2 * ip]) * 0.0625f - mx)
           + __expf((b + qkbs[2 * ip + 1]) * 0.0625f - mx);
    }
    float inv = 1.f / s;
    int wi = bB / BATCH, bb = bB % BATCH;
    float* gdst = out_attn + ((size_t)(bb * NWIN + wi)) * SS * NTOK + seg * 256 + tid;
#pragma unroll
    for (int ip = 0; ip < 11; ip++) {
        float a, b;
        upk(d[ip], a, b);
        a = __expf((a + qkbs[2 * ip]) * 0.0625f - mx) * inv + 1e-8f;
        b = __expf((b + qkbs[2 * ip + 1]) * 0.0625f - mx) * inv + 1e-8f;
        gdst[(2 * ip) * NTOK] = a;
        gdst[(2 * ip + 1) * NTOK] = b;
        apk[ip * 256 + tid] = pk(a, b);
    }
    __syncthreads();

    // partial denominators
    float* pden = g_pden + (bB * 3 + seg) * SS;
    for (int ip = 0; ip < 11; ip++) {
        float a, b;
        upk(apk[ip * 256 + tid], a, b);
        float sa = blockSum(a, red);
        float sb = blockSum(b, red);
        if (tid == 0) { pden[2 * ip] = sa; pden[2 * ip + 1] = sb; }
    }

    // partial mid: channel = tid, sum over this segment's 256 tokens
    unsigned long long acc[11];
#pragma unroll
    for (int ip = 0; ip < 11; ip++) acc[ip] = 0ULL;
    const __nv_bfloat16* vph = x2h + ((size_t)bB * NTOK + seg * 256) * 256 + tid;
    const __nv_bfloat16* vpl = x2l + ((size_t)bB * NTOK + seg * 256) * 256 + tid;
#pragma unroll 4
    for (int j = 0; j < 256; j++) {
        float v = __bfloat162float(vph[(size_t)j * 256])
                + __bfloat162float(vpl[(size_t)j * 256]);
        unsigned long long sv = pk(v, v);
#pragma unroll
        for (int ip = 0; ip < 11; ip++)
            acc[ip] = fma2(apk[ip * 256 + j], sv, acc[ip]);
    }
    float* pmid = g_pmid + (size_t)(bB * 3 + seg) * (SS * 256);
#pragma unroll
    for (int ip = 0; ip < 11; ip++) {
        float u0, u1;
        upk(acc[ip], u0, u1);
        pmid[(2 * ip) * 256 + tid] = u0;
        pmid[(2 * ip + 1) * 256 + tid] = u1;
    }
}

// combine 3 partials -> renormed mid (split bf16)
__global__ void k_comb(__nv_bfloat16* __restrict__ midh,
                       __nv_bfloat16* __restrict__ midl) {
    int m = blockIdx.x, c = threadIdx.x;  // m in [0, MGRU)
    int bB = m / SS, i = m % SS;
    size_t b3 = (size_t)bB * 3;
    float p = g_pmid[(b3 + 0) * (SS * 256) + i * 256 + c]
            + g_pmid[(b3 + 1) * (SS * 256) + i * 256 + c]
            + g_pmid[(b3 + 2) * (SS * 256) + i * 256 + c];
    float den = g_pden[(b3 + 0) * SS + i] + g_pden[(b3 + 1) * SS + i]
              + g_pden[(b3 + 2) * SS + i];
    float u = p / den;
    __nv_bfloat16 h = __float2bfloat16(u);
    midh[(size_t)m * DD + c] = h;
    midl[(size_t)m * DD + c] = __float2bfloat16(u - __bfloat162float(h));
}

__global__ void k_gate(const float* __restrict__ slots) {
    int m = blockIdx.x, c = threadIdx.x;
    int Bi = m / NAC, i = m % NAC;
    size_t row = (size_t)Bi * SS + i;
    float ir = g_xg[row * 768 + c];
    float iz = g_xg[row * 768 + 256 + c];
    float in_ = g_xg[row * 768 + 512 + c];
    float hr = g_hg[i * 768 + c];
    float hz = g_hg[i * 768 + 256 + c];
    float hn = g_hg[i * 768 + 512 + c];
    float h = slots[i * DD + c];
    float r = 1.f / (1.f + __expf(-(ir + hr)));
    float z = 1.f / (1.f + __expf(-(iz + hz)));
    float n = tanhf(in_ + r * hn);
    g_so[(size_t)m * DD + c] = (1.f - z) * n + z * h;
}

__global__ void k_final(float* __restrict__ out) {
    int m = blockIdx.x, c = threadIdx.x;
    int Bi = m / NAC, sl = m % NAC;
    int wi = Bi / BATCH, bb = Bi % BATCH;
    out[(((size_t)bb * NWIN + wi) * NAC + sl) * DD + c] =
        g_so[(size_t)m * DD + c] + g_t3[(size_t)m * DD + c];
}

extern "C" void kernel_launch(void* const* d_in, const int* in_sizes, int n_in,
                              void* d_out, int out_size) {
    const float* inputs = (const float*)d_in[0];
    const float* slots  = (const float*)d_in[1];
    const float* pe_w   = (const float*)d_in[2];
    const float* pe_b   = (const float*)d_in[3];
    const float* LN_g   = (const float*)d_in[4];
    const float* LN_b   = (const float*)d_in[5];
    const float* ni_g   = (const float*)d_in[6];
    const float* ni_b   = (const float*)d_in[7];
    const float* ns_g   = (const float*)d_in[8];
    const float* ns_b   = (const float*)d_in[9];
    const float* npf_g  = (const float*)d_in[10];
    const float* npf_b  = (const float*)d_in[11];
    const float* FC1_w  = (const float*)d_in[12];
    const float* FC1_b  = (const float*)d_in[13];
    const float* FC2_w  = (const float*)d_in[14];
    const float* FC2_b  = (const float*)d_in[15];
    const float* q_w    = (const float*)d_in[16];
    const float* q_b    = (const float*)d_in[17];
    const float* k_w    = (const float*)d_in[18];
    const float* k_b    = (const float*)d_in[19];
    const float* v_w    = (const float*)d_in[20];
    const float* v_b    = (const float*)d_in[21];
    const float* ff1_w  = (const float*)d_in[22];
    const float* ff1_b  = (const float*)d_in[23];
    const float* ff2_w  = (const float*)d_in[24];
    const float* ff2_b  = (const float*)d_in[25];
    const float* gru_wi = (const float*)d_in[26];
    const float* gru_wh = (const float*)d_in[27];
    const float* gru_bi = (const float*)d_in[28];
    const float* gru_bh = (const float*)d_in[29];

    float* out = (float*)d_out;
    float* out_attn = out + SLOTS_OUT_ELEMS;

    float *xg_, *so_, *t3_, *bgp_;
    cudaGetSymbolAddress((void**)&xg_, g_xg);
    cudaGetSymbolAddress((void**)&so_, g_so);
    cudaGetSymbolAddress((void**)&t3_, g_t3);
    cudaGetSymbolAddress((void**)&bgp_, g_bgp);

    __nv_bfloat16 *w1h, *w1l, *w2h, *w2l, *wgvh, *wgvl, *wf1h, *wf1l, *wf2h, *wf2l;
    __nv_bfloat16 *x0h, *x0l, *x1h, *x1l, *x2h, *x2l;
    __nv_bfloat16 *snh, *snl, *t2h, *t2l;
    cudaGetSymbolAddress((void**)&w1h, g_w1h); cudaGetSymbolAddress((void**)&w1l, g_w1l);
    cudaGetSymbolAddress((void**)&w2h, g_w2h); cudaGetSymbolAddress((void**)&w2l, g_w2l);
    cudaGetSymbolAddress((void**)&wgvh, g_wgvh); cudaGetSymbolAddress((void**)&wgvl, g_wgvl);
    cudaGetSymbolAddress((void**)&wf1h, g_wf1h); cudaGetSymbolAddress((void**)&wf1l, g_wf1l);
    cudaGetSymbolAddress((void**)&wf2h, g_wf2h); cudaGetSymbolAddress((void**)&wf2l, g_wf2l);
    cudaGetSymbolAddress((void**)&x0h, g_x0h); cudaGetSymbolAddress((void**)&x0l, g_x0l);
    cudaGetSymbolAddress((void**)&x1h, g_x1h); cudaGetSymbolAddress((void**)&x1l, g_x1l);
    cudaGetSymbolAddress((void**)&x2h, g_x2h); cudaGetSymbolAddress((void**)&x2l, g_x2l);
    cudaGetSymbolAddress((void**)&snh, g_solnh); cudaGetSymbolAddress((void**)&snl, g_solnl);
    cudaGetSymbolAddress((void**)&t2h, g_t2h); cudaGetSymbolAddress((void**)&t2l, g_t2l);

    cudaFuncSetAttribute((const void*)k_mma<true, true, false>,
                         cudaFuncAttributeMaxDynamicSharedMemorySize, MM_SMEM);
    cudaFuncSetAttribute((const void*)k_mma<false, false, true>,
                         cudaFuncAttributeMaxDynamicSharedMemorySize, MM_SMEM);
    cudaFuncSetAttribute((const void*)k_mma<false, false, false>,
                         cudaFuncAttributeMaxDynamicSharedMemorySize, MM_SMEM);
    cudaFuncSetAttribute((const void*)k_fc2ln,
                         cudaFuncAttributeMaxDynamicSharedMemorySize, F_SMEM);
    cudaFuncSetAttribute((const void*)k_attup3,
                         cudaFuncAttributeMaxDynamicSharedMemorySize, AT3_SMEM);

    k_splitall<<<1024, 256>>>(FC1_w, FC2_w, ff1_w, ff2_w);
    k_prep<<<768, 256>>>(gru_wi, v_w, v_b, gru_bi);

    k_pe<<<NTOK, 256>>>(pe_w, pe_b);
    k_winln<<<MBIG / 8, 256>>>(inputs, LN_g, LN_b);

    // FC1 (relu, split out)
    k_mma<true, true, false><<<dim3(2, MBIG / 128), 256, MM_SMEM>>>(
        x0h, x0l, w1h, w1l, FC1_b, nullptr, x1h, x1l, MBIG, 256);

    // FC2 + norm_input LN fused (split out)
    k_fc2ln<<<MBIG / 64, 256, F_SMEM>>>(x1h, x1l, w2h, w2l, FC2_b, ni_g, ni_b,
                                        x2h, x2l);

    // batch-invariant q, qk = q@k_w, qkb, hidden gates
    k_small<<<SS, 256>>>(slots, ns_g, ns_b, q_w, q_b, k_w, k_b, gru_wh, gru_bh);

    // fused dots+softmax + partial renorm/mid (3 token segments per bB)
    k_attup3<<<dim3(BWIN, 3), 256, AT3_SMEM>>>(out_attn, x2h, x2l);

    // combine partials -> mid (split bf16, rows 0..MGRU-1 of x0)
    k_comb<<<MGRU, 256>>>(x0h, x0l);

    // fused (V + GRU-input) GEMM: xg = mid @ (gru_wi@v_w)^T + bias'
    k_mma<false, false, true><<<dim3(6, MGRUPAD / 128), 256, MM_SMEM>>>(
        x0h, x0l, wgvh, wgvl, bgp_, xg_, nullptr, nullptr, MGRU, 768);

    k_gate<<<MSO, 256>>>(slots);

    k_ln2<<<MSO / 8, 256>>>(so_, snh, snl, npf_g, npf_b);
    k_mma<true, true, false><<<dim3(2, MSO / 128), 256, MM_SMEM>>>(
        snh, snl, wf1h, wf1l, ff1_b, nullptr, t2h, t2l, MSO, 256);
    k_mma<false, false, false><<<dim3(2, MSO / 128), 256, MM_SMEM>>>(
        t2h, t2l, wf2h, wf2l, ff2_b, t3_, nullptr, nullptr, MSO, 256);

    k_final<<<MSO, 256>>>(out);
}

// round 13
// speedup vs baseline: 2.1175x; 1.0211x over previous
#include <cuda_runtime.h>
#include <cuda_bf16.h>
#include <math.h>
#include <stdint.h>

#define DD 256
#define SS 22
#define NAC 20
#define NTOK 768
#define NWIN 7
#define BATCH 32
#define BWIN 224
#define MBIG 172032
#define MGRU 4928
#define MGRUPAD 4992
#define MSO  4480
#define SLOTS_OUT_ELEMS 1146880

__device__ float g_pe[NTOK * DD];
__device__ __nv_bfloat16 g_x0h[MBIG * DD], g_x0l[MBIG * DD];  // winln out; rows 0..4927 reused as mid
__device__ __nv_bfloat16 g_x1h[MBIG * DD], g_x1l[MBIG * DD];  // FC1 out
__device__ __nv_bfloat16 g_x2h[MBIG * DD], g_x2l[MBIG * DD];  // fc2+LN out
__device__ float g_qs[SS * DD];     // qk = q @ k_w
__device__ float g_qkb[SS];
__device__ float g_hg[SS * 768];
__device__ float g_pmid[672 * SS * 256];
__device__ float g_pden[672 * SS];
__device__ float g_xg[MGRU * 768];
__device__ float g_so[MSO * DD];
__device__ __nv_bfloat16 g_solnh[MSO * DD], g_solnl[MSO * DD];
__device__ __nv_bfloat16 g_t2h[MSO * DD], g_t2l[MSO * DD];
__device__ float g_t3[MSO * DD];
__device__ __nv_bfloat16 g_w1h[65536], g_w1l[65536];
__device__ __nv_bfloat16 g_w2h[65536], g_w2l[65536];
__device__ __nv_bfloat16 g_wgvh[196608], g_wgvl[196608];
__device__ float g_bgp[768];
__device__ __nv_bfloat16 g_wf1h[65536], g_wf1l[65536];
__device__ __nv_bfloat16 g_wf2h[65536], g_wf2l[65536];

// ---------------- helpers ----------------
__device__ __forceinline__ uint32_t smem_u32(const void* p) {
    uint32_t a;
    asm("{ .reg .u64 t; cvta.to.shared.u64 t, %1; cvt.u32.u64 %0, t; }" : "=r"(a) : "l"(p));
    return a;
}
__device__ __forceinline__ unsigned long long pk(float x, float y) {
    unsigned long long r;
    asm("mov.b64 %0, {%1,%2};" : "=l"(r) : "f"(x), "f"(y));
    return r;
}
__device__ __forceinline__ void upk(unsigned long long v, float& x, float& y) {
    asm("mov.b64 {%0,%1}, %2;" : "=f"(x), "=f"(y) : "l"(v));
}
__device__ __forceinline__ unsigned long long fma2(unsigned long long a,
                                                   unsigned long long b,
                                                   unsigned long long c) {
    unsigned long long d;
    asm("fma.rn.f32x2 %0, %1, %2, %3;" : "=l"(d) : "l"(a), "l"(b), "l"(c));
    return d;
}
__device__ __forceinline__ uint32_t bfpack(float a, float b) {
    __nv_bfloat162 t = __floats2bfloat162_rn(a, b);
    return *reinterpret_cast<uint32_t*>(&t);
}
__device__ __forceinline__ void ldsm4(uint32_t* r, uint32_t addr) {
    asm volatile("ldmatrix.sync.aligned.m8n8.x4.shared.b16 {%0,%1,%2,%3}, [%4];"
        : "=r"(r[0]), "=r"(r[1]), "=r"(r[2]), "=r"(r[3]) : "r"(addr));
}
__device__ __forceinline__ void mma16816(float* d, const uint32_t* a,
                                         uint32_t b0, uint32_t b1) {
    asm("mma.sync.aligned.m16n8k16.row.col.f32.bf16.bf16.f32 "
        "{%0,%1,%2,%3}, {%4,%5,%6,%7}, {%8,%9}, {%0,%1,%2,%3};"
        : "+f"(d[0]), "+f"(d[1]), "+f"(d[2]), "+f"(d[3])
        : "r"(a[0]), "r"(a[1]), "r"(a[2]), "r"(a[3]), "r"(b0), "r"(b1));
}
__device__ __forceinline__ void cp16(uint32_t sm, const void* g) {
    asm volatile("cp.async.cg.shared.global [%0], [%1], 16;" :: "r"(sm), "l"(g));
}
__device__ __forceinline__ void cp_commit() {
    asm volatile("cp.async.commit_group;" ::: "memory");
}
template <int N>
__device__ __forceinline__ void cp_wait() {
    asm volatile("cp.async.wait_group %0;" :: "n"(N) : "memory");
}
__device__ __forceinline__ void rec8(uint4 H, uint4 L, float* o) {
    const uint32_t hw[4] = {H.x, H.y, H.z, H.w};
    const uint32_t lw[4] = {L.x, L.y, L.z, L.w};
#pragma unroll
    for (int i = 0; i < 4; i++) {
        __nv_bfloat162 hb = *reinterpret_cast<const __nv_bfloat162*>(&hw[i]);
        __nv_bfloat162 lb = *reinterpret_cast<const __nv_bfloat162*>(&lw[i]);
        float2 hf = __bfloat1622float2(hb);
        float2 lf = __bfloat1622float2(lb);
        o[2 * i] = hf.x + lf.x;
        o[2 * i + 1] = hf.y + lf.y;
    }
}

__device__ __forceinline__ float blockSum(float v, float* s) {
    int tid = threadIdx.x;
#pragma unroll
    for (int o = 16; o > 0; o >>= 1) v += __shfl_down_sync(0xffffffffu, v, o);
    if ((tid & 31) == 0) s[tid >> 5] = v;
    __syncthreads();
    float r = (tid < (int)(blockDim.x >> 5)) ? s[tid] : 0.f;
    if (tid < 32) {
#pragma unroll
        for (int o = 4; o > 0; o >>= 1) r += __shfl_down_sync(0xffffffffu, r, o);
    }
    if (tid == 0) s[0] = r;
    __syncthreads();
    r = s[0];
    __syncthreads();
    return r;
}

// ---------------- small kernels ----------------
__global__ void k_pe(const float* __restrict__ pe_w, const float* __restrict__ pe_b) {
    int p = blockIdx.x, c = threadIdx.x;
    int t = p / 192, rem = p % 192, y = rem / 24, x = rem % 24;
    float g0 = t * (1.f / 3.f), g1 = y * (1.f / 7.f), g2 = x * (1.f / 23.f);
    const float* wr = pe_w + c * 6;
    g_pe[p * DD + c] = pe_b[c] + wr[0] * g0 + wr[1] * g1 + wr[2] * g2
        + wr[3] * (1.f - g0) + wr[4] * (1.f - g1) + wr[5] * (1.f - g2);
}

// warp-per-row gather + pe + LN, vectorized (float4 in, uint2 packed out)
__global__ void __launch_bounds__(256) k_winln(const float* __restrict__ inp,
                                               const float* __restrict__ gam,
                                               const float* __restrict__ bet) {
    int m = (blockIdx.x * 256 + threadIdx.x) >> 5;
    int lane = threadIdx.x & 31;
    int wiB = m / NTOK, p = m % NTOK;
    int wi = wiB / BATCH, bb = wiB % BATCH;
    int t = p / 192, rem = p % 192;
    int f = 2 * wi + t;
    const float4* src4 = (const float4*)(inp + ((size_t)(bb * 16 + f) * 192 + rem) * DD);
    const float4* pe4 = (const float4*)(g_pe + p * DD);
    float4 a0 = src4[lane], a1 = src4[lane + 32];
    float4 p0 = pe4[lane], p1 = pe4[lane + 32];
    float x[8];
    x[0] = a0.x + p0.x; x[1] = a0.y + p0.y; x[2] = a0.z + p0.z; x[3] = a0.w + p0.w;
    x[4] = a1.x + p1.x; x[5] = a1.y + p1.y; x[6] = a1.z + p1.z; x[7] = a1.w + p1.w;
    float s = 0.f, sq = 0.f;
#pragma unroll
    for (int i = 0; i < 8; i++) { s += x[i]; sq += x[i] * x[i]; }
#pragma unroll
    for (int o = 16; o > 0; o >>= 1) {
        s += __shfl_xor_sync(0xffffffffu, s, o);
        sq += __shfl_xor_sync(0xffffffffu, sq, o);
    }
    float mean = s * (1.f / 256.f);
    float var = sq * (1.f / 256.f) - mean * mean;
    float rs = rsqrtf(var + 1e-5f);
    const float4* g4 = (const float4*)gam;
    const float4* b4 = (const float4*)bet;
    float4 g0v = g4[lane], g1v = g4[lane + 32];
    float4 b0v = b4[lane], b1v = b4[lane + 32];
    float y[8];
    y[0] = (x[0] - mean) * rs * g0v.x + b0v.x;
    y[1] = (x[1] - mean) * rs * g0v.y + b0v.y;
    y[2] = (x[2] - mean) * rs * g0v.z + b0v.z;
    y[3] = (x[3] - mean) * rs * g0v.w + b0v.w;
    y[4] = (x[4] - mean) * rs * g1v.x + b1v.x;
    y[5] = (x[5] - mean) * rs * g1v.y + b1v.y;
    y[6] = (x[6] - mean) * rs * g1v.z + b1v.z;
    y[7] = (x[7] - mean) * rs * g1v.w + b1v.w;
    uint2 H0, L0, H1, L1;
    {
        __nv_bfloat162 h01 = __floats2bfloat162_rn(y[0], y[1]);
        __nv_bfloat162 h23 = __floats2bfloat162_rn(y[2], y[3]);
        __nv_bfloat162 h45 = __floats2bfloat162_rn(y[4], y[5]);
        __nv_bfloat162 h67 = __floats2bfloat162_rn(y[6], y[7]);
        H0.x = *reinterpret_cast<uint32_t*>(&h01);
        H0.y = *reinterpret_cast<uint32_t*>(&h23);
        H1.x = *reinterpret_cast<uint32_t*>(&h45);
        H1.y = *reinterpret_cast<uint32_t*>(&h67);
        L0.x = bfpack(y[0] - __bfloat162float(h01.x), y[1] - __bfloat162float(h01.y));
        L0.y = bfpack(y[2] - __bfloat162float(h23.x), y[3] - __bfloat162float(h23.y));
        L1.x = bfpack(y[4] - __bfloat162float(h45.x), y[5] - __bfloat162float(h45.y));
        L1.y = bfpack(y[6] - __bfloat162float(h67.x), y[7] - __bfloat162float(h67.y));
    }
    *reinterpret_cast<uint2*>(g_x0h + (size_t)m * DD + lane * 4) = H0;
    *reinterpret_cast<uint2*>(g_x0h + (size_t)m * DD + 128 + lane * 4) = H1;
    *reinterpret_cast<uint2*>(g_x0l + (size_t)m * DD + lane * 4) = L0;
    *reinterpret_cast<uint2*>(g_x0l + (size_t)m * DD + 128 + lane * 4) = L1;
}

// split weights: w1, w2, wf1, wf2
__global__ void k_splitall(const float* __restrict__ w1, const float* __restrict__ w2,
                           const float* __restrict__ wf1, const float* __restrict__ wf2) {
    int idx = blockIdx.x * 256 + threadIdx.x;
    if (idx >= 262144) return;
    const float* src;
    __nv_bfloat16 *h, *l;
    int j;
    if (idx < 65536)       { j = idx;          src = w1;  h = g_w1h;  l = g_w1l; }
    else if (idx < 131072) { j = idx - 65536;  src = w2;  h = g_w2h;  l = g_w2l; }
    else if (idx < 196608) { j = idx - 131072; src = wf1; h = g_wf1h; l = g_wf1l; }
    else                   { j = idx - 196608; src = wf2; h = g_wf2h; l = g_wf2l; }
    float x = src[j];
    __nv_bfloat16 hh = __float2bfloat16(x);
    h[j] = hh;
    l[j] = __float2bfloat16(x - __bfloat162float(hh));
}

// wgv = gru_wi @ v_w (768x256), split bf16; bgp = gru_bi + gru_wi @ v_b
__global__ void k_prep(const float* __restrict__ wg, const float* __restrict__ wv,
                       const float* __restrict__ vb, const float* __restrict__ bg) {
    __shared__ float swg[256];
    __shared__ float red[32];
    int u = blockIdx.x, c = threadIdx.x;
    swg[c] = wg[u * 256 + c];
    __syncthreads();
    float acc = 0.f;
#pragma unroll 8
    for (int d = 0; d < 256; d++) acc += swg[d] * wv[(size_t)d * 256 + c];
    __nv_bfloat16 h = __float2bfloat16(acc);
    g_wgvh[(size_t)u * 256 + c] = h;
    g_wgvl[(size_t)u * 256 + c] = __float2bfloat16(acc - __bfloat162float(h));
    float bp = blockSum(swg[c] * vb[c], red);
    if (c == 0) g_bgp[u] = bg[u] + bp;
}

// ---------------- generic 3-stage split-bf16 mma GEMM ----------------
#define ROW3 144
#define AMAT 18432
#define STG3 36864
#define MM_SMEM 110592

template <bool RELU, bool SPLIT, bool MBOUND>
__global__ void __launch_bounds__(256, 2) k_mma(
    const __nv_bfloat16* __restrict__ Ah, const __nv_bfloat16* __restrict__ Al,
    const __nv_bfloat16* __restrict__ Wh, const __nv_bfloat16* __restrict__ Wl,
    const float* __restrict__ bias, float* __restrict__ C,
    __nv_bfloat16* __restrict__ Ch, __nv_bfloat16* __restrict__ Cl,
    int M, int N) {
    extern __shared__ char sm[];
    int tid = threadIdx.x, lane = tid & 31, wid = tid >> 5;
    int n0 = blockIdx.x * 128, m0 = blockIdx.y * 128;
    int mw = wid & 3, nw = wid >> 2;
    uint32_t sb = smem_u32(sm);

    float acc[2][8][4];
#pragma unroll
    for (int i = 0; i < 2; i++)
#pragma unroll
        for (int j = 0; j < 8; j++)
#pragma unroll
            for (int k = 0; k < 4; k++) acc[i][j][k] = 0.f;

    auto cpStage = [&](int ch, int buf) {
        int k0 = ch * 32;
        uint32_t st = sb + (uint32_t)buf * STG3;
#pragma unroll
        for (int i = 0; i < 8; i++) {
            int idx = tid + i * 256;
            int mat = idx >> 10;
            int j = idx & 1023;
            int row = j >> 3, part = j & 7;
            uint32_t off = (mat ? AMAT : 0) + (uint32_t)row * ROW3
                         + (part & 3) * 16 + (part >> 2) * 64;
            int kk0 = k0 + (part & 3) * 8;
            if (mat == 0) {
                const __nv_bfloat16* g =
                    ((part < 4) ? Ah : Al) + (size_t)(m0 + row) * 256 + kk0;
                cp16(st + off, g);
            } else {
                const __nv_bfloat16* g =
                    ((part < 4) ? Wh : Wl) + (size_t)(n0 + row) * 256 + kk0;
                cp16(st + off, g);
            }
        }
    };

    cpStage(0, 0); cp_commit();
    cpStage(1, 1); cp_commit();

#pragma unroll
    for (int ch = 0; ch < 8; ch++) {
        if (ch < 7) cp_wait<1>(); else cp_wait<0>();
        __syncthreads();
        if (ch < 6) { cpStage(ch + 2, (ch + 2) % 3); cp_commit(); }
        uint32_t st = sb + (uint32_t)(ch % 3) * STG3;
#pragma unroll
        for (int ks = 0; ks < 2; ks++) {
            int k = ks * 16;
            uint32_t koff = (uint32_t)(k + (lane >> 4) * 8) * 2;
            uint32_t ah[2][4], al[2][4];
#pragma unroll
            for (int mt = 0; mt < 2; mt++) {
                uint32_t addr = st
                    + (uint32_t)(mw * 32 + mt * 16 + (lane & 15)) * ROW3 + koff;
                ldsm4(ah[mt], addr);
                ldsm4(al[mt], addr + 64);
            }
#pragma unroll
            for (int p = 0; p < 4; p++) {
                uint32_t ba = st + AMAT
                    + (uint32_t)(nw * 64 + p * 16 + (lane & 15)) * ROW3 + koff;
                uint32_t bh[4], bl[4];
                ldsm4(bh, ba);
                ldsm4(bl, ba + 64);
                mma16816(acc[0][2 * p],     ah[0], bh[0], bh[2]);
                mma16816(acc[0][2 * p + 1], ah[0], bh[1], bh[3]);
                mma16816(acc[1][2 * p],     ah[1], bh[0], bh[2]);
                mma16816(acc[1][2 * p + 1], ah[1], bh[1], bh[3]);
                mma16816(acc[0][2 * p],     ah[0], bl[0], bl[2]);
                mma16816(acc[0][2 * p + 1], ah[0], bl[1], bl[3]);
                mma16816(acc[1][2 * p],     ah[1], bl[0], bl[2]);
                mma16816(acc[1][2 * p + 1], ah[1], bl[1], bl[3]);
                mma16816(acc[0][2 * p],     al[0], bh[0], bh[2]);
                mma16816(acc[0][2 * p + 1], al[0], bh[1], bh[3]);
                mma16816(acc[1][2 * p],     al[1], bh[0], bh[2]);
                mma16816(acc[1][2 * p + 1], al[1], bh[1], bh[3]);
            }
        }
    }

#pragma unroll
    for (int nt = 0; nt < 8; nt++) {
        int col = n0 + nw * 64 + nt * 8 + (lane & 3) * 2;
        float bx = bias[col], by = bias[col + 1];
#pragma unroll
        for (int mt = 0; mt < 2; mt++) {
            int row = m0 + mw * 32 + mt * 16 + (lane >> 2);
            float* a = acc[mt][nt];
            float2 o0 = make_float2(a[0] + bx, a[1] + by);
            float2 o1 = make_float2(a[2] + bx, a[3] + by);
            if (RELU) {
                o0.x = fmaxf(o0.x, 0.f); o0.y = fmaxf(o0.y, 0.f);
                o1.x = fmaxf(o1.x, 0.f); o1.y = fmaxf(o1.y, 0.f);
            }
            bool w0 = !MBOUND || row < M;
            bool w1 = !MBOUND || row + 8 < M;
            if (SPLIT) {
                __nv_bfloat162 h0 = __floats2bfloat162_rn(o0.x, o0.y);
                __nv_bfloat162 h1 = __floats2bfloat162_rn(o1.x, o1.y);
                uint32_t L0 = bfpack(o0.x - __bfloat162float(h0.x),
                                     o0.y - __bfloat162float(h0.y));
                uint32_t L1 = bfpack(o1.x - __bfloat162float(h1.x),
                                     o1.y - __bfloat162float(h1.y));
                if (w0) {
                    *reinterpret_cast<uint32_t*>(Ch + (size_t)row * N + col) =
                        *reinterpret_cast<uint32_t*>(&h0);
                    *reinterpret_cast<uint32_t*>(Cl + (size_t)row * N + col) = L0;
                }
                if (w1) {
                    *reinterpret_cast<uint32_t*>(Ch + (size_t)(row + 8) * N + col) =
                        *reinterpret_cast<uint32_t*>(&h1);
                    *reinterpret_cast<uint32_t*>(Cl + (size_t)(row + 8) * N + col) = L1;
                }
            } else {
                if (w0) *reinterpret_cast<float2*>(C + (size_t)row * N + col) = o0;
                if (w1) *reinterpret_cast<float2*>(C + (size_t)(row + 8) * N + col) = o1;
            }
        }
    }
}

// ---------------- fused FC2 + LayerNorm GEMM ----------------
#define F_AROWS 64
#define F_BOFF 9216
#define F_STG 46080
#define F_GB 92160
#define F_RED 95232
#define F_SMEM 96256

__global__ void __launch_bounds__(256, 2) k_fc2ln(
    const __nv_bfloat16* __restrict__ Ah, const __nv_bfloat16* __restrict__ Al,
    const __nv_bfloat16* __restrict__ Wh, const __nv_bfloat16* __restrict__ Wl,
    const float* __restrict__ bias, const float* __restrict__ gam,
    const float* __restrict__ bet,
    __nv_bfloat16* __restrict__ Ch, __nv_bfloat16* __restrict__ Cl) {
    extern __shared__ char sm[];
    int tid = threadIdx.x, lane = tid & 31, wid = tid >> 5;
    int m0 = blockIdx.x * F_AROWS;
    int mw = wid & 3, nw = wid >> 2;
    uint32_t sb = smem_u32(sm);
    float* gb = (float*)(sm + F_GB);
    float2* red = (float2*)(sm + F_RED);

    {
        int c = tid;
        gb[c] = bias[c];
        gb[256 + c] = gam[c];
        gb[512 + c] = bet[c];
    }

    float acc[16][4];
#pragma unroll
    for (int j = 0; j < 16; j++)
#pragma unroll
        for (int k = 0; k < 4; k++) acc[j][k] = 0.f;

    auto cpStage = [&](int ch, int buf) {
        int k0 = ch * 32;
        uint32_t st = sb + (uint32_t)buf * F_STG;
#pragma unroll
        for (int i = 0; i < 10; i++) {
            int idx = tid + i * 256;
            if (idx < 512) {
                int row = idx >> 3, part = idx & 7;
                uint32_t off = (uint32_t)row * ROW3 + (part & 3) * 16 + (part >> 2) * 64;
                const __nv_bfloat16* g =
                    ((part < 4) ? Ah : Al) + (size_t)(m0 + row) * 256 + k0 + (part & 3) * 8;
                cp16(st + off, g);
            } else {
                int j = idx - 512;
                int row = j >> 3, part = j & 7;
                uint32_t off = F_BOFF + (uint32_t)row * ROW3 + (part & 3) * 16 + (part >> 2) * 64;
                const __nv_bfloat16* g =
                    ((part < 4) ? Wh : Wl) + (size_t)row * 256 + k0 + (part & 3) * 8;
                cp16(st + off, g);
            }
        }
    };

    cpStage(0, 0); cp_commit();

#pragma unroll
    for (int ch = 0; ch < 8; ch++) {
        cp_wait<0>();
        __syncthreads();
        if (ch < 7) { cpStage(ch + 1, (ch + 1) & 1); cp_commit(); }
        uint32_t st = sb + (uint32_t)(ch & 1) * F_STG;
#pragma unroll
        for (int ks = 0; ks < 2; ks++) {
            uint32_t koff = (uint32_t)(ks * 16 + (lane >> 4) * 8) * 2;
            uint32_t ah[4], al[4];
            uint32_t aaddr = st + (uint32_t)(mw * 16 + (lane & 15)) * ROW3 + koff;
            ldsm4(ah, aaddr);
            ldsm4(al, aaddr + 64);
#pragma unroll
            for (int p = 0; p < 8; p++) {
                uint32_t ba = st + F_BOFF
                    + (uint32_t)(nw * 128 + p * 16 + (lane & 15)) * ROW3 + koff;
                uint32_t bh[4], bl[4];
                ldsm4(bh, ba);
                ldsm4(bl, ba + 64);
                mma16816(acc[2 * p],     ah, bh[0], bh[2]);
                mma16816(acc[2 * p + 1], ah, bh[1], bh[3]);
                mma16816(acc[2 * p],     ah, bl[0], bl[2]);
                mma16816(acc[2 * p + 1], ah, bl[1], bl[3]);
                mma16816(acc[2 * p],     al, bh[0], bh[2]);
                mma16816(acc[2 * p + 1], al, bh[1], bh[3]);
            }
        }
    }

    float s0 = 0.f, q0 = 0.f, s1 = 0.f, q1 = 0.f;
#pragma unroll
    for (int nt = 0; nt < 16; nt++) {
        int col = nw * 128 + nt * 8 + (lane & 3) * 2;
        float bx = gb[col], by = gb[col + 1];
        acc[nt][0] += bx; acc[nt][1] += by;
        acc[nt][2] += bx; acc[nt][3] += by;
        s0 += acc[nt][0] + acc[nt][1];
        q0 += acc[nt][0] * acc[nt][0] + acc[nt][1] * acc[nt][1];
        s1 += acc[nt][2] + acc[nt][3];
        q1 += acc[nt][2] * acc[nt][2] + acc[nt][3] * acc[nt][3];
    }
#pragma unroll
    for (int o = 1; o <= 2; o <<= 1) {
        s0 += __shfl_xor_sync(0xffffffffu, s0, o);
        q0 += __shfl_xor_sync(0xffffffffu, q0, o);
        s1 += __shfl_xor_sync(0xffffffffu, s1, o);
        q1 += __shfl_xor_sync(0xffffffffu, q1, o);
    }
    int rloc = mw * 16 + (lane >> 2);
    if ((lane & 3) == 0) {
        red[rloc * 2 + nw] = make_float2(s0, q0);
        red[(rloc + 8) * 2 + nw] = make_float2(s1, q1);
    }
    __syncthreads();
    float2 a0 = red[rloc * 2], b0f = red[rloc * 2 + 1];
    float ss = a0.x + b0f.x, qq = a0.y + b0f.y;
    float mean0 = ss * (1.f / 256.f);
    float rs0 = rsqrtf(qq * (1.f / 256.f) - mean0 * mean0 + 1e-5f);
    float2 a1 = red[(rloc + 8) * 2], b1f = red[(rloc + 8) * 2 + 1];
    float ss1 = a1.x + b1f.x, qq1 = a1.y + b1f.y;
    float mean1 = ss1 * (1.f / 256.f);
    float rs1 = rsqrtf(qq1 * (1.f / 256.f) - mean1 * mean1 + 1e-5f);

    int row0 = m0 + rloc, row1 = row0 + 8;
#pragma unroll
    for (int nt = 0; nt < 16; nt++) {
        int col = nw * 128 + nt * 8 + (lane & 3) * 2;
        float gx = gb[256 + col], gy = gb[256 + col + 1];
        float ex = gb[512 + col], ey = gb[512 + col + 1];
        float y00 = (acc[nt][0] - mean0) * rs0 * gx + ex;
        float y01 = (acc[nt][1] - mean0) * rs0 * gy + ey;
        float y10 = (acc[nt][2] - mean1) * rs1 * gx + ex;
        float y11 = (acc[nt][3] - mean1) * rs1 * gy + ey;
        __nv_bfloat162 h0 = __floats2bfloat162_rn(y00, y01);
        __nv_bfloat162 h1 = __floats2bfloat162_rn(y10, y11);
        uint32_t L0 = bfpack(y00 - __bfloat162float(h0.x), y01 - __bfloat162float(h0.y));
        uint32_t L1 = bfpack(y10 - __bfloat162float(h1.x), y11 - __bfloat162float(h1.y));
        *reinterpret_cast<uint32_t*>(Ch + (size_t)row0 * 256 + col) =
            *reinterpret_cast<uint32_t*>(&h0);
        *reinterpret_cast<uint32_t*>(Cl + (size_t)row0 * 256 + col) = L0;
        *reinterpret_cast<uint32_t*>(Ch + (size_t)row1 * 256 + col) =
            *reinterpret_cast<uint32_t*>(&h1);
        *reinterpret_cast<uint32_t*>(Cl + (size_t)row1 * 256 + col) = L1;
    }
}

// k_small: q = LN_ns(slots)@q_w^T + q_b ; qk = q @ k_w ; qkb = q . k_b ;
//          hg = slots@gru_wh^T + gru_bh
__global__ void k_small(const float* __restrict__ slots,
                        const float* __restrict__ nsg, const float* __restrict__ nsb,
                        const float* __restrict__ qw, const float* __restrict__ qb,
                        const float* __restrict__ kw, const float* __restrict__ kb,
                        const float* __restrict__ wh, const float* __restrict__ bh) {
    __shared__ float red[32];
    __shared__ float sraw[DD];
    __shared__ float sln[DD];
    __shared__ float sq[DD];
    int i = blockIdx.x, c = threadIdx.x;
    float x = slots[i * DD + c];
    sraw[c] = x;
    float mean = blockSum(x, red) * (1.f / 256.f);
    float d0 = x - mean;
    float var = blockSum(d0 * d0, red) * (1.f / 256.f);
    sln[c] = d0 * rsqrtf(var + 1e-5f) * nsg[c] + nsb[c];
    __syncthreads();
    float acc = qb[c];
    const float* wr = qw + (size_t)c * 256;
#pragma unroll 8
    for (int k = 0; k < 256; k++) acc += sln[k] * wr[k];
    sq[c] = acc;
    float qkb = blockSum(acc * kb[c], red);
    if (c == 0) g_qkb[i] = qkb;
    float qk = 0.f;
#pragma unroll 8
    for (int d = 0; d < 256; d++) qk += sq[d] * kw[(size_t)d * 256 + c];
    g_qs[i * DD + c] = qk;
#pragma unroll
    for (int j = 0; j < 3; j++) {
        int u = j * 256 + c;
        float a = bh[u];
        const float* hr = wh + (size_t)u * 256;
#pragma unroll 8
        for (int k = 0; k < 256; k++) a += sraw[k] * hr[k];
        g_hg[i * 768 + u] = a;
    }
}

// ---------------- 3-way-split fused dots+softmax+partial(renorm,mid) ----------------
#define AT3_SMEM 45280

__global__ void __launch_bounds__(256, 3) k_attup3(
    float* __restrict__ out_attn,
    const __nv_bfloat16* __restrict__ x2h, const __nv_bfloat16* __restrict__ x2l) {
    extern __shared__ char sm[];
    unsigned long long* q2 = (unsigned long long*)sm;
    unsigned long long* apk = (unsigned long long*)(sm + 22528);
    float* red = (float*)(sm + 45056);
    float* qkbs = (float*)(sm + 45184);
    int bB = blockIdx.x, seg = blockIdx.y, tid = threadIdx.x;

    for (int idx = tid; idx < 11 * 256; idx += 256) {
        int ip = idx >> 8, k = idx & 255;
        q2[idx] = pk(g_qs[(2 * ip) * DD + k], g_qs[(2 * ip + 1) * DD + k]);
    }
    if (tid < SS) qkbs[tid] = g_qkb[tid];
    __syncthreads();

    size_t row = (size_t)bB * NTOK + seg * 256 + tid;
    unsigned long long d[11];
#pragma unroll
    for (int ip = 0; ip < 11; ip++) d[ip] = 0ULL;
    for (int kc = 0; kc < 256; kc += 8) {
        uint4 H = *(const uint4*)(x2h + row * 256 + kc);
        uint4 L = *(const uint4*)(x2l + row * 256 + kc);
        float o[8];
        rec8(H, L, o);
#pragma unroll
        for (int kl = 0; kl < 8; kl++) {
            unsigned long long sv = pk(o[kl], o[kl]);
#pragma unroll
            for (int ip = 0; ip < 11; ip++)
                d[ip] = fma2(q2[ip * 256 + kc + kl], sv, d[ip]);
        }
    }
    float mx = -1e30f;
#pragma unroll
    for (int ip = 0; ip < 11; ip++) {
        float a, b;
        upk(d[ip], a, b);
        a = (a + qkbs[2 * ip]) * 0.0625f;
        b = (b + qkbs[2 * ip + 1]) * 0.0625f;
        mx = fmaxf(mx, fmaxf(a, b));
    }
    float s = 0.f;
#pragma unroll
    for (int ip = 0; ip < 11; ip++) {
        float a, b;
        upk(d[ip], a, b);
        s += __expf((a + qkbs[2 * ip]) * 0.0625f - mx)
           + __expf((b + qkbs[2 * ip + 1]) * 0.0625f - mx);
    }
    float inv = 1.f / s;
    int wi = bB / BATCH, bb = bB % BATCH;
    float* gdst = out_attn + ((size_t)(bb * NWIN + wi)) * SS * NTOK + seg * 256 + tid;
#pragma unroll
    for (int ip = 0; ip < 11; ip++) {
        float a, b;
        upk(d[ip], a, b);
        a = __expf((a + qkbs[2 * ip]) * 0.0625f - mx) * inv + 1e-8f;
        b = __expf((b + qkbs[2 * ip + 1]) * 0.0625f - mx) * inv + 1e-8f;
        gdst[(2 * ip) * NTOK] = a;
        gdst[(2 * ip + 1) * NTOK] = b;
        apk[ip * 256 + tid] = pk(a, b);
    }
    __syncthreads();

    float* pden = g_pden + (bB * 3 + seg) * SS;
    for (int ip = 0; ip < 11; ip++) {
        float a, b;
        upk(apk[ip * 256 + tid], a, b);
        float sa = blockSum(a, red);
        float sb = blockSum(b, red);
        if (tid == 0) { pden[2 * ip] = sa; pden[2 * ip + 1] = sb; }
    }

    unsigned long long acc[11];
#pragma unroll
    for (int ip = 0; ip < 11; ip++) acc[ip] = 0ULL;
    const __nv_bfloat16* vph = x2h + ((size_t)bB * NTOK + seg * 256) * 256 + tid;
    const __nv_bfloat16* vpl = x2l + ((size_t)bB * NTOK + seg * 256) * 256 + tid;
#pragma unroll 4
    for (int j = 0; j < 256; j++) {
        float v = __bfloat162float(vph[(size_t)j * 256])
                + __bfloat162float(vpl[(size_t)j * 256]);
        unsigned long long sv = pk(v, v);
#pragma unroll
        for (int ip = 0; ip < 11; ip++)
            acc[ip] = fma2(apk[ip * 256 + j], sv, acc[ip]);
    }
    float* pmid = g_pmid + (size_t)(bB * 3 + seg) * (SS * 256);
#pragma unroll
    for (int ip = 0; ip < 11; ip++) {
        float u0, u1;
        upk(acc[ip], u0, u1);
        pmid[(2 * ip) * 256 + tid] = u0;
        pmid[(2 * ip + 1) * 256 + tid] = u1;
    }
}

// combine 3 partials -> renormed mid (split bf16)
__global__ void k_comb(__nv_bfloat16* __restrict__ midh,
                       __nv_bfloat16* __restrict__ midl) {
    int m = blockIdx.x, c = threadIdx.x;
    int bB = m / SS, i = m % SS;
    size_t b3 = (size_t)bB * 3;
    float p = g_pmid[(b3 + 0) * (SS * 256) + i * 256 + c]
            + g_pmid[(b3 + 1) * (SS * 256) + i * 256 + c]
            + g_pmid[(b3 + 2) * (SS * 256) + i * 256 + c];
    float den = g_pden[(b3 + 0) * SS + i] + g_pden[(b3 + 1) * SS + i]
              + g_pden[(b3 + 2) * SS + i];
    float u = p / den;
    __nv_bfloat16 h = __float2bfloat16(u);
    midh[(size_t)m * DD + c] = h;
    midl[(size_t)m * DD + c] = __float2bfloat16(u - __bfloat162float(h));
}

// fused GRU gate + residual-LN (split out); also writes g_so for final residual
__global__ void k_gateln(const float* __restrict__ slots,
                         const float* __restrict__ gam, const float* __restrict__ bet,
                         __nv_bfloat16* __restrict__ dsth,
                         __nv_bfloat16* __restrict__ dstl) {
    __shared__ float red[32];
    int m = blockIdx.x, c = threadIdx.x;
    int Bi = m / NAC, i = m % NAC;
    size_t row = (size_t)Bi * SS + i;
    float ir = g_xg[row * 768 + c];
    float iz = g_xg[row * 768 + 256 + c];
    float in_ = g_xg[row * 768 + 512 + c];
    float hr = g_hg[i * 768 + c];
    float hz = g_hg[i * 768 + 256 + c];
    float hn = g_hg[i * 768 + 512 + c];
    float h = slots[i * DD + c];
    float r = 1.f / (1.f + __expf(-(ir + hr)));
    float z = 1.f / (1.f + __expf(-(iz + hz)));
    float n = tanhf(in_ + r * hn);
    float val = (1.f - z) * n + z * h;
    g_so[(size_t)m * DD + c] = val;
    float mean = blockSum(val, red) * (1.f / 256.f);
    float d0 = val - mean;
    float var = blockSum(d0 * d0, red) * (1.f / 256.f);
    float y = d0 * rsqrtf(var + 1e-5f) * gam[c] + bet[c];
    __nv_bfloat16 hh = __float2bfloat16(y);
    dsth[(size_t)m * DD + c] = hh;
    dstl[(size_t)m * DD + c] = __float2bfloat16(y - __bfloat162float(hh));
}

__global__ void k_final(float* __restrict__ out) {
    int m = blockIdx.x, c = threadIdx.x;
    int Bi = m / NAC, sl = m % NAC;
    int wi = Bi / BATCH, bb = Bi % BATCH;
    out[(((size_t)bb * NWIN + wi) * NAC + sl) * DD + c] =
        g_so[(size_t)m * DD + c] + g_t3[(size_t)m * DD + c];
}

extern "C" void kernel_launch(void* const* d_in, const int* in_sizes, int n_in,
                              void* d_out, int out_size) {
    const float* inputs = (const float*)d_in[0];
    const float* slots  = (const float*)d_in[1];
    const float* pe_w   = (const float*)d_in[2];
    const float* pe_b   = (const float*)d_in[3];
    const float* LN_g   = (const float*)d_in[4];
    const float* LN_b   = (const float*)d_in[5];
    const float* ni_g   = (const float*)d_in[6];
    const float* ni_b   = (const float*)d_in[7];
    const float* ns_g   = (const float*)d_in[8];
    const float* ns_b   = (const float*)d_in[9];
    const float* npf_g  = (const float*)d_in[10];
    const float* npf_b  = (const float*)d_in[11];
    const float* FC1_w  = (const float*)d_in[12];
    const float* FC1_b  = (const float*)d_in[13];
    const float* FC2_w  = (const float*)d_in[14];
    const float* FC2_b  = (const float*)d_in[15];
    const float* q_w    = (const float*)d_in[16];
    const float* q_b    = (const float*)d_in[17];
    const float* k_w    = (const float*)d_in[18];
    const float* k_b    = (const float*)d_in[19];
    const float* v_w    = (const float*)d_in[20];
    const float* v_b    = (const float*)d_in[21];
    const float* ff1_w  = (const float*)d_in[22];
    const float* ff1_b  = (const float*)d_in[23];
    const float* ff2_w  = (const float*)d_in[24];
    const float* ff2_b  = (const float*)d_in[25];
    const float* gru_wi = (const float*)d_in[26];
    const float* gru_wh = (const float*)d_in[27];
    const float* gru_bi = (const float*)d_in[28];
    const float* gru_bh = (const float*)d_in[29];

    float* out = (float*)d_out;
    float* out_attn = out + SLOTS_OUT_ELEMS;

    float *xg_, *t3_, *bgp_;
    cudaGetSymbolAddress((void**)&xg_, g_xg);
    cudaGetSymbolAddress((void**)&t3_, g_t3);
    cudaGetSymbolAddress((void**)&bgp_, g_bgp);

    __nv_bfloat16 *w1h, *w1l, *w2h, *w2l, *wgvh, *wgvl, *wf1h, *wf1l, *wf2h, *wf2l;
    __nv_bfloat16 *x0h, *x0l, *x1h, *x1l, *x2h, *x2l;
    __nv_bfloat16 *snh, *snl, *t2h, *t2l;
    cudaGetSymbolAddress((void**)&w1h, g_w1h); cudaGetSymbolAddress((void**)&w1l, g_w1l);
    cudaGetSymbolAddress((void**)&w2h, g_w2h); cudaGetSymbolAddress((void**)&w2l, g_w2l);
    cudaGetSymbolAddress((void**)&wgvh, g_wgvh); cudaGetSymbolAddress((void**)&wgvl, g_wgvl);
    cudaGetSymbolAddress((void**)&wf1h, g_wf1h); cudaGetSymbolAddress((void**)&wf1l, g_wf1l);
    cudaGetSymbolAddress((void**)&wf2h, g_wf2h); cudaGetSymbolAddress((void**)&wf2l, g_wf2l);
    cudaGetSymbolAddress((void**)&x0h, g_x0h); cudaGetSymbolAddress((void**)&x0l, g_x0l);
    cudaGetSymbolAddress((void**)&x1h, g_x1h); cudaGetSymbolAddress((void**)&x1l, g_x1l);
    cudaGetSymbolAddress((void**)&x2h, g_x2h); cudaGetSymbolAddress((void**)&x2l, g_x2l);
    cudaGetSymbolAddress((void**)&snh, g_solnh); cudaGetSymbolAddress((void**)&snl, g_solnl);
    cudaGetSymbolAddress((void**)&t2h, g_t2h); cudaGetSymbolAddress((void**)&t2l, g_t2l);

    cudaFuncSetAttribute((const void*)k_mma<true, true, false>,
                         cudaFuncAttributeMaxDynamicSharedMemorySize, MM_SMEM);
    cudaFuncSetAttribute((const void*)k_mma<false, false, true>,
                         cudaFuncAttributeMaxDynamicSharedMemorySize, MM_SMEM);
    cudaFuncSetAttribute((const void*)k_mma<false, false, false>,
                         cudaFuncAttributeMaxDynamicSharedMemorySize, MM_SMEM);
    cudaFuncSetAttribute((const void*)k_fc2ln,
                         cudaFuncAttributeMaxDynamicSharedMemorySize, F_SMEM);
    cudaFuncSetAttribute((const void*)k_attup3,
                         cudaFuncAttributeMaxDynamicSharedMemorySize, AT3_SMEM);

    k_splitall<<<1024, 256>>>(FC1_w, FC2_w, ff1_w, ff2_w);
    k_prep<<<768, 256>>>(gru_wi, v_w, v_b, gru_bi);

    k_pe<<<NTOK, 256>>>(pe_w, pe_b);
    k_winln<<<MBIG / 8, 256>>>(inputs, LN_g, LN_b);

    // FC1 (relu, split out)
    k_mma<true, true, false><<<dim3(2, MBIG / 128), 256, MM_SMEM>>>(
        x0h, x0l, w1h, w1l, FC1_b, nullptr, x1h, x1l, MBIG, 256);

    // FC2 + norm_input LN fused (split out)
    k_fc2ln<<<MBIG / 64, 256, F_SMEM>>>(x1h, x1l, w2h, w2l, FC2_b, ni_g, ni_b,
                                        x2h, x2l);

    // batch-invariant q, qk = q@k_w, qkb, hidden gates
    k_small<<<SS, 256>>>(slots, ns_g, ns_b, q_w, q_b, k_w, k_b, gru_wh, gru_bh);

    // fused dots+softmax + partial renorm/mid (3 token segments per bB)
    k_attup3<<<dim3(BWIN, 3), 256, AT3_SMEM>>>(out_attn, x2h, x2l);

    // combine partials -> mid (split bf16, rows 0..MGRU-1 of x0)
    k_comb<<<MGRU, 256>>>(x0h, x0l);

    // fused (V + GRU-input) GEMM
    k_mma<false, false, true><<<dim3(6, MGRUPAD / 128), 256, MM_SMEM>>>(
        x0h, x0l, wgvh, wgvl, bgp_, xg_, nullptr, nullptr, MGRU, 768);

    // GRU gates + residual-LN fused
    k_gateln<<<MSO, 256>>>(slots, npf_g, npf_b, snh, snl);

    k_mma<true, true, false><<<dim3(2, MSO / 128), 256, MM_SMEM>>>(
        snh, snl, wf1h, wf1l, ff1_b, nullptr, t2h, t2l, MSO, 256);
    k_mma<false, false, false><<<dim3(2, MSO / 128), 256, MM_SMEM>>>(
        t2h, t2l, wf2h, wf2l, ff2_b, t3_, nullptr, nullptr, MSO, 256);

    k_final<<<MSO, 256>>>(out);
}